// round 4
// baseline (speedup 1.0000x reference)
#include <cuda_runtime.h>
#include <cstdint>
#include <math.h>

#define Bn 2
#define Ln 2048
#define Dn 1024
#define Hn 16
#define DKn 64
#define BHn (Bn*Hn)      // 32
#define Mn (Bn*Ln)       // 4096

// Scratch (device globals — no allocation allowed)
__device__ float g_k[(size_t)BHn*Ln*DKn];
__device__ float g_v[(size_t)BHn*Ln*DKn];
__device__ float g_q[(size_t)BHn*Ln*DKn];
__device__ float g_o[(size_t)BHn*Ln*DKn];
__device__ float g_part[(size_t)BHn*Ln*16];  // per-block partial row sums
__device__ float g_ri[(size_t)BHn*Ln];       // 1 / rowsum
// Fallback scores buffer in case the harness output holds only `normed`
__device__ float g_sc[(size_t)BHn*Ln*Ln];

// ---------------------------------------------------------------------------
// Projection GEMM: out[b,h,l,dk] = sum_d X[b,l,d] * W[d, h*DK+dk]
// M=4096, N=1024, K=1024. 128x128 tile, BK=8, 8x8 per thread, 256 threads.
// ---------------------------------------------------------------------------
__global__ __launch_bounds__(256) void proj_kernel(const float* __restrict__ X,
                                                   const float* __restrict__ W,
                                                   int which) {
    float* out = (which == 0) ? g_k : ((which == 1) ? g_v : g_q);
    __shared__ float As[8][132];
    __shared__ float Bs[8][132];
    const int bm = blockIdx.y * 128;
    const int bn = blockIdx.x * 128;
    const int tid = threadIdx.x;
    const int tx = tid & 15, ty = tid >> 4;

    float acc[8][8];
    #pragma unroll
    for (int i = 0; i < 8; i++)
        #pragma unroll
        for (int j = 0; j < 8; j++) acc[i][j] = 0.f;

    const int am = tid >> 1;
    const int ak = (tid & 1) * 4;
    const int bk = tid >> 5;
    const int bn4 = (tid & 31) * 4;

    for (int k0 = 0; k0 < Dn; k0 += 8) {
        float4 a = *(const float4*)&X[(size_t)(bm + am) * Dn + k0 + ak];
        As[ak+0][am] = a.x; As[ak+1][am] = a.y;
        As[ak+2][am] = a.z; As[ak+3][am] = a.w;
        float4 b = *(const float4*)&W[(size_t)(k0 + bk) * Dn + bn + bn4];
        *(float4*)&Bs[bk][bn4] = b;
        __syncthreads();
        #pragma unroll
        for (int kk = 0; kk < 8; kk++) {
            float ra[8], rb[8];
            *(float4*)&ra[0] = *(const float4*)&As[kk][ty*8];
            *(float4*)&ra[4] = *(const float4*)&As[kk][ty*8+4];
            *(float4*)&rb[0] = *(const float4*)&Bs[kk][tx*8];
            *(float4*)&rb[4] = *(const float4*)&Bs[kk][tx*8+4];
            #pragma unroll
            for (int i = 0; i < 8; i++)
                #pragma unroll
                for (int j = 0; j < 8; j++)
                    acc[i][j] = fmaf(ra[i], rb[j], acc[i][j]);
        }
        __syncthreads();
    }
    const int n0 = bn + tx*8;
    const int h = n0 >> 6;       // 8 | 64, so the 8 columns stay in one head
    const int dk = n0 & 63;
    #pragma unroll
    for (int i = 0; i < 8; i++) {
        int m = bm + ty*8 + i;
        int bb = m >> 11, l = m & (Ln-1);
        float* po = &out[(((size_t)(bb*Hn + h))*Ln + l)*DKn + dk];
        *(float4*)&po[0] = make_float4(acc[i][0],acc[i][1],acc[i][2],acc[i][3]);
        *(float4*)&po[4] = make_float4(acc[i][4],acc[i][5],acc[i][6],acc[i][7]);
    }
}

// ---------------------------------------------------------------------------
// Scores: u[bh,q,j] = exp((q.k)/8) or 0 if masked. Writes u to sc (the
// unnormalized attn output) and deterministic per-block partial row sums.
// Block: 128q x 128j, 8x8 per thread, 256 threads. DK split into 2 chunks.
// ---------------------------------------------------------------------------
__global__ __launch_bounds__(256) void scores_kernel(const int* __restrict__ mask,
                                                     float* __restrict__ sc) {
    const int bh = blockIdx.z;
    const int q0 = blockIdx.y * 128;
    const int j0 = blockIdx.x * 128;
    const int b = bh >> 4;
    const int tid = threadIdx.x;
    const int tx = tid & 15, ty = tid >> 4;

    __shared__ float Qs[32][132];   // Qs[d][q]  (132 = mult of 4: float4-safe)
    __shared__ float Ks[32][132];   // Ks[d][j]

    float acc[8][8];
    #pragma unroll
    for (int i = 0; i < 8; i++)
        #pragma unroll
        for (int j = 0; j < 8; j++) acc[i][j] = 0.f;

    #pragma unroll
    for (int d0 = 0; d0 < DKn; d0 += 32) {
        // load 128 rows x 32 d (transposed into [d][row])
        #pragma unroll
        for (int it = 0; it < 4; it++) {
            int e = tid + it*256;          // e in [0,1024)
            int r = e >> 3, c4 = (e & 7) * 4;
            float4 vq = *(const float4*)&g_q[(((size_t)bh)*Ln + q0 + r)*DKn + d0 + c4];
            Qs[c4+0][r] = vq.x; Qs[c4+1][r] = vq.y;
            Qs[c4+2][r] = vq.z; Qs[c4+3][r] = vq.w;
            float4 vk = *(const float4*)&g_k[(((size_t)bh)*Ln + j0 + r)*DKn + d0 + c4];
            Ks[c4+0][r] = vk.x; Ks[c4+1][r] = vk.y;
            Ks[c4+2][r] = vk.z; Ks[c4+3][r] = vk.w;
        }
        __syncthreads();
        #pragma unroll
        for (int kk = 0; kk < 32; kk++) {
            float ra[8], rb[8];
            *(float4*)&ra[0] = *(const float4*)&Qs[kk][ty*8];
            *(float4*)&ra[4] = *(const float4*)&Qs[kk][ty*8+4];
            *(float4*)&rb[0] = *(const float4*)&Ks[kk][tx*8];
            *(float4*)&rb[4] = *(const float4*)&Ks[kk][tx*8+4];
            #pragma unroll
            for (int i = 0; i < 8; i++)
                #pragma unroll
                for (int j = 0; j < 8; j++)
                    acc[i][j] = fmaf(ra[i], rb[j], acc[i][j]);
        }
        __syncthreads();
    }

    // mask, exponentiate, write u, accumulate row partial sums
    float rsum[8];
    #pragma unroll
    for (int i = 0; i < 8; i++) rsum[i] = 0.f;

    #pragma unroll
    for (int i = 0; i < 8; i++) {
        int q = q0 + ty*8 + i;
        size_t mbase = ((size_t)b*Ln + q)*Ln + j0 + tx*8;
        int4 m0 = *(const int4*)(mask + mbase);
        int4 m1 = *(const int4*)(mask + mbase + 4);
        float u[8];
        u[0] = m0.x ? 0.f : __expf(acc[i][0]*0.125f);
        u[1] = m0.y ? 0.f : __expf(acc[i][1]*0.125f);
        u[2] = m0.z ? 0.f : __expf(acc[i][2]*0.125f);
        u[3] = m0.w ? 0.f : __expf(acc[i][3]*0.125f);
        u[4] = m1.x ? 0.f : __expf(acc[i][4]*0.125f);
        u[5] = m1.y ? 0.f : __expf(acc[i][5]*0.125f);
        u[6] = m1.z ? 0.f : __expf(acc[i][6]*0.125f);
        u[7] = m1.w ? 0.f : __expf(acc[i][7]*0.125f);
        #pragma unroll
        for (int j = 0; j < 8; j++) rsum[i] += u[j];
        size_t sbase = ((size_t)bh*Ln + q)*Ln + j0 + tx*8;
        *(float4*)(sc + sbase)     = make_float4(u[0],u[1],u[2],u[3]);
        *(float4*)(sc + sbase + 4) = make_float4(u[4],u[5],u[6],u[7]);
    }

    // reduce across the 16 tx lanes (all in the same warp for a given ty)
    #pragma unroll
    for (int i = 0; i < 8; i++) {
        float s = rsum[i];
        #pragma unroll
        for (int off = 8; off; off >>= 1)
            s += __shfl_xor_sync(0xffffffffu, s, off);
        if (tx == 0) {
            int q = q0 + ty*8 + i;
            g_part[(((size_t)bh)*Ln + q)*16 + blockIdx.x] = s;
        }
    }
}

// ---------------------------------------------------------------------------
// Row-sum reduction: ri[bh,q] = 1 / sum_jb part[bh,q,jb]
// ---------------------------------------------------------------------------
__global__ __launch_bounds__(256) void rowsum_kernel() {
    int row = blockIdx.x * 256 + threadIdx.x;   // bh*Ln + q
    float s = 0.f;
    #pragma unroll
    for (int jb = 0; jb < 16; jb++) s += g_part[(size_t)row*16 + jb];
    g_ri[row] = 1.0f / s;
}

// ---------------------------------------------------------------------------
// PV: p = u * ri written in place (final attn output); o = (sum u*V) * ri.
// Block: 128 q x 64 dk, j chunks of 32. Thread: 8q x 4dk.
// ---------------------------------------------------------------------------
__global__ __launch_bounds__(256) void pv_kernel(float* __restrict__ sc) {
    const int bh = blockIdx.y;
    const int q0 = blockIdx.x * 128;
    const int tid = threadIdx.x;
    const int tx = tid & 15, ty = tid >> 4;

    __shared__ float Ps[32][132];  // Ps[j][q] (raw u); 132 = mult of 4
    __shared__ float Vs[32][64];   // Vs[j][dk]
    __shared__ float riS[128];

    if (tid < 128) riS[tid] = g_ri[(size_t)bh*Ln + q0 + tid];

    float acc[8][4];
    #pragma unroll
    for (int i = 0; i < 8; i++)
        #pragma unroll
        for (int c = 0; c < 4; c++) acc[i][c] = 0.f;

    for (int j0 = 0; j0 < Ln; j0 += 32) {
        __syncthreads();
        #pragma unroll
        for (int it = 0; it < 16; it++) {
            int e = tid + it*256;            // 4096 elems
            int q = e >> 5, j = e & 31;
            size_t gi = (((size_t)bh)*Ln + q0 + q)*Ln + j0 + j;
            float u = sc[gi];
            sc[gi] = u * riS[q];             // final normalized attn
            Ps[j][q] = u;
        }
        #pragma unroll
        for (int it = 0; it < 8; it++) {
            int e = tid + it*256;            // 2048 elems
            int j = e >> 6, d = e & 63;
            Vs[j][d] = g_v[(((size_t)bh)*Ln + j0 + j)*DKn + d];
        }
        __syncthreads();
        #pragma unroll 8
        for (int jj = 0; jj < 32; jj++) {
            float pv[8], vv[4];
            *(float4*)&pv[0] = *(const float4*)&Ps[jj][ty*8];
            *(float4*)&pv[4] = *(const float4*)&Ps[jj][ty*8+4];
            *(float4*)&vv[0] = *(const float4*)&Vs[jj][tx*4];
            #pragma unroll
            for (int i = 0; i < 8; i++)
                #pragma unroll
                for (int c = 0; c < 4; c++)
                    acc[i][c] = fmaf(pv[i], vv[c], acc[i][c]);
        }
    }

    #pragma unroll
    for (int i = 0; i < 8; i++) {
        int q = q0 + ty*8 + i;
        float ri = riS[ty*8 + i];
        float* po = &g_o[(((size_t)bh)*Ln + q)*DKn + tx*4];
        *(float4*)po = make_float4(acc[i][0]*ri, acc[i][1]*ri,
                                   acc[i][2]*ri, acc[i][3]*ri);
    }
}

// ---------------------------------------------------------------------------
// Residual + LayerNorm: normed[b,l,d] over D=1024, one block per (b,l).
// ---------------------------------------------------------------------------
__global__ __launch_bounds__(256) void ln_kernel(const float* __restrict__ query,
                                                 const float* __restrict__ gamma,
                                                 const float* __restrict__ beta,
                                                 float* __restrict__ out) {
    const int row = blockIdx.x;          // b*L + l
    const int b = row >> 11, l = row & (Ln-1);
    const int tid = threadIdx.x;
    float vals[4];
    float s = 0.f, ss = 0.f;
    #pragma unroll
    for (int it = 0; it < 4; it++) {
        int d = tid + it*256;
        int h = d >> 6, dk = d & 63;
        float o = g_o[(((size_t)(b*Hn + h))*Ln + l)*DKn + dk];
        float r = o + query[(size_t)row*Dn + d];
        vals[it] = r;
        s += r; ss += r*r;
    }
    __shared__ float sm[8], sq[8], stat[2];
    #pragma unroll
    for (int off = 16; off; off >>= 1) {
        s  += __shfl_xor_sync(0xffffffffu, s, off);
        ss += __shfl_xor_sync(0xffffffffu, ss, off);
    }
    int warp = tid >> 5, lane = tid & 31;
    if (lane == 0) { sm[warp] = s; sq[warp] = ss; }
    __syncthreads();
    if (tid == 0) {
        float S = 0.f, SS = 0.f;
        #pragma unroll
        for (int w = 0; w < 8; w++) { S += sm[w]; SS += sq[w]; }
        float mu = S * (1.0f/Dn);
        float var = SS * (1.0f/Dn) - mu*mu;
        stat[0] = mu;
        stat[1] = rsqrtf(var + 1e-6f);
    }
    __syncthreads();
    float mu = stat[0], rstd = stat[1];
    #pragma unroll
    for (int it = 0; it < 4; it++) {
        int d = tid + it*256;
        out[(size_t)row*Dn + d] = (vals[it] - mu) * rstd * gamma[d] + beta[d];
    }
}

// ---------------------------------------------------------------------------
extern "C" void kernel_launch(void* const* d_in, const int* in_sizes, int n_in,
                              void* d_out, int out_size) {
    const float* key   = (const float*)d_in[0];
    const float* value = (const float*)d_in[1];
    const float* query = (const float*)d_in[2];
    const int*   mask  = (const int*)d_in[3];
    const float* Wk = (const float*)d_in[4];
    const float* Wv = (const float*)d_in[5];
    const float* Wq = (const float*)d_in[6];
    const float* lng = (const float*)d_in[7];
    const float* lnb = (const float*)d_in[8];

    float* normed = (float*)d_out;                       // [B, L, D]
    float* attn;
    if ((size_t)out_size > (size_t)Bn*Ln*Dn) {
        attn = normed + (size_t)Bn*Ln*Dn;                // [B*H, L, L]
    } else {
        cudaGetSymbolAddress((void**)&attn, g_sc);
    }

    dim3 gp(Dn/128, Mn/128);     // (8, 32)
    proj_kernel<<<gp, 256>>>(key,   Wk, 0);
    proj_kernel<<<gp, 256>>>(value, Wv, 1);
    proj_kernel<<<gp, 256>>>(query, Wq, 2);

    dim3 gs(Ln/128, Ln/128, BHn);   // (16, 16, 32)
    scores_kernel<<<gs, 256>>>(mask, attn);

    rowsum_kernel<<<(BHn*Ln)/256, 256>>>();

    dim3 gv(Ln/128, BHn);        // (16, 32)
    pv_kernel<<<gv, 256>>>(attn);

    ln_kernel<<<Mn, 256>>>(query, lng, lnb, normed);
}

// round 5
// speedup vs baseline: 1.4926x; 1.4926x over previous
#include <cuda_runtime.h>
#include <cstdint>
#include <math.h>

#define Bn 2
#define Ln 2048
#define Dn 1024
#define Hn 16
#define DKn 64
#define BHn (Bn*Hn)      // 32
#define Mn (Bn*Ln)       // 4096

typedef unsigned long long u64;

// Scratch (device globals — no allocation allowed)
__device__ float g_k[(size_t)BHn*Ln*DKn];
__device__ float g_v[(size_t)BHn*Ln*DKn];
__device__ float g_q[(size_t)BHn*Ln*DKn];
__device__ float g_o[(size_t)BHn*Ln*DKn];
__device__ float g_part[(size_t)BHn*Ln*16];  // per-block partial row sums
__device__ float g_ri[(size_t)BHn*Ln];       // 1 / rowsum
// Fallback scores buffer in case the harness output holds only `normed`
__device__ float g_sc[(size_t)BHn*Ln*Ln];

// ---- packed fp32 helpers (FFMA2 via PTX; not emitted by ptxas from C++) ----
__device__ __forceinline__ u64 pack2(float a) {
    u64 r; unsigned int u = __float_as_uint(a);
    asm("mov.b64 %0, {%1, %1};" : "=l"(r) : "r"(u));
    return r;
}
__device__ __forceinline__ void fma2(u64& d, u64 a, u64 b) {
    asm("fma.rn.f32x2 %0, %1, %2, %0;" : "+l"(d) : "l"(a), "l"(b));
}
__device__ __forceinline__ float2 unpack2(u64 v) {
    unsigned int lo, hi;
    asm("mov.b64 {%0, %1}, %2;" : "=r"(lo), "=r"(hi) : "l"(v));
    return make_float2(__uint_as_float(lo), __uint_as_float(hi));
}

// ---------------------------------------------------------------------------
// Projection GEMM: out[b,h,l,dk] = sum_d X[b,l,d] * W[d, h*DK+dk]
// M=4096, N=1024, K=1024. 128x128 tile, BK=8, 8x8 per thread, 256 threads.
// ---------------------------------------------------------------------------
__global__ __launch_bounds__(256, 2) void proj_kernel(const float* __restrict__ X,
                                                      const float* __restrict__ W,
                                                      int which) {
    float* out = (which == 0) ? g_k : ((which == 1) ? g_v : g_q);
    __shared__ float As[8][132];
    __shared__ float Bs[8][132];
    const int bm = blockIdx.y * 128;
    const int bn = blockIdx.x * 128;
    const int tid = threadIdx.x;
    const int tx = tid & 15, ty = tid >> 4;

    u64 acc[8][4];
    #pragma unroll
    for (int i = 0; i < 8; i++)
        #pragma unroll
        for (int p = 0; p < 4; p++) acc[i][p] = 0ull;

    const int am = tid >> 1;
    const int ak = (tid & 1) * 4;
    const int bk = tid >> 5;
    const int bn4 = (tid & 31) * 4;

    for (int k0 = 0; k0 < Dn; k0 += 8) {
        float4 a = *(const float4*)&X[(size_t)(bm + am) * Dn + k0 + ak];
        As[ak+0][am] = a.x; As[ak+1][am] = a.y;
        As[ak+2][am] = a.z; As[ak+3][am] = a.w;
        float4 b = *(const float4*)&W[(size_t)(k0 + bk) * Dn + bn + bn4];
        *(float4*)&Bs[bk][bn4] = b;
        __syncthreads();
        #pragma unroll
        for (int kk = 0; kk < 8; kk++) {
            float ra[8];
            *(float4*)&ra[0] = *(const float4*)&As[kk][ty*8];
            *(float4*)&ra[4] = *(const float4*)&As[kk][ty*8+4];
            u64 rb[4];
            *(ulonglong2*)&rb[0] = *(const ulonglong2*)&Bs[kk][tx*8];
            *(ulonglong2*)&rb[2] = *(const ulonglong2*)&Bs[kk][tx*8+4];
            #pragma unroll
            for (int i = 0; i < 8; i++) {
                u64 ap = pack2(ra[i]);
                #pragma unroll
                for (int p = 0; p < 4; p++) fma2(acc[i][p], ap, rb[p]);
            }
        }
        __syncthreads();
    }
    const int n0 = bn + tx*8;
    const int h = n0 >> 6;       // 8 | 64, so the 8 columns stay in one head
    const int dk = n0 & 63;
    #pragma unroll
    for (int i = 0; i < 8; i++) {
        int m = bm + ty*8 + i;
        int bb = m >> 11, l = m & (Ln-1);
        float* po = &out[(((size_t)(bb*Hn + h))*Ln + l)*DKn + dk];
        float2 c0 = unpack2(acc[i][0]), c1 = unpack2(acc[i][1]);
        float2 c2 = unpack2(acc[i][2]), c3 = unpack2(acc[i][3]);
        *(float4*)&po[0] = make_float4(c0.x, c0.y, c1.x, c1.y);
        *(float4*)&po[4] = make_float4(c2.x, c2.y, c3.x, c3.y);
    }
}

// ---------------------------------------------------------------------------
// Scores: u[bh,q,j] = exp((q.k)/8) or 0 if masked. Writes u to sc (the
// unnormalized attn output) and deterministic per-block partial row sums.
// Block: 128q x 128j, 8x8 per thread, 256 threads. DK split into 2 chunks.
// ---------------------------------------------------------------------------
__global__ __launch_bounds__(256, 2) void scores_kernel(const int* __restrict__ mask,
                                                        float* __restrict__ sc) {
    const int bh = blockIdx.z;
    const int q0 = blockIdx.y * 128;
    const int j0 = blockIdx.x * 128;
    const int b = bh >> 4;
    const int tid = threadIdx.x;
    const int tx = tid & 15, ty = tid >> 4;

    __shared__ float Qs[32][132];   // Qs[d][q]
    __shared__ float Ks[32][132];   // Ks[d][j]

    u64 acc[8][4];
    #pragma unroll
    for (int i = 0; i < 8; i++)
        #pragma unroll
        for (int p = 0; p < 4; p++) acc[i][p] = 0ull;

    #pragma unroll
    for (int d0 = 0; d0 < DKn; d0 += 32) {
        // load 128 rows x 32 d (transposed into [d][row])
        #pragma unroll
        for (int it = 0; it < 4; it++) {
            int e = tid + it*256;          // e in [0,1024)
            int r = e >> 3, c4 = (e & 7) * 4;
            float4 vq = *(const float4*)&g_q[(((size_t)bh)*Ln + q0 + r)*DKn + d0 + c4];
            Qs[c4+0][r] = vq.x; Qs[c4+1][r] = vq.y;
            Qs[c4+2][r] = vq.z; Qs[c4+3][r] = vq.w;
            float4 vk = *(const float4*)&g_k[(((size_t)bh)*Ln + j0 + r)*DKn + d0 + c4];
            Ks[c4+0][r] = vk.x; Ks[c4+1][r] = vk.y;
            Ks[c4+2][r] = vk.z; Ks[c4+3][r] = vk.w;
        }
        __syncthreads();
        #pragma unroll
        for (int kk = 0; kk < 32; kk++) {
            float ra[8];
            *(float4*)&ra[0] = *(const float4*)&Qs[kk][ty*8];
            *(float4*)&ra[4] = *(const float4*)&Qs[kk][ty*8+4];
            u64 rb[4];
            *(ulonglong2*)&rb[0] = *(const ulonglong2*)&Ks[kk][tx*8];
            *(ulonglong2*)&rb[2] = *(const ulonglong2*)&Ks[kk][tx*8+4];
            #pragma unroll
            for (int i = 0; i < 8; i++) {
                u64 ap = pack2(ra[i]);
                #pragma unroll
                for (int p = 0; p < 4; p++) fma2(acc[i][p], ap, rb[p]);
            }
        }
        __syncthreads();
    }

    // mask, exponentiate, write u, accumulate row partial sums (per-i,
    // minimal live state to keep registers under the 128 cap)
    float rsum[8];
    #pragma unroll
    for (int i = 0; i < 8; i++) {
        int q = q0 + ty*8 + i;
        float2 c0 = unpack2(acc[i][0]), c1 = unpack2(acc[i][1]);
        float2 c2 = unpack2(acc[i][2]), c3 = unpack2(acc[i][3]);
        size_t mbase = ((size_t)b*Ln + q)*Ln + j0 + tx*8;
        int4 m0 = *(const int4*)(mask + mbase);
        int4 m1 = *(const int4*)(mask + mbase + 4);
        float u0 = m0.x ? 0.f : __expf(c0.x*0.125f);
        float u1 = m0.y ? 0.f : __expf(c0.y*0.125f);
        float u2 = m0.z ? 0.f : __expf(c1.x*0.125f);
        float u3 = m0.w ? 0.f : __expf(c1.y*0.125f);
        float u4 = m1.x ? 0.f : __expf(c2.x*0.125f);
        float u5 = m1.y ? 0.f : __expf(c2.y*0.125f);
        float u6 = m1.z ? 0.f : __expf(c3.x*0.125f);
        float u7 = m1.w ? 0.f : __expf(c3.y*0.125f);
        rsum[i] = ((u0+u1)+(u2+u3)) + ((u4+u5)+(u6+u7));
        size_t sbase = ((size_t)bh*Ln + q)*Ln + j0 + tx*8;
        *(float4*)(sc + sbase)     = make_float4(u0,u1,u2,u3);
        *(float4*)(sc + sbase + 4) = make_float4(u4,u5,u6,u7);
    }

    // reduce across the 16 tx lanes (all in the same warp for a given ty)
    #pragma unroll
    for (int i = 0; i < 8; i++) {
        float s = rsum[i];
        #pragma unroll
        for (int off = 8; off; off >>= 1)
            s += __shfl_xor_sync(0xffffffffu, s, off);
        if (tx == 0) {
            int q = q0 + ty*8 + i;
            g_part[(((size_t)bh)*Ln + q)*16 + blockIdx.x] = s;
        }
    }
}

// ---------------------------------------------------------------------------
// Row-sum reduction: ri[bh,q] = 1 / sum_jb part[bh,q,jb]
// ---------------------------------------------------------------------------
__global__ __launch_bounds__(256) void rowsum_kernel() {
    int row = blockIdx.x * 256 + threadIdx.x;   // bh*Ln + q
    float s = 0.f;
    #pragma unroll
    for (int jb = 0; jb < 16; jb++) s += g_part[(size_t)row*16 + jb];
    g_ri[row] = 1.0f / s;
}

// ---------------------------------------------------------------------------
// PV: p = u * ri written in place (final attn output); o = (sum u*V) * ri.
// Block: 256 q x 64 dk, j chunks of 32. Thread: 8q x 8dk (f32x2 pairs).
// ---------------------------------------------------------------------------
__global__ __launch_bounds__(256, 2) void pv_kernel(float* __restrict__ sc) {
    const int bh = blockIdx.y;
    const int q0 = blockIdx.x * 256;
    const int tid = threadIdx.x;
    const int tx = tid & 7, ty = tid >> 3;   // tx: dk/8, ty: q/8

    __shared__ float Ps[32][260];  // Ps[j][q] (raw u); 260 = mult of 4
    __shared__ float Vs[32][64];   // Vs[j][dk]
    __shared__ float riS[256];

    riS[tid] = g_ri[(size_t)bh*Ln + q0 + tid];

    u64 acc[8][4];
    #pragma unroll
    for (int i = 0; i < 8; i++)
        #pragma unroll
        for (int p = 0; p < 4; p++) acc[i][p] = 0ull;

    for (int j0 = 0; j0 < Ln; j0 += 32) {
        __syncthreads();
        // u tile: 256q x 32j = 2048 float4
        #pragma unroll
        for (int it = 0; it < 8; it++) {
            int e4 = tid + it*256;           // [0,2048)
            int q = e4 >> 3, j4 = (e4 & 7) * 4;
            size_t gi = (((size_t)bh)*Ln + q0 + q)*Ln + j0 + j4;
            float4 u4 = *(const float4*)(sc + gi);
            float ri = riS[q];
            *(float4*)(sc + gi) = make_float4(u4.x*ri, u4.y*ri, u4.z*ri, u4.w*ri);
            Ps[j4+0][q] = u4.x; Ps[j4+1][q] = u4.y;
            Ps[j4+2][q] = u4.z; Ps[j4+3][q] = u4.w;
        }
        // V tile: 32j x 64dk = 512 float4
        #pragma unroll
        for (int it = 0; it < 2; it++) {
            int e4 = tid + it*256;           // [0,512)
            int j = e4 >> 4, d4 = (e4 & 15) * 4;
            *(float4*)&Vs[j][d4] =
                *(const float4*)&g_v[(((size_t)bh)*Ln + j0 + j)*DKn + d4];
        }
        __syncthreads();
        #pragma unroll 8
        for (int jj = 0; jj < 32; jj++) {
            float pv[8];
            *(float4*)&pv[0] = *(const float4*)&Ps[jj][ty*8];
            *(float4*)&pv[4] = *(const float4*)&Ps[jj][ty*8+4];
            u64 vv[4];
            *(ulonglong2*)&vv[0] = *(const ulonglong2*)&Vs[jj][tx*8];
            *(ulonglong2*)&vv[2] = *(const ulonglong2*)&Vs[jj][tx*8+4];
            #pragma unroll
            for (int i = 0; i < 8; i++) {
                u64 ap = pack2(pv[i]);
                #pragma unroll
                for (int p = 0; p < 4; p++) fma2(acc[i][p], ap, vv[p]);
            }
        }
    }

    #pragma unroll
    for (int i = 0; i < 8; i++) {
        int q = q0 + ty*8 + i;
        float ri = riS[ty*8 + i];
        float2 c0 = unpack2(acc[i][0]), c1 = unpack2(acc[i][1]);
        float2 c2 = unpack2(acc[i][2]), c3 = unpack2(acc[i][3]);
        float* po = &g_o[(((size_t)bh)*Ln + q)*DKn + tx*8];
        *(float4*)&po[0] = make_float4(c0.x*ri, c0.y*ri, c1.x*ri, c1.y*ri);
        *(float4*)&po[4] = make_float4(c2.x*ri, c2.y*ri, c3.x*ri, c3.y*ri);
    }
}

// ---------------------------------------------------------------------------
// Residual + LayerNorm: normed[b,l,d] over D=1024, one block per (b,l).
// ---------------------------------------------------------------------------
__global__ __launch_bounds__(256) void ln_kernel(const float* __restrict__ query,
                                                 const float* __restrict__ gamma,
                                                 const float* __restrict__ beta,
                                                 float* __restrict__ out) {
    const int row = blockIdx.x;          // b*L + l
    const int b = row >> 11, l = row & (Ln-1);
    const int tid = threadIdx.x;
    float vals[4];
    float s = 0.f, ss = 0.f;
    #pragma unroll
    for (int it = 0; it < 4; it++) {
        int d = tid + it*256;
        int h = d >> 6, dk = d & 63;
        float o = g_o[(((size_t)(b*Hn + h))*Ln + l)*DKn + dk];
        float r = o + query[(size_t)row*Dn + d];
        vals[it] = r;
        s += r; ss += r*r;
    }
    __shared__ float sm[8], sq[8], stat[2];
    #pragma unroll
    for (int off = 16; off; off >>= 1) {
        s  += __shfl_xor_sync(0xffffffffu, s, off);
        ss += __shfl_xor_sync(0xffffffffu, ss, off);
    }
    int warp = tid >> 5, lane = tid & 31;
    if (lane == 0) { sm[warp] = s; sq[warp] = ss; }
    __syncthreads();
    if (tid == 0) {
        float S = 0.f, SS = 0.f;
        #pragma unroll
        for (int w = 0; w < 8; w++) { S += sm[w]; SS += sq[w]; }
        float mu = S * (1.0f/Dn);
        float var = SS * (1.0f/Dn) - mu*mu;
        stat[0] = mu;
        stat[1] = rsqrtf(var + 1e-6f);
    }
    __syncthreads();
    float mu = stat[0], rstd = stat[1];
    #pragma unroll
    for (int it = 0; it < 4; it++) {
        int d = tid + it*256;
        out[(size_t)row*Dn + d] = (vals[it] - mu) * rstd * gamma[d] + beta[d];
    }
}

// ---------------------------------------------------------------------------
extern "C" void kernel_launch(void* const* d_in, const int* in_sizes, int n_in,
                              void* d_out, int out_size) {
    const float* key   = (const float*)d_in[0];
    const float* value = (const float*)d_in[1];
    const float* query = (const float*)d_in[2];
    const int*   mask  = (const int*)d_in[3];
    const float* Wk = (const float*)d_in[4];
    const float* Wv = (const float*)d_in[5];
    const float* Wq = (const float*)d_in[6];
    const float* lng = (const float*)d_in[7];
    const float* lnb = (const float*)d_in[8];

    float* normed = (float*)d_out;                       // [B, L, D]
    float* attn;
    if ((size_t)out_size > (size_t)Bn*Ln*Dn) {
        attn = normed + (size_t)Bn*Ln*Dn;                // [B*H, L, L]
    } else {
        cudaGetSymbolAddress((void**)&attn, g_sc);
    }

    dim3 gp(Dn/128, Mn/128);     // (8, 32)
    proj_kernel<<<gp, 256>>>(key,   Wk, 0);
    proj_kernel<<<gp, 256>>>(value, Wv, 1);
    proj_kernel<<<gp, 256>>>(query, Wq, 2);

    dim3 gs(Ln/128, Ln/128, BHn);   // (16, 16, 32)
    scores_kernel<<<gs, 256>>>(mask, attn);

    rowsum_kernel<<<(BHn*Ln)/256, 256>>>();

    dim3 gv(Ln/256, BHn);        // (8, 32)
    pv_kernel<<<gv, 256>>>(attn);

    ln_kernel<<<Mn, 256>>>(query, lng, lnb, normed);
}

// round 6
// speedup vs baseline: 1.8139x; 1.2153x over previous
#include <cuda_runtime.h>
#include <cstdint>
#include <math.h>

#define Bn 2
#define Ln 2048
#define Dn 1024
#define Hn 16
#define DKn 64
#define BHn (Bn*Hn)      // 32
#define Mn (Bn*Ln)       // 4096

typedef unsigned long long u64;

// Scratch (device globals — no allocation allowed)
__device__ float g_k[(size_t)BHn*Ln*DKn];
__device__ float g_v[(size_t)BHn*Ln*DKn];
__device__ float g_q[(size_t)BHn*Ln*DKn];
__device__ float g_o[(size_t)BHn*Ln*DKn];
__device__ float g_part[(size_t)BHn*Ln*32]; // per-(block,warp_n) partial row sums
__device__ float g_ri[(size_t)BHn*Ln];      // 1 / rowsum
// Fallback scores buffer in case the harness output holds only `normed`
__device__ float g_sc[(size_t)BHn*Ln*Ln];

// ---- packed fp32 helpers (FFMA2 via PTX) ----
__device__ __forceinline__ u64 pack2(float a) {
    u64 r; unsigned int u = __float_as_uint(a);
    asm("mov.b64 %0, {%1, %1};" : "=l"(r) : "r"(u));
    return r;
}
__device__ __forceinline__ void fma2(u64& d, u64 a, u64 b) {
    asm("fma.rn.f32x2 %0, %1, %2, %0;" : "+l"(d) : "l"(a), "l"(b));
}
__device__ __forceinline__ float2 unpack2(u64 v) {
    unsigned int lo, hi;
    asm("mov.b64 {%0, %1}, %2;" : "=r"(lo), "=r"(hi) : "l"(v));
    return make_float2(__uint_as_float(lo), __uint_as_float(hi));
}

// ---- tf32 mma helpers ----
__device__ __forceinline__ unsigned f2tf(float x) {
    unsigned r; asm("cvt.rna.tf32.f32 %0, %1;" : "=r"(r) : "f"(x));
    return r;
}
// D(16x8,f32) += A(16x8,tf32) * B(8x8,tf32)
__device__ __forceinline__ void mma_tf32(float* c, const unsigned* a, const unsigned* b) {
    asm volatile(
        "mma.sync.aligned.m16n8k8.row.col.f32.tf32.tf32.f32 "
        "{%0,%1,%2,%3}, {%4,%5,%6,%7}, {%8,%9}, {%0,%1,%2,%3};"
        : "+f"(c[0]), "+f"(c[1]), "+f"(c[2]), "+f"(c[3])
        : "r"(a[0]), "r"(a[1]), "r"(a[2]), "r"(a[3]),
          "r"(b[0]), "r"(b[1]));
}

// ---------------------------------------------------------------------------
// Projection GEMM (unchanged, FFMA2): out[b,h,l,dk] = sum_d X[b,l,d]*W[d,h*DK+dk]
// ---------------------------------------------------------------------------
__global__ __launch_bounds__(256, 2) void proj_kernel(const float* __restrict__ X,
                                                      const float* __restrict__ W,
                                                      int which) {
    float* out = (which == 0) ? g_k : ((which == 1) ? g_v : g_q);
    __shared__ float As[8][132];
    __shared__ float Bs[8][132];
    const int bm = blockIdx.y * 128;
    const int bn = blockIdx.x * 128;
    const int tid = threadIdx.x;
    const int tx = tid & 15, ty = tid >> 4;

    u64 acc[8][4];
    #pragma unroll
    for (int i = 0; i < 8; i++)
        #pragma unroll
        for (int p = 0; p < 4; p++) acc[i][p] = 0ull;

    const int am = tid >> 1;
    const int ak = (tid & 1) * 4;
    const int bk = tid >> 5;
    const int bn4 = (tid & 31) * 4;

    for (int k0 = 0; k0 < Dn; k0 += 8) {
        float4 a = *(const float4*)&X[(size_t)(bm + am) * Dn + k0 + ak];
        As[ak+0][am] = a.x; As[ak+1][am] = a.y;
        As[ak+2][am] = a.z; As[ak+3][am] = a.w;
        float4 b = *(const float4*)&W[(size_t)(k0 + bk) * Dn + bn + bn4];
        *(float4*)&Bs[bk][bn4] = b;
        __syncthreads();
        #pragma unroll
        for (int kk = 0; kk < 8; kk++) {
            float ra[8];
            *(float4*)&ra[0] = *(const float4*)&As[kk][ty*8];
            *(float4*)&ra[4] = *(const float4*)&As[kk][ty*8+4];
            u64 rb[4];
            *(ulonglong2*)&rb[0] = *(const ulonglong2*)&Bs[kk][tx*8];
            *(ulonglong2*)&rb[2] = *(const ulonglong2*)&Bs[kk][tx*8+4];
            #pragma unroll
            for (int i = 0; i < 8; i++) {
                u64 ap = pack2(ra[i]);
                #pragma unroll
                for (int p = 0; p < 4; p++) fma2(acc[i][p], ap, rb[p]);
            }
        }
        __syncthreads();
    }
    const int n0 = bn + tx*8;
    const int h = n0 >> 6;
    const int dk = n0 & 63;
    #pragma unroll
    for (int i = 0; i < 8; i++) {
        int m = bm + ty*8 + i;
        int bb = m >> 11, l = m & (Ln-1);
        float* po = &out[(((size_t)(bb*Hn + h))*Ln + l)*DKn + dk];
        float2 c0 = unpack2(acc[i][0]), c1 = unpack2(acc[i][1]);
        float2 c2 = unpack2(acc[i][2]), c3 = unpack2(acc[i][3]);
        *(float4*)&po[0] = make_float4(c0.x, c0.y, c1.x, c1.y);
        *(float4*)&po[4] = make_float4(c2.x, c2.y, c3.x, c3.y);
    }
}

// ---------------------------------------------------------------------------
// Scores via tf32 mma: u[bh,q,j] = exp((q.k)/8) or 0 if masked.
// Block 128q x 128j, 8 warps = 4(m) x 2(n); warp tile 32q x 64j.
// ---------------------------------------------------------------------------
__global__ __launch_bounds__(256, 2) void scores_kernel(const int* __restrict__ mask,
                                                        float* __restrict__ sc) {
    const int bh = blockIdx.z;
    const int q0 = blockIdx.y * 128;
    const int j0 = blockIdx.x * 128;
    const int b = bh >> 4;
    const int tid = threadIdx.x;
    const int w = tid >> 5, lane = tid & 31;
    const int g = lane >> 2, t = lane & 3;
    const int qw = (w >> 1) * 32;     // warp q offset within tile
    const int jw = (w & 1) * 64;      // warp j offset within tile

    __shared__ unsigned Qs[128][36];  // tf32 bits, stride 36 (conflict-free frags)
    __shared__ unsigned Ks[128][36];

    float acc[2][8][4];
    #pragma unroll
    for (int mt = 0; mt < 2; mt++)
        #pragma unroll
        for (int nt = 0; nt < 8; nt++)
            #pragma unroll
            for (int c = 0; c < 4; c++) acc[mt][nt][c] = 0.f;

    #pragma unroll
    for (int dc = 0; dc < DKn; dc += 32) {
        __syncthreads();
        #pragma unroll
        for (int it = 0; it < 4; it++) {
            int e = tid + it*256;         // [0,1024)
            int r = e >> 3, c4 = (e & 7) * 4;
            float4 vq = *(const float4*)&g_q[((size_t)bh*Ln + q0 + r)*DKn + dc + c4];
            Qs[r][c4+0] = f2tf(vq.x); Qs[r][c4+1] = f2tf(vq.y);
            Qs[r][c4+2] = f2tf(vq.z); Qs[r][c4+3] = f2tf(vq.w);
            float4 vk = *(const float4*)&g_k[((size_t)bh*Ln + j0 + r)*DKn + dc + c4];
            Ks[r][c4+0] = f2tf(vk.x); Ks[r][c4+1] = f2tf(vk.y);
            Ks[r][c4+2] = f2tf(vk.z); Ks[r][c4+3] = f2tf(vk.w);
        }
        __syncthreads();
        #pragma unroll
        for (int ks = 0; ks < 4; ks++) {
            int k = ks * 8;
            unsigned a[2][4];
            #pragma unroll
            for (int mt = 0; mt < 2; mt++) {
                int r = qw + mt*16 + g;
                a[mt][0] = Qs[r][k+t];
                a[mt][1] = Qs[r+8][k+t];
                a[mt][2] = Qs[r][k+t+4];
                a[mt][3] = Qs[r+8][k+t+4];
            }
            #pragma unroll
            for (int nt = 0; nt < 8; nt++) {
                unsigned b2[2];
                int r = jw + nt*8 + g;
                b2[0] = Ks[r][k+t];
                b2[1] = Ks[r][k+t+4];
                mma_tf32(acc[0][nt], a[0], b2);
                mma_tf32(acc[1][nt], a[1], b2);
            }
        }
    }

    // epilogue: mask, exp, store u, per-row partial sums
    #pragma unroll
    for (int mt = 0; mt < 2; mt++) {
        #pragma unroll
        for (int h2 = 0; h2 < 2; h2++) {
            int q = q0 + qw + mt*16 + h2*8 + g;
            float s = 0.f;
            #pragma unroll
            for (int nt = 0; nt < 8; nt++) {
                int j = j0 + jw + nt*8 + 2*t;
                int2 mv = *(const int2*)(mask + ((size_t)b*Ln + q)*Ln + j);
                float c0 = acc[mt][nt][h2*2+0];
                float c1 = acc[mt][nt][h2*2+1];
                float u0 = mv.x ? 0.f : __expf(c0*0.125f);
                float u1 = mv.y ? 0.f : __expf(c1*0.125f);
                s += u0 + u1;
                *(float2*)(sc + ((size_t)bh*Ln + q)*Ln + j) = make_float2(u0, u1);
            }
            s += __shfl_xor_sync(0xffffffffu, s, 1);
            s += __shfl_xor_sync(0xffffffffu, s, 2);
            if (t == 0)
                g_part[((size_t)bh*Ln + q)*32 + blockIdx.x*2 + (w & 1)] = s;
        }
    }
}

// ---------------------------------------------------------------------------
// Row-sum reduction: ri[bh,q] = 1 / sum of 32 partials
// ---------------------------------------------------------------------------
__global__ __launch_bounds__(256) void rowsum_kernel() {
    int row = blockIdx.x * 256 + threadIdx.x;   // bh*Ln + q
    float s = 0.f;
    #pragma unroll
    for (int jb = 0; jb < 32; jb++) s += g_part[(size_t)row*32 + jb];
    g_ri[row] = 1.0f / s;
}

// ---------------------------------------------------------------------------
// PV via tf32 mma: normalize u in place (final attn), o = sum p*V.
// Block 128q x 64dk, j chunks of 32; 8 warps, warp tile 16q x 64dk.
// ---------------------------------------------------------------------------
__global__ __launch_bounds__(256, 2) void pv_kernel(float* __restrict__ sc) {
    const int bh = blockIdx.y;
    const int q0 = blockIdx.x * 128;
    const int tid = threadIdx.x;
    const int w = tid >> 5, lane = tid & 31;
    const int g = lane >> 2, t = lane & 3;
    const int qw = w * 16;

    __shared__ unsigned Ps[128][36];  // tf32 of normalized p
    __shared__ unsigned Vs[32][72];   // tf32 of V tile; stride 72 conflict-free
    __shared__ float riS[128];

    if (tid < 128) riS[tid] = g_ri[(size_t)bh*Ln + q0 + tid];

    float acc[8][4];
    #pragma unroll
    for (int nt = 0; nt < 8; nt++)
        #pragma unroll
        for (int c = 0; c < 4; c++) acc[nt][c] = 0.f;

    for (int j0 = 0; j0 < Ln; j0 += 32) {
        __syncthreads();
        // stage P: 128q x 32j; normalize into sc, tf32 into Ps
        #pragma unroll
        for (int it = 0; it < 4; it++) {
            int e4 = tid + it*256;          // [0,1024)
            int q = e4 >> 3, j4 = (e4 & 7) * 4;
            size_t gi = ((size_t)bh*Ln + q0 + q)*Ln + j0 + j4;
            float4 u4 = *(const float4*)(sc + gi);
            float ri = riS[q];
            float p0 = u4.x*ri, p1 = u4.y*ri, p2 = u4.z*ri, p3 = u4.w*ri;
            *(float4*)(sc + gi) = make_float4(p0, p1, p2, p3);
            Ps[q][j4+0] = f2tf(p0); Ps[q][j4+1] = f2tf(p1);
            Ps[q][j4+2] = f2tf(p2); Ps[q][j4+3] = f2tf(p3);
        }
        // stage V: 32j x 64dk
        #pragma unroll
        for (int it = 0; it < 2; it++) {
            int e4 = tid + it*256;          // [0,512)
            int j = e4 >> 4, d4 = (e4 & 15) * 4;
            float4 v4 = *(const float4*)&g_v[((size_t)bh*Ln + j0 + j)*DKn + d4];
            Vs[j][d4+0] = f2tf(v4.x); Vs[j][d4+1] = f2tf(v4.y);
            Vs[j][d4+2] = f2tf(v4.z); Vs[j][d4+3] = f2tf(v4.w);
        }
        __syncthreads();
        #pragma unroll
        for (int ks = 0; ks < 4; ks++) {
            int k = ks * 8;
            unsigned a[4];
            a[0] = Ps[qw + g][k+t];
            a[1] = Ps[qw + 8 + g][k+t];
            a[2] = Ps[qw + g][k+t+4];
            a[3] = Ps[qw + 8 + g][k+t+4];
            #pragma unroll
            for (int nt = 0; nt < 8; nt++) {
                unsigned b2[2];
                b2[0] = Vs[k+t][nt*8 + g];
                b2[1] = Vs[k+t+4][nt*8 + g];
                mma_tf32(acc[nt], a, b2);
            }
        }
    }

    // epilogue: acc already holds normalized output
    #pragma unroll
    for (int h2 = 0; h2 < 2; h2++) {
        int q = q0 + qw + h2*8 + g;
        #pragma unroll
        for (int nt = 0; nt < 8; nt++) {
            int d = nt*8 + 2*t;
            *(float2*)&g_o[((size_t)bh*Ln + q)*DKn + d] =
                make_float2(acc[nt][h2*2+0], acc[nt][h2*2+1]);
        }
    }
}

// ---------------------------------------------------------------------------
// Residual + LayerNorm (unchanged)
// ---------------------------------------------------------------------------
__global__ __launch_bounds__(256) void ln_kernel(const float* __restrict__ query,
                                                 const float* __restrict__ gamma,
                                                 const float* __restrict__ beta,
                                                 float* __restrict__ out) {
    const int row = blockIdx.x;          // b*L + l
    const int b = row >> 11, l = row & (Ln-1);
    const int tid = threadIdx.x;
    float vals[4];
    float s = 0.f, ss = 0.f;
    #pragma unroll
    for (int it = 0; it < 4; it++) {
        int d = tid + it*256;
        int h = d >> 6, dk = d & 63;
        float o = g_o[(((size_t)(b*Hn + h))*Ln + l)*DKn + dk];
        float r = o + query[(size_t)row*Dn + d];
        vals[it] = r;
        s += r; ss += r*r;
    }
    __shared__ float sm[8], sq[8], stat[2];
    #pragma unroll
    for (int off = 16; off; off >>= 1) {
        s  += __shfl_xor_sync(0xffffffffu, s, off);
        ss += __shfl_xor_sync(0xffffffffu, ss, off);
    }
    int warp = tid >> 5, lane = tid & 31;
    if (lane == 0) { sm[warp] = s; sq[warp] = ss; }
    __syncthreads();
    if (tid == 0) {
        float S = 0.f, SS = 0.f;
        #pragma unroll
        for (int w = 0; w < 8; w++) { S += sm[w]; SS += sq[w]; }
        float mu = S * (1.0f/Dn);
        float var = SS * (1.0f/Dn) - mu*mu;
        stat[0] = mu;
        stat[1] = rsqrtf(var + 1e-6f);
    }
    __syncthreads();
    float mu = stat[0], rstd = stat[1];
    #pragma unroll
    for (int it = 0; it < 4; it++) {
        int d = tid + it*256;
        out[(size_t)row*Dn + d] = (vals[it] - mu) * rstd * gamma[d] + beta[d];
    }
}

// ---------------------------------------------------------------------------
extern "C" void kernel_launch(void* const* d_in, const int* in_sizes, int n_in,
                              void* d_out, int out_size) {
    const float* key   = (const float*)d_in[0];
    const float* value = (const float*)d_in[1];
    const float* query = (const float*)d_in[2];
    const int*   mask  = (const int*)d_in[3];
    const float* Wk = (const float*)d_in[4];
    const float* Wv = (const float*)d_in[5];
    const float* Wq = (const float*)d_in[6];
    const float* lng = (const float*)d_in[7];
    const float* lnb = (const float*)d_in[8];

    float* normed = (float*)d_out;                       // [B, L, D]
    float* attn;
    if ((size_t)out_size > (size_t)Bn*Ln*Dn) {
        attn = normed + (size_t)Bn*Ln*Dn;                // [B*H, L, L]
    } else {
        cudaGetSymbolAddress((void**)&attn, g_sc);
    }

    dim3 gp(Dn/128, Mn/128);     // (8, 32)
    proj_kernel<<<gp, 256>>>(key,   Wk, 0);
    proj_kernel<<<gp, 256>>>(value, Wv, 1);
    proj_kernel<<<gp, 256>>>(query, Wq, 2);

    dim3 gs(Ln/128, Ln/128, BHn);   // (16, 16, 32)
    scores_kernel<<<gs, 256>>>(mask, attn);

    rowsum_kernel<<<(BHn*Ln)/256, 256>>>();

    dim3 gv(Ln/128, BHn);        // (16, 32)
    pv_kernel<<<gv, 256>>>(attn);

    ln_kernel<<<Mn, 256>>>(query, lng, lnb, normed);
}

// round 7
// speedup vs baseline: 2.7092x; 1.4935x over previous
#include <cuda_runtime.h>
#include <cstdint>
#include <math.h>

#define Bn 2
#define Ln 2048
#define Dn 1024
#define Hn 16
#define DKn 64
#define BHn (Bn*Hn)      // 32
#define Mn (Bn*Ln)       // 4096

// Scratch (device globals — no allocation allowed)
__device__ float g_k[(size_t)BHn*Ln*DKn];
__device__ float g_v[(size_t)BHn*Ln*DKn];
__device__ float g_q[(size_t)BHn*Ln*DKn];
__device__ float g_o[(size_t)BHn*Ln*DKn];
__device__ float g_part[(size_t)BHn*Ln*32]; // per-(block,warp_n) partial row sums
__device__ float g_ri[(size_t)BHn*Ln];      // 1 / rowsum
// Fallback scores buffer in case the harness output holds only `normed`
__device__ float g_sc[(size_t)BHn*Ln*Ln];

// ---- tf32 mma helpers ----
__device__ __forceinline__ unsigned f2tf(float x) {
    unsigned r; asm("cvt.rna.tf32.f32 %0, %1;" : "=r"(r) : "f"(x));
    return r;
}
// D(16x8,f32) += A(16x8,tf32) * B(8x8,tf32)
__device__ __forceinline__ void mma_tf32(float* c, const unsigned* a, const unsigned* b) {
    asm volatile(
        "mma.sync.aligned.m16n8k8.row.col.f32.tf32.tf32.f32 "
        "{%0,%1,%2,%3}, {%4,%5,%6,%7}, {%8,%9}, {%0,%1,%2,%3};"
        : "+f"(c[0]), "+f"(c[1]), "+f"(c[2]), "+f"(c[3])
        : "r"(a[0]), "r"(a[1]), "r"(a[2]), "r"(a[3]),
          "r"(b[0]), "r"(b[1]));
}

// ---------------------------------------------------------------------------
// Fused projection GEMMs via tf32 mma: out[b,h,l,dk] = sum_d X[b,l,d]*W[d,n]
// blockIdx.z selects (X, W, out) in {K, V, Q}.
// Block 128m x 128n, k-chunks of 32; 8 warps = 4(m) x 2(n), warp 32m x 64n.
// ---------------------------------------------------------------------------
__global__ __launch_bounds__(256, 2) void proj_kernel(const float* __restrict__ Xk,
                                                      const float* __restrict__ Xv,
                                                      const float* __restrict__ Xq,
                                                      const float* __restrict__ Wk,
                                                      const float* __restrict__ Wv,
                                                      const float* __restrict__ Wq) {
    const int which = blockIdx.z;
    const float* X = (which == 0) ? Xk : ((which == 1) ? Xv : Xq);
    const float* W = (which == 0) ? Wk : ((which == 1) ? Wv : Wq);
    float* out = (which == 0) ? g_k : ((which == 1) ? g_v : g_q);

    const int bm = blockIdx.y * 128;
    const int bn = blockIdx.x * 128;
    const int tid = threadIdx.x;
    const int w = tid >> 5, lane = tid & 31;
    const int g = lane >> 2, t = lane & 3;
    const int mw = (w >> 1) * 32;     // warp m offset within tile
    const int nw = (w & 1) * 64;      // warp n offset within tile

    __shared__ unsigned Xs[128][36];   // [m][k], stride 36 (conflict-free frags)
    __shared__ unsigned Ws[32][136];   // [k][n], stride 136 (conflict-free frags)

    float acc[2][8][4];
    #pragma unroll
    for (int mt = 0; mt < 2; mt++)
        #pragma unroll
        for (int nt = 0; nt < 8; nt++)
            #pragma unroll
            for (int c = 0; c < 4; c++) acc[mt][nt][c] = 0.f;

    for (int k0 = 0; k0 < Dn; k0 += 32) {
        __syncthreads();
        // stage X: 128 m-rows x 32 k
        #pragma unroll
        for (int it = 0; it < 4; it++) {
            int e = tid + it*256;             // [0,1024) float4 slots
            int r = e >> 3, c4 = (e & 7) * 4;
            float4 v = *(const float4*)&X[(size_t)(bm + r)*Dn + k0 + c4];
            Xs[r][c4+0] = f2tf(v.x); Xs[r][c4+1] = f2tf(v.y);
            Xs[r][c4+2] = f2tf(v.z); Xs[r][c4+3] = f2tf(v.w);
        }
        // stage W: 32 k-rows x 128 n (no transpose; fragment reads row k, col n)
        #pragma unroll
        for (int it = 0; it < 4; it++) {
            int e = tid + it*256;             // [0,1024) float4 slots
            int kr = e >> 5, n4 = (e & 31) * 4;
            float4 v = *(const float4*)&W[(size_t)(k0 + kr)*Dn + bn + n4];
            Ws[kr][n4+0] = f2tf(v.x); Ws[kr][n4+1] = f2tf(v.y);
            Ws[kr][n4+2] = f2tf(v.z); Ws[kr][n4+3] = f2tf(v.w);
        }
        __syncthreads();
        #pragma unroll
        for (int ks = 0; ks < 4; ks++) {
            int k = ks * 8;
            unsigned a[2][4];
            #pragma unroll
            for (int mt = 0; mt < 2; mt++) {
                int r = mw + mt*16 + g;
                a[mt][0] = Xs[r][k+t];
                a[mt][1] = Xs[r+8][k+t];
                a[mt][2] = Xs[r][k+t+4];
                a[mt][3] = Xs[r+8][k+t+4];
            }
            #pragma unroll
            for (int nt = 0; nt < 8; nt++) {
                unsigned b2[2];
                int n = nw + nt*8 + g;
                b2[0] = Ws[k+t][n];
                b2[1] = Ws[k+t+4][n];
                mma_tf32(acc[0][nt], a[0], b2);
                mma_tf32(acc[1][nt], a[1], b2);
            }
        }
    }

    // epilogue: write to [b,h,l,dk] layout (n even, so float2 stays in one head)
    #pragma unroll
    for (int mt = 0; mt < 2; mt++) {
        #pragma unroll
        for (int h2 = 0; h2 < 2; h2++) {
            int m = bm + mw + mt*16 + h2*8 + g;
            int bb = m >> 11, l = m & (Ln-1);
            #pragma unroll
            for (int nt = 0; nt < 8; nt++) {
                int n = bn + nw + nt*8 + 2*t;
                int h = n >> 6, dk = n & 63;
                *(float2*)&out[(((size_t)(bb*Hn + h))*Ln + l)*DKn + dk] =
                    make_float2(acc[mt][nt][h2*2+0], acc[mt][nt][h2*2+1]);
            }
        }
    }
}

// ---------------------------------------------------------------------------
// Scores via tf32 mma: u[bh,q,j] = exp((q.k)/8) or 0 if masked.
// Block 128q x 128j, 8 warps = 4(m) x 2(n); warp tile 32q x 64j.
// ---------------------------------------------------------------------------
__global__ __launch_bounds__(256, 2) void scores_kernel(const int* __restrict__ mask,
                                                        float* __restrict__ sc) {
    const int bh = blockIdx.z;
    const int q0 = blockIdx.y * 128;
    const int j0 = blockIdx.x * 128;
    const int b = bh >> 4;
    const int tid = threadIdx.x;
    const int w = tid >> 5, lane = tid & 31;
    const int g = lane >> 2, t = lane & 3;
    const int qw = (w >> 1) * 32;     // warp q offset within tile
    const int jw = (w & 1) * 64;      // warp j offset within tile

    __shared__ unsigned Qs[128][36];  // tf32 bits, stride 36 (conflict-free frags)
    __shared__ unsigned Ks[128][36];

    float acc[2][8][4];
    #pragma unroll
    for (int mt = 0; mt < 2; mt++)
        #pragma unroll
        for (int nt = 0; nt < 8; nt++)
            #pragma unroll
            for (int c = 0; c < 4; c++) acc[mt][nt][c] = 0.f;

    #pragma unroll
    for (int dc = 0; dc < DKn; dc += 32) {
        __syncthreads();
        #pragma unroll
        for (int it = 0; it < 4; it++) {
            int e = tid + it*256;         // [0,1024)
            int r = e >> 3, c4 = (e & 7) * 4;
            float4 vq = *(const float4*)&g_q[((size_t)bh*Ln + q0 + r)*DKn + dc + c4];
            Qs[r][c4+0] = f2tf(vq.x); Qs[r][c4+1] = f2tf(vq.y);
            Qs[r][c4+2] = f2tf(vq.z); Qs[r][c4+3] = f2tf(vq.w);
            float4 vk = *(const float4*)&g_k[((size_t)bh*Ln + j0 + r)*DKn + dc + c4];
            Ks[r][c4+0] = f2tf(vk.x); Ks[r][c4+1] = f2tf(vk.y);
            Ks[r][c4+2] = f2tf(vk.z); Ks[r][c4+3] = f2tf(vk.w);
        }
        __syncthreads();
        #pragma unroll
        for (int ks = 0; ks < 4; ks++) {
            int k = ks * 8;
            unsigned a[2][4];
            #pragma unroll
            for (int mt = 0; mt < 2; mt++) {
                int r = qw + mt*16 + g;
                a[mt][0] = Qs[r][k+t];
                a[mt][1] = Qs[r+8][k+t];
                a[mt][2] = Qs[r][k+t+4];
                a[mt][3] = Qs[r+8][k+t+4];
            }
            #pragma unroll
            for (int nt = 0; nt < 8; nt++) {
                unsigned b2[2];
                int r = jw + nt*8 + g;
                b2[0] = Ks[r][k+t];
                b2[1] = Ks[r][k+t+4];
                mma_tf32(acc[0][nt], a[0], b2);
                mma_tf32(acc[1][nt], a[1], b2);
            }
        }
    }

    // epilogue: mask, exp, store u, per-row partial sums
    #pragma unroll
    for (int mt = 0; mt < 2; mt++) {
        #pragma unroll
        for (int h2 = 0; h2 < 2; h2++) {
            int q = q0 + qw + mt*16 + h2*8 + g;
            float s = 0.f;
            #pragma unroll
            for (int nt = 0; nt < 8; nt++) {
                int j = j0 + jw + nt*8 + 2*t;
                int2 mv = *(const int2*)(mask + ((size_t)b*Ln + q)*Ln + j);
                float c0 = acc[mt][nt][h2*2+0];
                float c1 = acc[mt][nt][h2*2+1];
                float u0 = mv.x ? 0.f : __expf(c0*0.125f);
                float u1 = mv.y ? 0.f : __expf(c1*0.125f);
                s += u0 + u1;
                *(float2*)(sc + ((size_t)bh*Ln + q)*Ln + j) = make_float2(u0, u1);
            }
            s += __shfl_xor_sync(0xffffffffu, s, 1);
            s += __shfl_xor_sync(0xffffffffu, s, 2);
            if (t == 0)
                g_part[((size_t)bh*Ln + q)*32 + blockIdx.x*2 + (w & 1)] = s;
        }
    }
}

// ---------------------------------------------------------------------------
// Row-sum reduction: ri[bh,q] = 1 / sum of 32 partials
// ---------------------------------------------------------------------------
__global__ __launch_bounds__(256) void rowsum_kernel() {
    int row = blockIdx.x * 256 + threadIdx.x;   // bh*Ln + q
    float s = 0.f;
    #pragma unroll
    for (int jb = 0; jb < 32; jb++) s += g_part[(size_t)row*32 + jb];
    g_ri[row] = 1.0f / s;
}

// ---------------------------------------------------------------------------
// PV via tf32 mma: normalize u in place (final attn), o = sum p*V.
// Block 128q x 64dk, j chunks of 32; 8 warps, warp tile 16q x 64dk.
// ---------------------------------------------------------------------------
__global__ __launch_bounds__(256, 2) void pv_kernel(float* __restrict__ sc) {
    const int bh = blockIdx.y;
    const int q0 = blockIdx.x * 128;
    const int tid = threadIdx.x;
    const int w = tid >> 5, lane = tid & 31;
    const int g = lane >> 2, t = lane & 3;
    const int qw = w * 16;

    __shared__ unsigned Ps[128][36];  // tf32 of normalized p
    __shared__ unsigned Vs[32][72];   // tf32 of V tile; stride 72 conflict-free
    __shared__ float riS[128];

    if (tid < 128) riS[tid] = g_ri[(size_t)bh*Ln + q0 + tid];

    float acc[8][4];
    #pragma unroll
    for (int nt = 0; nt < 8; nt++)
        #pragma unroll
        for (int c = 0; c < 4; c++) acc[nt][c] = 0.f;

    for (int j0 = 0; j0 < Ln; j0 += 32) {
        __syncthreads();
        // stage P: 128q x 32j; normalize into sc, tf32 into Ps
        #pragma unroll
        for (int it = 0; it < 4; it++) {
            int e4 = tid + it*256;          // [0,1024)
            int q = e4 >> 3, j4 = (e4 & 7) * 4;
            size_t gi = ((size_t)bh*Ln + q0 + q)*Ln + j0 + j4;
            float4 u4 = *(const float4*)(sc + gi);
            float ri = riS[q];
            float p0 = u4.x*ri, p1 = u4.y*ri, p2 = u4.z*ri, p3 = u4.w*ri;
            *(float4*)(sc + gi) = make_float4(p0, p1, p2, p3);
            Ps[q][j4+0] = f2tf(p0); Ps[q][j4+1] = f2tf(p1);
            Ps[q][j4+2] = f2tf(p2); Ps[q][j4+3] = f2tf(p3);
        }
        // stage V: 32j x 64dk
        #pragma unroll
        for (int it = 0; it < 2; it++) {
            int e4 = tid + it*256;          // [0,512)
            int j = e4 >> 4, d4 = (e4 & 15) * 4;
            float4 v4 = *(const float4*)&g_v[((size_t)bh*Ln + j0 + j)*DKn + d4];
            Vs[j][d4+0] = f2tf(v4.x); Vs[j][d4+1] = f2tf(v4.y);
            Vs[j][d4+2] = f2tf(v4.z); Vs[j][d4+3] = f2tf(v4.w);
        }
        __syncthreads();
        #pragma unroll
        for (int ks = 0; ks < 4; ks++) {
            int k = ks * 8;
            unsigned a[4];
            a[0] = Ps[qw + g][k+t];
            a[1] = Ps[qw + 8 + g][k+t];
            a[2] = Ps[qw + g][k+t+4];
            a[3] = Ps[qw + 8 + g][k+t+4];
            #pragma unroll
            for (int nt = 0; nt < 8; nt++) {
                unsigned b2[2];
                b2[0] = Vs[k+t][nt*8 + g];
                b2[1] = Vs[k+t+4][nt*8 + g];
                mma_tf32(acc[nt], a, b2);
            }
        }
    }

    // epilogue: acc already holds normalized output
    #pragma unroll
    for (int h2 = 0; h2 < 2; h2++) {
        int q = q0 + qw + h2*8 + g;
        #pragma unroll
        for (int nt = 0; nt < 8; nt++) {
            int d = nt*8 + 2*t;
            *(float2*)&g_o[((size_t)bh*Ln + q)*DKn + d] =
                make_float2(acc[nt][h2*2+0], acc[nt][h2*2+1]);
        }
    }
}

// ---------------------------------------------------------------------------
// Residual + LayerNorm (unchanged)
// ---------------------------------------------------------------------------
__global__ __launch_bounds__(256) void ln_kernel(const float* __restrict__ query,
                                                 const float* __restrict__ gamma,
                                                 const float* __restrict__ beta,
                                                 float* __restrict__ out) {
    const int row = blockIdx.x;          // b*L + l
    const int b = row >> 11, l = row & (Ln-1);
    const int tid = threadIdx.x;
    float vals[4];
    float s = 0.f, ss = 0.f;
    #pragma unroll
    for (int it = 0; it < 4; it++) {
        int d = tid + it*256;
        int h = d >> 6, dk = d & 63;
        float o = g_o[(((size_t)(b*Hn + h))*Ln + l)*DKn + dk];
        float r = o + query[(size_t)row*Dn + d];
        vals[it] = r;
        s += r; ss += r*r;
    }
    __shared__ float sm[8], sq[8], stat[2];
    #pragma unroll
    for (int off = 16; off; off >>= 1) {
        s  += __shfl_xor_sync(0xffffffffu, s, off);
        ss += __shfl_xor_sync(0xffffffffu, ss, off);
    }
    int warp = tid >> 5, lane = tid & 31;
    if (lane == 0) { sm[warp] = s; sq[warp] = ss; }
    __syncthreads();
    if (tid == 0) {
        float S = 0.f, SS = 0.f;
        #pragma unroll
        for (int w = 0; w < 8; w++) { S += sm[w]; SS += sq[w]; }
        float mu = S * (1.0f/Dn);
        float var = SS * (1.0f/Dn) - mu*mu;
        stat[0] = mu;
        stat[1] = rsqrtf(var + 1e-6f);
    }
    __syncthreads();
    float mu = stat[0], rstd = stat[1];
    #pragma unroll
    for (int it = 0; it < 4; it++) {
        int d = tid + it*256;
        out[(size_t)row*Dn + d] = (vals[it] - mu) * rstd * gamma[d] + beta[d];
    }
}

// ---------------------------------------------------------------------------
extern "C" void kernel_launch(void* const* d_in, const int* in_sizes, int n_in,
                              void* d_out, int out_size) {
    const float* key   = (const float*)d_in[0];
    const float* value = (const float*)d_in[1];
    const float* query = (const float*)d_in[2];
    const int*   mask  = (const int*)d_in[3];
    const float* Wk = (const float*)d_in[4];
    const float* Wv = (const float*)d_in[5];
    const float* Wq = (const float*)d_in[6];
    const float* lng = (const float*)d_in[7];
    const float* lnb = (const float*)d_in[8];

    float* normed = (float*)d_out;                       // [B, L, D]
    float* attn;
    if ((size_t)out_size > (size_t)Bn*Ln*Dn) {
        attn = normed + (size_t)Bn*Ln*Dn;                // [B*H, L, L]
    } else {
        cudaGetSymbolAddress((void**)&attn, g_sc);
    }

    dim3 gp(Dn/128, Mn/128, 3);     // (8, 32, 3) — fused K/V/Q projections
    proj_kernel<<<gp, 256>>>(key, value, query, Wk, Wv, Wq);

    dim3 gs(Ln/128, Ln/128, BHn);   // (16, 16, 32)
    scores_kernel<<<gs, 256>>>(mask, attn);

    rowsum_kernel<<<(BHn*Ln)/256, 256>>>();

    dim3 gv(Ln/128, BHn);        // (16, 32)
    pv_kernel<<<gv, 256>>>(attn);

    ln_kernel<<<Mn, 256>>>(query, lng, lnb, normed);
}

// round 8
// speedup vs baseline: 3.7056x; 1.3678x over previous
#include <cuda_runtime.h>
#include <cstdint>
#include <math.h>

#define Bn 2
#define Ln 2048
#define Dn 1024
#define Hn 16
#define DKn 64
#define BHn (Bn*Hn)      // 32
#define Mn (Bn*Ln)       // 4096

// Scratch (device globals — no allocation allowed)
__device__ float g_k[(size_t)BHn*Ln*DKn];
__device__ float g_v[(size_t)BHn*Ln*DKn];
__device__ float g_q[(size_t)BHn*Ln*DKn];
__device__ float g_o[(size_t)BHn*Ln*DKn];
__device__ float g_part[(size_t)BHn*Ln*32]; // per-(block,warp_n) partial row sums
__device__ float g_ri[(size_t)BHn*Ln];      // 1 / rowsum
// Fallback scores buffer in case the harness output holds only `normed`
__device__ float g_sc[(size_t)BHn*Ln*Ln];

// ---- tf32 mma helpers ----
__device__ __forceinline__ unsigned f2tf(float x) {
    unsigned r; asm("cvt.rna.tf32.f32 %0, %1;" : "=r"(r) : "f"(x));
    return r;
}
// D(16x8,f32) += A(16x8,tf32) * B(8x8,tf32)
__device__ __forceinline__ void mma_tf32(float* c, const unsigned* a, const unsigned* b) {
    asm volatile(
        "mma.sync.aligned.m16n8k8.row.col.f32.tf32.tf32.f32 "
        "{%0,%1,%2,%3}, {%4,%5,%6,%7}, {%8,%9}, {%0,%1,%2,%3};"
        : "+f"(c[0]), "+f"(c[1]), "+f"(c[2]), "+f"(c[3])
        : "r"(a[0]), "r"(a[1]), "r"(a[2]), "r"(a[3]),
          "r"(b[0]), "r"(b[1]));
}

// ---- cp.async helpers ----
__device__ __forceinline__ void cp16(void* smem_dst, const void* gmem_src) {
    unsigned dst = (unsigned)__cvta_generic_to_shared(smem_dst);
    asm volatile("cp.async.cg.shared.global [%0], [%1], 16;"
                 :: "r"(dst), "l"(gmem_src));
}
__device__ __forceinline__ void cp_commit() {
    asm volatile("cp.async.commit_group;");
}

// ---------------------------------------------------------------------------
// Fused projection GEMMs via tf32 mma: out[b,h,l,dk] = sum_d X[b,l,d]*W[d,n]
// blockIdx.z selects (X, W, out) in {K, V, Q}.
// ---------------------------------------------------------------------------
__global__ __launch_bounds__(256, 2) void proj_kernel(const float* __restrict__ Xk,
                                                      const float* __restrict__ Xv,
                                                      const float* __restrict__ Xq,
                                                      const float* __restrict__ Wk,
                                                      const float* __restrict__ Wv,
                                                      const float* __restrict__ Wq) {
    const int which = blockIdx.z;
    const float* X = (which == 0) ? Xk : ((which == 1) ? Xv : Xq);
    const float* W = (which == 0) ? Wk : ((which == 1) ? Wv : Wq);
    float* out = (which == 0) ? g_k : ((which == 1) ? g_v : g_q);

    const int bm = blockIdx.y * 128;
    const int bn = blockIdx.x * 128;
    const int tid = threadIdx.x;
    const int w = tid >> 5, lane = tid & 31;
    const int g = lane >> 2, t = lane & 3;
    const int mw = (w >> 1) * 32;
    const int nw = (w & 1) * 64;

    __shared__ unsigned Xs[128][36];
    __shared__ unsigned Ws[32][136];

    float acc[2][8][4];
    #pragma unroll
    for (int mt = 0; mt < 2; mt++)
        #pragma unroll
        for (int nt = 0; nt < 8; nt++)
            #pragma unroll
            for (int c = 0; c < 4; c++) acc[mt][nt][c] = 0.f;

    for (int k0 = 0; k0 < Dn; k0 += 32) {
        __syncthreads();
        #pragma unroll
        for (int it = 0; it < 4; it++) {
            int e = tid + it*256;
            int r = e >> 3, c4 = (e & 7) * 4;
            float4 v = *(const float4*)&X[(size_t)(bm + r)*Dn + k0 + c4];
            Xs[r][c4+0] = f2tf(v.x); Xs[r][c4+1] = f2tf(v.y);
            Xs[r][c4+2] = f2tf(v.z); Xs[r][c4+3] = f2tf(v.w);
        }
        #pragma unroll
        for (int it = 0; it < 4; it++) {
            int e = tid + it*256;
            int kr = e >> 5, n4 = (e & 31) * 4;
            float4 v = *(const float4*)&W[(size_t)(k0 + kr)*Dn + bn + n4];
            Ws[kr][n4+0] = f2tf(v.x); Ws[kr][n4+1] = f2tf(v.y);
            Ws[kr][n4+2] = f2tf(v.z); Ws[kr][n4+3] = f2tf(v.w);
        }
        __syncthreads();
        #pragma unroll
        for (int ks = 0; ks < 4; ks++) {
            int k = ks * 8;
            unsigned a[2][4];
            #pragma unroll
            for (int mt = 0; mt < 2; mt++) {
                int r = mw + mt*16 + g;
                a[mt][0] = Xs[r][k+t];
                a[mt][1] = Xs[r+8][k+t];
                a[mt][2] = Xs[r][k+t+4];
                a[mt][3] = Xs[r+8][k+t+4];
            }
            #pragma unroll
            for (int nt = 0; nt < 8; nt++) {
                unsigned b2[2];
                int n = nw + nt*8 + g;
                b2[0] = Ws[k+t][n];
                b2[1] = Ws[k+t+4][n];
                mma_tf32(acc[0][nt], a[0], b2);
                mma_tf32(acc[1][nt], a[1], b2);
            }
        }
    }

    #pragma unroll
    for (int mt = 0; mt < 2; mt++) {
        #pragma unroll
        for (int h2 = 0; h2 < 2; h2++) {
            int m = bm + mw + mt*16 + h2*8 + g;
            int bb = m >> 11, l = m & (Ln-1);
            #pragma unroll
            for (int nt = 0; nt < 8; nt++) {
                int n = bn + nw + nt*8 + 2*t;
                int h = n >> 6, dk = n & 63;
                *(float2*)&out[(((size_t)(bb*Hn + h))*Ln + l)*DKn + dk] =
                    make_float2(acc[mt][nt][h2*2+0], acc[mt][nt][h2*2+1]);
            }
        }
    }
}

// ---------------------------------------------------------------------------
// Scores via tf32 mma: u[bh,q,j] = exp((q.k)/8) or 0 if masked.
// ---------------------------------------------------------------------------
__global__ __launch_bounds__(256, 2) void scores_kernel(const int* __restrict__ mask,
                                                        float* __restrict__ sc) {
    const int bh = blockIdx.z;
    const int q0 = blockIdx.y * 128;
    const int j0 = blockIdx.x * 128;
    const int b = bh >> 4;
    const int tid = threadIdx.x;
    const int w = tid >> 5, lane = tid & 31;
    const int g = lane >> 2, t = lane & 3;
    const int qw = (w >> 1) * 32;
    const int jw = (w & 1) * 64;

    __shared__ unsigned Qs[128][36];
    __shared__ unsigned Ks[128][36];

    float acc[2][8][4];
    #pragma unroll
    for (int mt = 0; mt < 2; mt++)
        #pragma unroll
        for (int nt = 0; nt < 8; nt++)
            #pragma unroll
            for (int c = 0; c < 4; c++) acc[mt][nt][c] = 0.f;

    #pragma unroll
    for (int dc = 0; dc < DKn; dc += 32) {
        __syncthreads();
        #pragma unroll
        for (int it = 0; it < 4; it++) {
            int e = tid + it*256;
            int r = e >> 3, c4 = (e & 7) * 4;
            float4 vq = *(const float4*)&g_q[((size_t)bh*Ln + q0 + r)*DKn + dc + c4];
            Qs[r][c4+0] = f2tf(vq.x); Qs[r][c4+1] = f2tf(vq.y);
            Qs[r][c4+2] = f2tf(vq.z); Qs[r][c4+3] = f2tf(vq.w);
            float4 vk = *(const float4*)&g_k[((size_t)bh*Ln + j0 + r)*DKn + dc + c4];
            Ks[r][c4+0] = f2tf(vk.x); Ks[r][c4+1] = f2tf(vk.y);
            Ks[r][c4+2] = f2tf(vk.z); Ks[r][c4+3] = f2tf(vk.w);
        }
        __syncthreads();
        #pragma unroll
        for (int ks = 0; ks < 4; ks++) {
            int k = ks * 8;
            unsigned a[2][4];
            #pragma unroll
            for (int mt = 0; mt < 2; mt++) {
                int r = qw + mt*16 + g;
                a[mt][0] = Qs[r][k+t];
                a[mt][1] = Qs[r+8][k+t];
                a[mt][2] = Qs[r][k+t+4];
                a[mt][3] = Qs[r+8][k+t+4];
            }
            #pragma unroll
            for (int nt = 0; nt < 8; nt++) {
                unsigned b2[2];
                int r = jw + nt*8 + g;
                b2[0] = Ks[r][k+t];
                b2[1] = Ks[r][k+t+4];
                mma_tf32(acc[0][nt], a[0], b2);
                mma_tf32(acc[1][nt], a[1], b2);
            }
        }
    }

    #pragma unroll
    for (int mt = 0; mt < 2; mt++) {
        #pragma unroll
        for (int h2 = 0; h2 < 2; h2++) {
            int q = q0 + qw + mt*16 + h2*8 + g;
            float s = 0.f;
            #pragma unroll
            for (int nt = 0; nt < 8; nt++) {
                int j = j0 + jw + nt*8 + 2*t;
                int2 mv = *(const int2*)(mask + ((size_t)b*Ln + q)*Ln + j);
                float c0 = acc[mt][nt][h2*2+0];
                float c1 = acc[mt][nt][h2*2+1];
                float u0 = mv.x ? 0.f : __expf(c0*0.125f);
                float u1 = mv.y ? 0.f : __expf(c1*0.125f);
                s += u0 + u1;
                *(float2*)(sc + ((size_t)bh*Ln + q)*Ln + j) = make_float2(u0, u1);
            }
            s += __shfl_xor_sync(0xffffffffu, s, 1);
            s += __shfl_xor_sync(0xffffffffu, s, 2);
            if (t == 0)
                g_part[((size_t)bh*Ln + q)*32 + blockIdx.x*2 + (w & 1)] = s;
        }
    }
}

// ---------------------------------------------------------------------------
// Row-sum reduction: ri[bh,q] = 1 / sum of 32 partials
// ---------------------------------------------------------------------------
__global__ __launch_bounds__(256) void rowsum_kernel() {
    int row = blockIdx.x * 256 + threadIdx.x;   // bh*Ln + q
    float s = 0.f;
    #pragma unroll
    for (int jb = 0; jb < 32; jb++) s += g_part[(size_t)row*32 + jb];
    g_ri[row] = 1.0f / s;
}

// ---------------------------------------------------------------------------
// PV via tf32 mma, cp.async double-buffered:
//   - u staged raw via cp.async ping-pong (chunk i+1 in flight during chunk i)
//   - V prefetched through registers (single smem buffer)
//   - p = u*ri streamed back in place (final attn); o = (sum u*V)*ri
// Block 128q x 64dk, j chunks of 32; 8 warps, warp tile 16q x 64dk.
// ---------------------------------------------------------------------------
__global__ __launch_bounds__(256, 2) void pv_kernel(float* __restrict__ sc) {
    const int bh = blockIdx.y;
    const int q0 = blockIdx.x * 128;
    const int tid = threadIdx.x;
    const int w = tid >> 5, lane = tid & 31;
    const int g = lane >> 2, t = lane & 3;
    const int qw = w * 16;

    __shared__ float Ps[2][128][36];   // raw u, double-buffered (stride 36: frag-conflict-free, 144B rows)
    __shared__ float Vs[32][72];       // raw V (stride 72: frag-conflict-free, 288B rows)
    __shared__ float riS[128];

    if (tid < 128) riS[tid] = g_ri[(size_t)bh*Ln + q0 + tid];

    const size_t scb = ((size_t)bh*Ln + q0)*Ln;
    const size_t vb  = (size_t)bh*Ln*DKn;

    float acc[8][4];
    #pragma unroll
    for (int nt = 0; nt < 8; nt++)
        #pragma unroll
        for (int c = 0; c < 4; c++) acc[nt][c] = 0.f;

    // prologue: chunk 0 u via cp.async; chunk 0 V into registers
    #pragma unroll
    for (int it = 0; it < 4; it++) {
        int e4 = tid + it*256;
        int q = e4 >> 3, j4 = (e4 & 7) * 4;
        cp16(&Ps[0][q][j4], sc + scb + (size_t)q*Ln + j4);
    }
    cp_commit();
    float4 vr0, vr1;
    {
        int j = tid >> 4, d4 = (tid & 15) * 4;
        vr0 = *(const float4*)&g_v[vb + (size_t)j*DKn + d4];
        int e4 = tid + 256;
        int j2 = e4 >> 4, d42 = (e4 & 15) * 4;
        vr1 = *(const float4*)&g_v[vb + (size_t)j2*DKn + d42];
    }

    const int NCH = Ln / 32;   // 64
    for (int i = 0; i < NCH; i++) {
        const int jc = i * 32;
        float* Pc = &Ps[i & 1][0][0];

        if (i < NCH - 1) {
            #pragma unroll
            for (int it = 0; it < 4; it++) {
                int e4 = tid + it*256;
                int q = e4 >> 3, j4 = (e4 & 7) * 4;
                cp16(&Ps[(i+1) & 1][q][j4], sc + scb + (size_t)q*Ln + jc + 32 + j4);
            }
            cp_commit();
            asm volatile("cp.async.wait_group 1;");
        } else {
            asm volatile("cp.async.wait_group 0;");
        }

        // stash prefetched V, then sync (u chunk i + V chunk i visible to all)
        {
            int j = tid >> 4, d4 = (tid & 15) * 4;
            *(float4*)&Vs[j][d4] = vr0;
            int e4 = tid + 256;
            int j2 = e4 >> 4, d42 = (e4 & 15) * 4;
            *(float4*)&Vs[j2][d42] = vr1;
        }
        __syncthreads();

        // prefetch next V into registers (latency covered by p-write + MMA)
        if (i < NCH - 1) {
            int j = tid >> 4, d4 = (tid & 15) * 4;
            vr0 = *(const float4*)&g_v[vb + (size_t)(jc + 32 + j)*DKn + d4];
            int e4 = tid + 256;
            int j2 = e4 >> 4, d42 = (e4 & 15) * 4;
            vr1 = *(const float4*)&g_v[vb + (size_t)(jc + 32 + j2)*DKn + d42];
        }

        // p-write: normalized attn back to gmem (read staged u from smem)
        #pragma unroll
        for (int it = 0; it < 4; it++) {
            int e4 = tid + it*256;
            int q = e4 >> 3, j4 = (e4 & 7) * 4;
            const float* pr = Pc + q*36 + j4;
            float4 u4 = *(const float4*)pr;
            float ri = riS[q];
            *(float4*)(sc + scb + (size_t)q*Ln + jc + j4) =
                make_float4(u4.x*ri, u4.y*ri, u4.z*ri, u4.w*ri);
        }

        // MMA over chunk (raw u; cvt at fragment load)
        #pragma unroll
        for (int ks = 0; ks < 4; ks++) {
            int k = ks * 8;
            unsigned a[4];
            a[0] = f2tf(Pc[(qw + g)*36 + k + t]);
            a[1] = f2tf(Pc[(qw + 8 + g)*36 + k + t]);
            a[2] = f2tf(Pc[(qw + g)*36 + k + t + 4]);
            a[3] = f2tf(Pc[(qw + 8 + g)*36 + k + t + 4]);
            #pragma unroll
            for (int nt = 0; nt < 8; nt++) {
                unsigned b2[2];
                b2[0] = f2tf(Vs[k + t][nt*8 + g]);
                b2[1] = f2tf(Vs[k + t + 4][nt*8 + g]);
                mma_tf32(acc[nt], a, b2);
            }
        }
        __syncthreads();
    }

    // epilogue: scale by ri
    #pragma unroll
    for (int h2 = 0; h2 < 2; h2++) {
        int qr = qw + h2*8 + g;
        float ri = riS[qr];
        int q = q0 + qr;
        #pragma unroll
        for (int nt = 0; nt < 8; nt++) {
            int d = nt*8 + 2*t;
            *(float2*)&g_o[((size_t)bh*Ln + q)*DKn + d] =
                make_float2(acc[nt][h2*2+0]*ri, acc[nt][h2*2+1]*ri);
        }
    }
}

// ---------------------------------------------------------------------------
// Residual + LayerNorm (unchanged)
// ---------------------------------------------------------------------------
__global__ __launch_bounds__(256) void ln_kernel(const float* __restrict__ query,
                                                 const float* __restrict__ gamma,
                                                 const float* __restrict__ beta,
                                                 float* __restrict__ out) {
    const int row = blockIdx.x;          // b*L + l
    const int b = row >> 11, l = row & (Ln-1);
    const int tid = threadIdx.x;
    float vals[4];
    float s = 0.f, ss = 0.f;
    #pragma unroll
    for (int it = 0; it < 4; it++) {
        int d = tid + it*256;
        int h = d >> 6, dk = d & 63;
        float o = g_o[(((size_t)(b*Hn + h))*Ln + l)*DKn + dk];
        float r = o + query[(size_t)row*Dn + d];
        vals[it] = r;
        s += r; ss += r*r;
    }
    __shared__ float sm[8], sq[8], stat[2];
    #pragma unroll
    for (int off = 16; off; off >>= 1) {
        s  += __shfl_xor_sync(0xffffffffu, s, off);
        ss += __shfl_xor_sync(0xffffffffu, ss, off);
    }
    int warp = tid >> 5, lane = tid & 31;
    if (lane == 0) { sm[warp] = s; sq[warp] = ss; }
    __syncthreads();
    if (tid == 0) {
        float S = 0.f, SS = 0.f;
        #pragma unroll
        for (int w = 0; w < 8; w++) { S += sm[w]; SS += sq[w]; }
        float mu = S * (1.0f/Dn);
        float var = SS * (1.0f/Dn) - mu*mu;
        stat[0] = mu;
        stat[1] = rsqrtf(var + 1e-6f);
    }
    __syncthreads();
    float mu = stat[0], rstd = stat[1];
    #pragma unroll
    for (int it = 0; it < 4; it++) {
        int d = tid + it*256;
        out[(size_t)row*Dn + d] = (vals[it] - mu) * rstd * gamma[d] + beta[d];
    }
}

// ---------------------------------------------------------------------------
extern "C" void kernel_launch(void* const* d_in, const int* in_sizes, int n_in,
                              void* d_out, int out_size) {
    const float* key   = (const float*)d_in[0];
    const float* value = (const float*)d_in[1];
    const float* query = (const float*)d_in[2];
    const int*   mask  = (const int*)d_in[3];
    const float* Wk = (const float*)d_in[4];
    const float* Wv = (const float*)d_in[5];
    const float* Wq = (const float*)d_in[6];
    const float* lng = (const float*)d_in[7];
    const float* lnb = (const float*)d_in[8];

    float* normed = (float*)d_out;                       // [B, L, D]
    float* attn;
    if ((size_t)out_size > (size_t)Bn*Ln*Dn) {
        attn = normed + (size_t)Bn*Ln*Dn;                // [B*H, L, L]
    } else {
        cudaGetSymbolAddress((void**)&attn, g_sc);
    }

    dim3 gp(Dn/128, Mn/128, 3);     // (8, 32, 3) — fused K/V/Q projections
    proj_kernel<<<gp, 256>>>(key, value, query, Wk, Wv, Wq);

    dim3 gs(Ln/128, Ln/128, BHn);   // (16, 16, 32)
    scores_kernel<<<gs, 256>>>(mask, attn);

    rowsum_kernel<<<(BHn*Ln)/256, 256>>>();

    dim3 gv(Ln/128, BHn);        // (16, 32)
    pv_kernel<<<gv, 256>>>(attn);

    ln_kernel<<<Mn, 256>>>(query, lng, lnb, normed);
}

// round 10
// speedup vs baseline: 3.7483x; 1.0115x over previous
#include <cuda_runtime.h>
#include <cstdint>
#include <math.h>

#define Bn 2
#define Ln 2048
#define Dn 1024
#define Hn 16
#define DKn 64
#define BHn (Bn*Hn)      // 32
#define Mn (Bn*Ln)       // 4096

// Scratch (device globals — no allocation allowed)
__device__ float g_k[(size_t)BHn*Ln*DKn];
__device__ float g_v[(size_t)BHn*Ln*DKn];
__device__ float g_q[(size_t)BHn*Ln*DKn];
__device__ float g_o[(size_t)BHn*Ln*DKn];
__device__ float g_part[(size_t)BHn*Ln*32]; // per-(block,warp_n) partial row sums
__device__ float g_ri[(size_t)BHn*Ln];      // 1 / rowsum
// Fallback scores buffer in case the harness output holds only `normed`
__device__ float g_sc[(size_t)BHn*Ln*Ln];

// ---- tf32 mma helpers ----
__device__ __forceinline__ unsigned f2tf(float x) {
    unsigned r; asm("cvt.rna.tf32.f32 %0, %1;" : "=r"(r) : "f"(x));
    return r;
}
// D(16x8,f32) += A(16x8,tf32) * B(8x8,tf32)
__device__ __forceinline__ void mma_tf32(float* c, const unsigned* a, const unsigned* b) {
    asm volatile(
        "mma.sync.aligned.m16n8k8.row.col.f32.tf32.tf32.f32 "
        "{%0,%1,%2,%3}, {%4,%5,%6,%7}, {%8,%9}, {%0,%1,%2,%3};"
        : "+f"(c[0]), "+f"(c[1]), "+f"(c[2]), "+f"(c[3])
        : "r"(a[0]), "r"(a[1]), "r"(a[2]), "r"(a[3]),
          "r"(b[0]), "r"(b[1]));
}

// ---- cp.async helpers ----
__device__ __forceinline__ void cp16(void* smem_dst, const void* gmem_src) {
    unsigned dst = (unsigned)__cvta_generic_to_shared(smem_dst);
    asm volatile("cp.async.cg.shared.global [%0], [%1], 16;"
                 :: "r"(dst), "l"(gmem_src));
}
__device__ __forceinline__ void cp_commit() {
    asm volatile("cp.async.commit_group;");
}

// ---------------------------------------------------------------------------
// Fused projection GEMMs via tf32 mma, cp.async double-buffered.
// out[b,h,l,dk] = sum_d X[b,l,d]*W[d,n]; blockIdx.z selects {K,V,Q}.
// Dynamic smem: Xr[2][128][36] raw + Wr[2][32][136] raw.
// Each chunk stage = 1024 float4 slots = 4 cp16 per thread (256 threads).
// ---------------------------------------------------------------------------
#define PROJ_SMEM ((2*128*36 + 2*32*136) * 4)
__global__ __launch_bounds__(256, 2) void proj_kernel(const float* __restrict__ Xk,
                                                      const float* __restrict__ Xv,
                                                      const float* __restrict__ Xq,
                                                      const float* __restrict__ Wk,
                                                      const float* __restrict__ Wv,
                                                      const float* __restrict__ Wq) {
    const int which = blockIdx.z;
    const float* X = (which == 0) ? Xk : ((which == 1) ? Xv : Xq);
    const float* W = (which == 0) ? Wk : ((which == 1) ? Wv : Wq);
    float* out = (which == 0) ? g_k : ((which == 1) ? g_v : g_q);

    const int bm = blockIdx.y * 128;
    const int bn = blockIdx.x * 128;
    const int tid = threadIdx.x;
    const int w = tid >> 5, lane = tid & 31;
    const int g = lane >> 2, t = lane & 3;
    const int mw = (w >> 1) * 32;
    const int nw = (w & 1) * 64;

    extern __shared__ float smem[];
    float* Xr = smem;                 // [2][128][36]
    float* Wr = smem + 2*128*36;      // [2][32][136]

    // stage one k-chunk into buffer `buf`:
    //   X: 128 rows x 32 floats  (1024 float4 slots)
    //   W: 32 rows x 128 floats  (1024 float4 slots)
    #define PROJ_STAGE(buf, k0)                                                   \
        do {                                                                      \
            float* Xd = &Xr[(size_t)(buf)*128*36];                                \
            float* Wd = &Wr[(size_t)(buf)*32*136];                                \
            _Pragma("unroll")                                                     \
            for (int it = 0; it < 4; it++) {                                      \
                int e = tid + it*256;                                             \
                int r = e >> 3, c4 = (e & 7) * 4;                                 \
                cp16(&Xd[r*36 + c4], &X[(size_t)(bm + r)*Dn + (k0) + c4]);        \
            }                                                                     \
            _Pragma("unroll")                                                     \
            for (int it = 0; it < 4; it++) {                                      \
                int e = tid + it*256;                                             \
                int kr = e >> 5, n4 = (e & 31) * 4;                               \
                cp16(&Wd[kr*136 + n4], &W[(size_t)((k0) + kr)*Dn + bn + n4]);     \
            }                                                                     \
            cp_commit();                                                          \
        } while (0)

    // prologue: chunk 0
    PROJ_STAGE(0, 0);

    float acc[2][8][4];
    #pragma unroll
    for (int mt = 0; mt < 2; mt++)
        #pragma unroll
        for (int nt = 0; nt < 8; nt++)
            #pragma unroll
            for (int c = 0; c < 4; c++) acc[mt][nt][c] = 0.f;

    const int NCH = Dn / 32;   // 32
    for (int i = 0; i < NCH; i++) {
        if (i < NCH - 1) {
            PROJ_STAGE((i + 1) & 1, (i + 1) * 32);
            asm volatile("cp.async.wait_group 1;");
        } else {
            asm volatile("cp.async.wait_group 0;");
        }
        __syncthreads();

        const float* Xc = &Xr[(size_t)(i & 1)*128*36];
        const float* Wc = &Wr[(size_t)(i & 1)*32*136];
        #pragma unroll
        for (int ks = 0; ks < 4; ks++) {
            int k = ks * 8;
            unsigned a[2][4];
            #pragma unroll
            for (int mt = 0; mt < 2; mt++) {
                int r = mw + mt*16 + g;
                a[mt][0] = f2tf(Xc[r*36 + k + t]);
                a[mt][1] = f2tf(Xc[(r+8)*36 + k + t]);
                a[mt][2] = f2tf(Xc[r*36 + k + t + 4]);
                a[mt][3] = f2tf(Xc[(r+8)*36 + k + t + 4]);
            }
            #pragma unroll
            for (int nt = 0; nt < 8; nt++) {
                int n = nw + nt*8 + g;
                unsigned b2[2];
                b2[0] = f2tf(Wc[(k+t)*136 + n]);
                b2[1] = f2tf(Wc[(k+t+4)*136 + n]);
                mma_tf32(acc[0][nt], a[0], b2);
                mma_tf32(acc[1][nt], a[1], b2);
            }
        }
        __syncthreads();
    }

    #pragma unroll
    for (int mt = 0; mt < 2; mt++) {
        #pragma unroll
        for (int h2 = 0; h2 < 2; h2++) {
            int m = bm + mw + mt*16 + h2*8 + g;
            int bb = m >> 11, l = m & (Ln-1);
            #pragma unroll
            for (int nt = 0; nt < 8; nt++) {
                int n = bn + nw + nt*8 + 2*t;
                int h = n >> 6, dk = n & 63;
                *(float2*)&out[(((size_t)(bb*Hn + h))*Ln + l)*DKn + dk] =
                    make_float2(acc[mt][nt][h2*2+0], acc[mt][nt][h2*2+1]);
            }
        }
    }
    #undef PROJ_STAGE
}

// ---------------------------------------------------------------------------
// Scores via tf32 mma, one-shot cp.async staging of full Q/K tiles (DK=64).
// u[bh,q,j] = exp((q.k)/8) or 0 if masked.
// Dynamic smem: Qr[128][68] + Kr[128][68] raw floats.
// ---------------------------------------------------------------------------
#define SCORES_SMEM (2*128*68*4)
__global__ __launch_bounds__(256, 2) void scores_kernel(const int* __restrict__ mask,
                                                        float* __restrict__ sc) {
    const int bh = blockIdx.z;
    const int q0 = blockIdx.y * 128;
    const int j0 = blockIdx.x * 128;
    const int b = bh >> 4;
    const int tid = threadIdx.x;
    const int w = tid >> 5, lane = tid & 31;
    const int g = lane >> 2, t = lane & 3;
    const int qw = (w >> 1) * 32;
    const int jw = (w & 1) * 64;

    extern __shared__ float smem[];
    float* Qr = smem;               // [128][68]
    float* Kr = smem + 128*68;      // [128][68]

    // stage all of Q,K: 128 rows x 16 float4 each = 2048 slots = 8/thread
    #pragma unroll
    for (int it = 0; it < 8; it++) {
        int e = tid + it*256;          // [0,2048)
        int r = e >> 4, c4 = (e & 15) * 4;
        cp16(&Qr[r*68 + c4], &g_q[((size_t)bh*Ln + q0 + r)*DKn + c4]);
    }
    #pragma unroll
    for (int it = 0; it < 8; it++) {
        int e = tid + it*256;
        int r = e >> 4, c4 = (e & 15) * 4;
        cp16(&Kr[r*68 + c4], &g_k[((size_t)bh*Ln + j0 + r)*DKn + c4]);
    }
    cp_commit();
    asm volatile("cp.async.wait_group 0;");
    __syncthreads();

    float acc[2][8][4];
    #pragma unroll
    for (int mt = 0; mt < 2; mt++)
        #pragma unroll
        for (int nt = 0; nt < 8; nt++)
            #pragma unroll
            for (int c = 0; c < 4; c++) acc[mt][nt][c] = 0.f;

    #pragma unroll
    for (int ks = 0; ks < 8; ks++) {
        int k = ks * 8;
        unsigned a[2][4];
        #pragma unroll
        for (int mt = 0; mt < 2; mt++) {
            int r = qw + mt*16 + g;
            a[mt][0] = f2tf(Qr[r*68 + k + t]);
            a[mt][1] = f2tf(Qr[(r+8)*68 + k + t]);
            a[mt][2] = f2tf(Qr[r*68 + k + t + 4]);
            a[mt][3] = f2tf(Qr[(r+8)*68 + k + t + 4]);
        }
        #pragma unroll
        for (int nt = 0; nt < 8; nt++) {
            int r = jw + nt*8 + g;
            unsigned b2[2];
            b2[0] = f2tf(Kr[r*68 + k + t]);
            b2[1] = f2tf(Kr[r*68 + k + t + 4]);
            mma_tf32(acc[0][nt], a[0], b2);
            mma_tf32(acc[1][nt], a[1], b2);
        }
    }

    // epilogue: mask, exp, store u, per-row partial sums
    #pragma unroll
    for (int mt = 0; mt < 2; mt++) {
        #pragma unroll
        for (int h2 = 0; h2 < 2; h2++) {
            int q = q0 + qw + mt*16 + h2*8 + g;
            float s = 0.f;
            #pragma unroll
            for (int nt = 0; nt < 8; nt++) {
                int j = j0 + jw + nt*8 + 2*t;
                int2 mv = *(const int2*)(mask + ((size_t)b*Ln + q)*Ln + j);
                float c0 = acc[mt][nt][h2*2+0];
                float c1 = acc[mt][nt][h2*2+1];
                float u0 = mv.x ? 0.f : __expf(c0*0.125f);
                float u1 = mv.y ? 0.f : __expf(c1*0.125f);
                s += u0 + u1;
                *(float2*)(sc + ((size_t)bh*Ln + q)*Ln + j) = make_float2(u0, u1);
            }
            s += __shfl_xor_sync(0xffffffffu, s, 1);
            s += __shfl_xor_sync(0xffffffffu, s, 2);
            if (t == 0)
                g_part[((size_t)bh*Ln + q)*32 + blockIdx.x*2 + (w & 1)] = s;
        }
    }
}

// ---------------------------------------------------------------------------
// Row-sum reduction: ri[bh,q] = 1 / sum of 32 partials
// ---------------------------------------------------------------------------
__global__ __launch_bounds__(256) void rowsum_kernel() {
    int row = blockIdx.x * 256 + threadIdx.x;   // bh*Ln + q
    float s = 0.f;
    #pragma unroll
    for (int jb = 0; jb < 32; jb++) s += g_part[(size_t)row*32 + jb];
    g_ri[row] = 1.0f / s;
}

// ---------------------------------------------------------------------------
// PV via tf32 mma, cp.async double-buffered (unchanged — round-8 validated).
// ---------------------------------------------------------------------------
__global__ __launch_bounds__(256, 2) void pv_kernel(float* __restrict__ sc) {
    const int bh = blockIdx.y;
    const int q0 = blockIdx.x * 128;
    const int tid = threadIdx.x;
    const int w = tid >> 5, lane = tid & 31;
    const int g = lane >> 2, t = lane & 3;
    const int qw = w * 16;

    __shared__ float Ps[2][128][36];
    __shared__ float Vs[32][72];
    __shared__ float riS[128];

    if (tid < 128) riS[tid] = g_ri[(size_t)bh*Ln + q0 + tid];

    const size_t scb = ((size_t)bh*Ln + q0)*Ln;
    const size_t vb  = (size_t)bh*Ln*DKn;

    float acc[8][4];
    #pragma unroll
    for (int nt = 0; nt < 8; nt++)
        #pragma unroll
        for (int c = 0; c < 4; c++) acc[nt][c] = 0.f;

    #pragma unroll
    for (int it = 0; it < 4; it++) {
        int e4 = tid + it*256;
        int q = e4 >> 3, j4 = (e4 & 7) * 4;
        cp16(&Ps[0][q][j4], sc + scb + (size_t)q*Ln + j4);
    }
    cp_commit();
    float4 vr0, vr1;
    {
        int j = tid >> 4, d4 = (tid & 15) * 4;
        vr0 = *(const float4*)&g_v[vb + (size_t)j*DKn + d4];
        int e4 = tid + 256;
        int j2 = e4 >> 4, d42 = (e4 & 15) * 4;
        vr1 = *(const float4*)&g_v[vb + (size_t)j2*DKn + d42];
    }

    const int NCH = Ln / 32;   // 64
    for (int i = 0; i < NCH; i++) {
        const int jc = i * 32;
        float* Pc = &Ps[i & 1][0][0];

        if (i < NCH - 1) {
            #pragma unroll
            for (int it = 0; it < 4; it++) {
                int e4 = tid + it*256;
                int q = e4 >> 3, j4 = (e4 & 7) * 4;
                cp16(&Ps[(i+1) & 1][q][j4], sc + scb + (size_t)q*Ln + jc + 32 + j4);
            }
            cp_commit();
            asm volatile("cp.async.wait_group 1;");
        } else {
            asm volatile("cp.async.wait_group 0;");
        }

        {
            int j = tid >> 4, d4 = (tid & 15) * 4;
            *(float4*)&Vs[j][d4] = vr0;
            int e4 = tid + 256;
            int j2 = e4 >> 4, d42 = (e4 & 15) * 4;
            *(float4*)&Vs[j2][d42] = vr1;
        }
        __syncthreads();

        if (i < NCH - 1) {
            int j = tid >> 4, d4 = (tid & 15) * 4;
            vr0 = *(const float4*)&g_v[vb + (size_t)(jc + 32 + j)*DKn + d4];
            int e4 = tid + 256;
            int j2 = e4 >> 4, d42 = (e4 & 15) * 4;
            vr1 = *(const float4*)&g_v[vb + (size_t)(jc + 32 + j2)*DKn + d42];
        }

        #pragma unroll
        for (int it = 0; it < 4; it++) {
            int e4 = tid + it*256;
            int q = e4 >> 3, j4 = (e4 & 7) * 4;
            const float* pr = Pc + q*36 + j4;
            float4 u4 = *(const float4*)pr;
            float ri = riS[q];
            *(float4*)(sc + scb + (size_t)q*Ln + jc + j4) =
                make_float4(u4.x*ri, u4.y*ri, u4.z*ri, u4.w*ri);
        }

        #pragma unroll
        for (int ks = 0; ks < 4; ks++) {
            int k = ks * 8;
            unsigned a[4];
            a[0] = f2tf(Pc[(qw + g)*36 + k + t]);
            a[1] = f2tf(Pc[(qw + 8 + g)*36 + k + t]);
            a[2] = f2tf(Pc[(qw + g)*36 + k + t + 4]);
            a[3] = f2tf(Pc[(qw + 8 + g)*36 + k + t + 4]);
            #pragma unroll
            for (int nt = 0; nt < 8; nt++) {
                unsigned b2[2];
                b2[0] = f2tf(Vs[k + t][nt*8 + g]);
                b2[1] = f2tf(Vs[k + t + 4][nt*8 + g]);
                mma_tf32(acc[nt], a, b2);
            }
        }
        __syncthreads();
    }

    #pragma unroll
    for (int h2 = 0; h2 < 2; h2++) {
        int qr = qw + h2*8 + g;
        float ri = riS[qr];
        int q = q0 + qr;
        #pragma unroll
        for (int nt = 0; nt < 8; nt++) {
            int d = nt*8 + 2*t;
            *(float2*)&g_o[((size_t)bh*Ln + q)*DKn + d] =
                make_float2(acc[nt][h2*2+0]*ri, acc[nt][h2*2+1]*ri);
        }
    }
}

// ---------------------------------------------------------------------------
// Residual + LayerNorm (unchanged)
// ---------------------------------------------------------------------------
__global__ __launch_bounds__(256) void ln_kernel(const float* __restrict__ query,
                                                 const float* __restrict__ gamma,
                                                 const float* __restrict__ beta,
                                                 float* __restrict__ out) {
    const int row = blockIdx.x;          // b*L + l
    const int b = row >> 11, l = row & (Ln-1);
    const int tid = threadIdx.x;
    float vals[4];
    float s = 0.f, ss = 0.f;
    #pragma unroll
    for (int it = 0; it < 4; it++) {
        int d = tid + it*256;
        int h = d >> 6, dk = d & 63;
        float o = g_o[(((size_t)(b*Hn + h))*Ln + l)*DKn + dk];
        float r = o + query[(size_t)row*Dn + d];
        vals[it] = r;
        s += r; ss += r*r;
    }
    __shared__ float sm[8], sq[8], stat[2];
    #pragma unroll
    for (int off = 16; off; off >>= 1) {
        s  += __shfl_xor_sync(0xffffffffu, s, off);
        ss += __shfl_xor_sync(0xffffffffu, ss, off);
    }
    int warp = tid >> 5, lane = tid & 31;
    if (lane == 0) { sm[warp] = s; sq[warp] = ss; }
    __syncthreads();
    if (tid == 0) {
        float S = 0.f, SS = 0.f;
        #pragma unroll
        for (int w = 0; w < 8; w++) { S += sm[w]; SS += sq[w]; }
        float mu = S * (1.0f/Dn);
        float var = SS * (1.0f/Dn) - mu*mu;
        stat[0] = mu;
        stat[1] = rsqrtf(var + 1e-6f);
    }
    __syncthreads();
    float mu = stat[0], rstd = stat[1];
    #pragma unroll
    for (int it = 0; it < 4; it++) {
        int d = tid + it*256;
        out[(size_t)row*Dn + d] = (vals[it] - mu) * rstd * gamma[d] + beta[d];
    }
}

// ---------------------------------------------------------------------------
extern "C" void kernel_launch(void* const* d_in, const int* in_sizes, int n_in,
                              void* d_out, int out_size) {
    const float* key   = (const float*)d_in[0];
    const float* value = (const float*)d_in[1];
    const float* query = (const float*)d_in[2];
    const int*   mask  = (const int*)d_in[3];
    const float* Wk = (const float*)d_in[4];
    const float* Wv = (const float*)d_in[5];
    const float* Wq = (const float*)d_in[6];
    const float* lng = (const float*)d_in[7];
    const float* lnb = (const float*)d_in[8];

    float* normed = (float*)d_out;                       // [B, L, D]
    float* attn;
    if ((size_t)out_size > (size_t)Bn*Ln*Dn) {
        attn = normed + (size_t)Bn*Ln*Dn;                // [B*H, L, L]
    } else {
        cudaGetSymbolAddress((void**)&attn, g_sc);
    }

    // raise dynamic smem limits (idempotent; host-side, graph-safe)
    cudaFuncSetAttribute(proj_kernel,
                         cudaFuncAttributeMaxDynamicSharedMemorySize, PROJ_SMEM);
    cudaFuncSetAttribute(scores_kernel,
                         cudaFuncAttributeMaxDynamicSharedMemorySize, SCORES_SMEM);

    dim3 gp(Dn/128, Mn/128, 3);     // (8, 32, 3) — fused K/V/Q projections
    proj_kernel<<<gp, 256, PROJ_SMEM>>>(key, value, query, Wk, Wv, Wq);

    dim3 gs(Ln/128, Ln/128, BHn);   // (16, 16, 32)
    scores_kernel<<<gs, 256, SCORES_SMEM>>>(mask, attn);

    rowsum_kernel<<<(BHn*Ln)/256, 256>>>();

    dim3 gv(Ln/128, BHn);        // (16, 32)
    pv_kernel<<<gv, 256>>>(attn);

    ln_kernel<<<Mn, 256>>>(query, lng, lnb, normed);
}

// round 12
// speedup vs baseline: 3.7534x; 1.0014x over previous
#include <cuda_runtime.h>
#include <cuda_fp16.h>
#include <cstdint>
#include <math.h>

#define Bn 2
#define Ln 2048
#define Dn 1024
#define Hn 16
#define DKn 64
#define BHn (Bn*Hn)      // 32
#define Mn (Bn*Ln)       // 4096

// Scratch (device globals — no allocation allowed)
__device__ float g_k[(size_t)BHn*Ln*DKn];
__device__ float g_v[(size_t)BHn*Ln*DKn];
__device__ float g_q[(size_t)BHn*Ln*DKn];
__device__ float g_o[(size_t)BHn*Ln*DKn];
__device__ float g_part[(size_t)BHn*Ln*32]; // per-(block,warp_n) partial row sums
__device__ float g_ri[(size_t)BHn*Ln];      // 1 / rowsum
__device__ __half g_ub[(size_t)BHn*Ln*Ln];  // unnormalized u, fp16
// Fallback scores buffer in case the harness output holds only `normed`
__device__ float g_sc[(size_t)BHn*Ln*Ln];

// ---- tf32 mma helpers ----
__device__ __forceinline__ unsigned f2tf(float x) {
    unsigned r; asm("cvt.rna.tf32.f32 %0, %1;" : "=r"(r) : "f"(x));
    return r;
}
// D(16x8,f32) += A(16x8,tf32) * B(8x8,tf32)
__device__ __forceinline__ void mma_tf32(float* c, const unsigned* a, const unsigned* b) {
    asm volatile(
        "mma.sync.aligned.m16n8k8.row.col.f32.tf32.tf32.f32 "
        "{%0,%1,%2,%3}, {%4,%5,%6,%7}, {%8,%9}, {%0,%1,%2,%3};"
        : "+f"(c[0]), "+f"(c[1]), "+f"(c[2]), "+f"(c[3])
        : "r"(a[0]), "r"(a[1]), "r"(a[2]), "r"(a[3]),
          "r"(b[0]), "r"(b[1]));
}

// ---- cp.async helpers ----
__device__ __forceinline__ void cp16(void* smem_dst, const void* gmem_src) {
    unsigned dst = (unsigned)__cvta_generic_to_shared(smem_dst);
    asm volatile("cp.async.cg.shared.global [%0], [%1], 16;"
                 :: "r"(dst), "l"(gmem_src));
}
__device__ __forceinline__ void cp_commit() {
    asm volatile("cp.async.commit_group;");
}

// ---------------------------------------------------------------------------
// Fused projection GEMMs via tf32 mma, cp.async double-buffered (unchanged).
// ---------------------------------------------------------------------------
#define PROJ_SMEM ((2*128*36 + 2*32*136) * 4)
__global__ __launch_bounds__(256, 2) void proj_kernel(const float* __restrict__ Xk,
                                                      const float* __restrict__ Xv,
                                                      const float* __restrict__ Xq,
                                                      const float* __restrict__ Wk,
                                                      const float* __restrict__ Wv,
                                                      const float* __restrict__ Wq) {
    const int which = blockIdx.z;
    const float* X = (which == 0) ? Xk : ((which == 1) ? Xv : Xq);
    const float* W = (which == 0) ? Wk : ((which == 1) ? Wv : Wq);
    float* out = (which == 0) ? g_k : ((which == 1) ? g_v : g_q);

    const int bm = blockIdx.y * 128;
    const int bn = blockIdx.x * 128;
    const int tid = threadIdx.x;
    const int w = tid >> 5, lane = tid & 31;
    const int g = lane >> 2, t = lane & 3;
    const int mw = (w >> 1) * 32;
    const int nw = (w & 1) * 64;

    extern __shared__ float smem[];
    float* Xr = smem;                 // [2][128][36]
    float* Wr = smem + 2*128*36;      // [2][32][136]

    #define PROJ_STAGE(buf, k0)                                                   \
        do {                                                                      \
            float* Xd = &Xr[(size_t)(buf)*128*36];                                \
            float* Wd = &Wr[(size_t)(buf)*32*136];                                \
            _Pragma("unroll")                                                     \
            for (int it = 0; it < 4; it++) {                                      \
                int e = tid + it*256;                                             \
                int r = e >> 3, c4 = (e & 7) * 4;                                 \
                cp16(&Xd[r*36 + c4], &X[(size_t)(bm + r)*Dn + (k0) + c4]);        \
            }                                                                     \
            _Pragma("unroll")                                                     \
            for (int it = 0; it < 4; it++) {                                      \
                int e = tid + it*256;                                             \
                int kr = e >> 5, n4 = (e & 31) * 4;                               \
                cp16(&Wd[kr*136 + n4], &W[(size_t)((k0) + kr)*Dn + bn + n4]);     \
            }                                                                     \
            cp_commit();                                                          \
        } while (0)

    PROJ_STAGE(0, 0);

    float acc[2][8][4];
    #pragma unroll
    for (int mt = 0; mt < 2; mt++)
        #pragma unroll
        for (int nt = 0; nt < 8; nt++)
            #pragma unroll
            for (int c = 0; c < 4; c++) acc[mt][nt][c] = 0.f;

    const int NCH = Dn / 32;   // 32
    for (int i = 0; i < NCH; i++) {
        if (i < NCH - 1) {
            PROJ_STAGE((i + 1) & 1, (i + 1) * 32);
            asm volatile("cp.async.wait_group 1;");
        } else {
            asm volatile("cp.async.wait_group 0;");
        }
        __syncthreads();

        const float* Xc = &Xr[(size_t)(i & 1)*128*36];
        const float* Wc = &Wr[(size_t)(i & 1)*32*136];
        #pragma unroll
        for (int ks = 0; ks < 4; ks++) {
            int k = ks * 8;
            unsigned a[2][4];
            #pragma unroll
            for (int mt = 0; mt < 2; mt++) {
                int r = mw + mt*16 + g;
                a[mt][0] = f2tf(Xc[r*36 + k + t]);
                a[mt][1] = f2tf(Xc[(r+8)*36 + k + t]);
                a[mt][2] = f2tf(Xc[r*36 + k + t + 4]);
                a[mt][3] = f2tf(Xc[(r+8)*36 + k + t + 4]);
            }
            #pragma unroll
            for (int nt = 0; nt < 8; nt++) {
                int n = nw + nt*8 + g;
                unsigned b2[2];
                b2[0] = f2tf(Wc[(k+t)*136 + n]);
                b2[1] = f2tf(Wc[(k+t+4)*136 + n]);
                mma_tf32(acc[0][nt], a[0], b2);
                mma_tf32(acc[1][nt], a[1], b2);
            }
        }
        __syncthreads();
    }

    #pragma unroll
    for (int mt = 0; mt < 2; mt++) {
        #pragma unroll
        for (int h2 = 0; h2 < 2; h2++) {
            int m = bm + mw + mt*16 + h2*8 + g;
            int bb = m >> 11, l = m & (Ln-1);
            #pragma unroll
            for (int nt = 0; nt < 8; nt++) {
                int n = bn + nw + nt*8 + 2*t;
                int h = n >> 6, dk = n & 63;
                *(float2*)&out[(((size_t)(bb*Hn + h))*Ln + l)*DKn + dk] =
                    make_float2(acc[mt][nt][h2*2+0], acc[mt][nt][h2*2+1]);
            }
        }
    }
    #undef PROJ_STAGE
}

// ---------------------------------------------------------------------------
// Scores via tf32 mma: u = exp((q.k)/8) or 0; u written as fp16 to g_ub.
// Mask prefetched into a 64-bit register bitmap during cp.async staging.
// ---------------------------------------------------------------------------
#define SCORES_SMEM (2*128*68*4)
__global__ __launch_bounds__(256, 2) void scores_kernel(const int* __restrict__ mask) {
    const int bh = blockIdx.z;
    const int q0 = blockIdx.y * 128;
    const int j0 = blockIdx.x * 128;
    const int b = bh >> 4;
    const int tid = threadIdx.x;
    const int w = tid >> 5, lane = tid & 31;
    const int g = lane >> 2, t = lane & 3;
    const int qw = (w >> 1) * 32;
    const int jw = (w & 1) * 64;

    extern __shared__ float smem[];
    float* Qr = smem;               // [128][68]
    float* Kr = smem + 128*68;      // [128][68]

    // stage all of Q,K (cp.async, in flight while we prefetch mask)
    #pragma unroll
    for (int it = 0; it < 8; it++) {
        int e = tid + it*256;
        int r = e >> 4, c4 = (e & 15) * 4;
        cp16(&Qr[r*68 + c4], &g_q[((size_t)bh*Ln + q0 + r)*DKn + c4]);
    }
    #pragma unroll
    for (int it = 0; it < 8; it++) {
        int e = tid + it*256;
        int r = e >> 4, c4 = (e & 15) * 4;
        cp16(&Kr[r*68 + c4], &g_k[((size_t)bh*Ln + j0 + r)*DKn + c4]);
    }
    cp_commit();

    // mask prefetch + bit-compress: 64 bools -> 1 u64 (overlaps staging)
    unsigned long long mbits = 0ull;
    #pragma unroll
    for (int mt = 0; mt < 2; mt++) {
        #pragma unroll
        for (int h2 = 0; h2 < 2; h2++) {
            int q = q0 + qw + mt*16 + h2*8 + g;
            int2 mv[8];
            #pragma unroll
            for (int nt = 0; nt < 8; nt++) {
                int j = j0 + jw + nt*8 + 2*t;
                mv[nt] = *(const int2*)(mask + ((size_t)b*Ln + q)*Ln + j);
            }
            #pragma unroll
            for (int nt = 0; nt < 8; nt++) {
                int bit = ((mt*2 + h2)*8 + nt)*2;
                if (mv[nt].x) mbits |= 1ull << bit;
                if (mv[nt].y) mbits |= 2ull << bit;
            }
        }
    }

    asm volatile("cp.async.wait_group 0;");
    __syncthreads();

    float acc[2][8][4];
    #pragma unroll
    for (int mt = 0; mt < 2; mt++)
        #pragma unroll
        for (int nt = 0; nt < 8; nt++)
            #pragma unroll
            for (int c = 0; c < 4; c++) acc[mt][nt][c] = 0.f;

    #pragma unroll
    for (int ks = 0; ks < 8; ks++) {
        int k = ks * 8;
        unsigned a[2][4];
        #pragma unroll
        for (int mt = 0; mt < 2; mt++) {
            int r = qw + mt*16 + g;
            a[mt][0] = f2tf(Qr[r*68 + k + t]);
            a[mt][1] = f2tf(Qr[(r+8)*68 + k + t]);
            a[mt][2] = f2tf(Qr[r*68 + k + t + 4]);
            a[mt][3] = f2tf(Qr[(r+8)*68 + k + t + 4]);
        }
        #pragma unroll
        for (int nt = 0; nt < 8; nt++) {
            int r = jw + nt*8 + g;
            unsigned b2[2];
            b2[0] = f2tf(Kr[r*68 + k + t]);
            b2[1] = f2tf(Kr[r*68 + k + t + 4]);
            mma_tf32(acc[0][nt], a[0], b2);
            mma_tf32(acc[1][nt], a[1], b2);
        }
    }

    // epilogue: exp (masked via bitmap), fp16-pack u, per-row partial sums
    #pragma unroll
    for (int mt = 0; mt < 2; mt++) {
        #pragma unroll
        for (int h2 = 0; h2 < 2; h2++) {
            int q = q0 + qw + mt*16 + h2*8 + g;
            float s = 0.f;
            #pragma unroll
            for (int nt = 0; nt < 8; nt++) {
                int j = j0 + jw + nt*8 + 2*t;
                int bit = ((mt*2 + h2)*8 + nt)*2;
                float c0 = acc[mt][nt][h2*2+0];
                float c1 = acc[mt][nt][h2*2+1];
                float u0 = ((mbits >> bit) & 1ull) ? 0.f : __expf(c0*0.125f);
                float u1 = ((mbits >> bit) & 2ull) ? 0.f : __expf(c1*0.125f);
                s += u0 + u1;
                __half2 hu = __floats2half2_rn(u0, u1);
                *(__half2*)(g_ub + ((size_t)bh*Ln + q)*Ln + j) = hu;
            }
            s += __shfl_xor_sync(0xffffffffu, s, 1);
            s += __shfl_xor_sync(0xffffffffu, s, 2);
            if (t == 0)
                g_part[((size_t)bh*Ln + q)*32 + blockIdx.x*2 + (w & 1)] = s;
        }
    }
}

// ---------------------------------------------------------------------------
// Row-sum reduction: ri[bh,q] = 1 / sum of 32 partials
// ---------------------------------------------------------------------------
__global__ __launch_bounds__(256) void rowsum_kernel() {
    int row = blockIdx.x * 256 + threadIdx.x;   // bh*Ln + q
    float s = 0.f;
    #pragma unroll
    for (int jb = 0; jb < 32; jb++) s += g_part[(size_t)row*32 + jb];
    g_ri[row] = 1.0f / s;
}

// ---------------------------------------------------------------------------
// PV via tf32 mma, cp.async double-buffered; reads fp16 u from g_ub,
// writes fp32 p = u*ri to attn (final output), o = (sum u*V)*ri.
// ---------------------------------------------------------------------------
__global__ __launch_bounds__(256, 2) void pv_kernel(float* __restrict__ attn) {
    const int bh = blockIdx.y;
    const int q0 = blockIdx.x * 128;
    const int tid = threadIdx.x;
    const int w = tid >> 5, lane = tid & 31;
    const int g = lane >> 2, t = lane & 3;
    const int qw = w * 16;

    __shared__ __half Ps[2][128][40];   // raw u, fp16, double-buffered
    __shared__ float Vs[32][72];
    __shared__ float riS[128];

    if (tid < 128) riS[tid] = g_ri[(size_t)bh*Ln + q0 + tid];

    const size_t scb = ((size_t)bh*Ln + q0)*Ln;   // element base for u / attn
    const size_t vb  = (size_t)bh*Ln*DKn;

    float acc[8][4];
    #pragma unroll
    for (int nt = 0; nt < 8; nt++)
        #pragma unroll
        for (int c = 0; c < 4; c++) acc[nt][c] = 0.f;

    // prologue: chunk 0 u (fp16, 512 cp16 = 2/thread); chunk 0 V into regs
    #pragma unroll
    for (int it = 0; it < 2; it++) {
        int e = tid + it*256;            // [0,512)
        int q = e >> 2, c8 = (e & 3) * 8;
        cp16(&Ps[0][q][c8], g_ub + scb + (size_t)q*Ln + c8);
    }
    cp_commit();
    float4 vr0, vr1;
    {
        int j = tid >> 4, d4 = (tid & 15) * 4;
        vr0 = *(const float4*)&g_v[vb + (size_t)j*DKn + d4];
        int e4 = tid + 256;
        int j2 = e4 >> 4, d42 = (e4 & 15) * 4;
        vr1 = *(const float4*)&g_v[vb + (size_t)j2*DKn + d42];
    }

    const int NCH = Ln / 32;   // 64
    for (int i = 0; i < NCH; i++) {
        const int jc = i * 32;
        const __half* Pc = &Ps[i & 1][0][0];

        if (i < NCH - 1) {
            #pragma unroll
            for (int it = 0; it < 2; it++) {
                int e = tid + it*256;
                int q = e >> 2, c8 = (e & 3) * 8;
                cp16(&Ps[(i+1) & 1][q][c8], g_ub + scb + (size_t)q*Ln + jc + 32 + c8);
            }
            cp_commit();
            asm volatile("cp.async.wait_group 1;");
        } else {
            asm volatile("cp.async.wait_group 0;");
        }

        {
            int j = tid >> 4, d4 = (tid & 15) * 4;
            *(float4*)&Vs[j][d4] = vr0;
            int e4 = tid + 256;
            int j2 = e4 >> 4, d42 = (e4 & 15) * 4;
            *(float4*)&Vs[j2][d42] = vr1;
        }
        __syncthreads();

        if (i < NCH - 1) {
            int j = tid >> 4, d4 = (tid & 15) * 4;
            vr0 = *(const float4*)&g_v[vb + (size_t)(jc + 32 + j)*DKn + d4];
            int e4 = tid + 256;
            int j2 = e4 >> 4, d42 = (e4 & 15) * 4;
            vr1 = *(const float4*)&g_v[vb + (size_t)(jc + 32 + j2)*DKn + d42];
        }

        // p-write: expand fp16 u, scale by ri, store fp32 to attn
        #pragma unroll
        for (int it = 0; it < 2; it++) {
            int e = tid + it*256;          // [0,512): 8 halves per slot
            int q = e >> 2, j8 = (e & 3) * 8;
            uint4 pw = *(const uint4*)(Pc + q*40 + j8);
            float ri = riS[q];
            float2 f0 = __half22float2(*(__half2*)&pw.x);
            float2 f1 = __half22float2(*(__half2*)&pw.y);
            float2 f2 = __half22float2(*(__half2*)&pw.z);
            float2 f3 = __half22float2(*(__half2*)&pw.w);
            size_t gi = scb + (size_t)q*Ln + jc + j8;
            *(float4*)(attn + gi) =
                make_float4(f0.x*ri, f0.y*ri, f1.x*ri, f1.y*ri);
            *(float4*)(attn + gi + 4) =
                make_float4(f2.x*ri, f2.y*ri, f3.x*ri, f3.y*ri);
        }

        // MMA over chunk (fp16 u; expand to tf32 at fragment load)
        #pragma unroll
        for (int ks = 0; ks < 4; ks++) {
            int k = ks * 8;
            unsigned a[4];
            a[0] = f2tf(__half2float(Pc[(qw + g)*40 + k + t]));
            a[1] = f2tf(__half2float(Pc[(qw + 8 + g)*40 + k + t]));
            a[2] = f2tf(__half2float(Pc[(qw + g)*40 + k + t + 4]));
            a[3] = f2tf(__half2float(Pc[(qw + 8 + g)*40 + k + t + 4]));
            #pragma unroll
            for (int nt = 0; nt < 8; nt++) {
                unsigned b2[2];
                b2[0] = f2tf(Vs[k + t][nt*8 + g]);
                b2[1] = f2tf(Vs[k + t + 4][nt*8 + g]);
                mma_tf32(acc[nt], a, b2);
            }
        }
        __syncthreads();
    }

    #pragma unroll
    for (int h2 = 0; h2 < 2; h2++) {
        int qr = qw + h2*8 + g;
        float ri = riS[qr];
        int q = q0 + qr;
        #pragma unroll
        for (int nt = 0; nt < 8; nt++) {
            int d = nt*8 + 2*t;
            *(float2*)&g_o[((size_t)bh*Ln + q)*DKn + d] =
                make_float2(acc[nt][h2*2+0]*ri, acc[nt][h2*2+1]*ri);
        }
    }
}

// ---------------------------------------------------------------------------
// Residual + LayerNorm (unchanged)
// ---------------------------------------------------------------------------
__global__ __launch_bounds__(256) void ln_kernel(const float* __restrict__ query,
                                                 const float* __restrict__ gamma,
                                                 const float* __restrict__ beta,
                                                 float* __restrict__ out) {
    const int row = blockIdx.x;          // b*L + l
    const int b = row >> 11, l = row & (Ln-1);
    const int tid = threadIdx.x;
    float vals[4];
    float s = 0.f, ss = 0.f;
    #pragma unroll
    for (int it = 0; it < 4; it++) {
        int d = tid + it*256;
        int h = d >> 6, dk = d & 63;
        float o = g_o[(((size_t)(b*Hn + h))*Ln + l)*DKn + dk];
        float r = o + query[(size_t)row*Dn + d];
        vals[it] = r;
        s += r; ss += r*r;
    }
    __shared__ float sm[8], sq[8], stat[2];
    #pragma unroll
    for (int off = 16; off; off >>= 1) {
        s  += __shfl_xor_sync(0xffffffffu, s, off);
        ss += __shfl_xor_sync(0xffffffffu, ss, off);
    }
    int warp = tid >> 5, lane = tid & 31;
    if (lane == 0) { sm[warp] = s; sq[warp] = ss; }
    __syncthreads();
    if (tid == 0) {
        float S = 0.f, SS = 0.f;
        #pragma unroll
        for (int w = 0; w < 8; w++) { S += sm[w]; SS += sq[w]; }
        float mu = S * (1.0f/Dn);
        float var = SS * (1.0f/Dn) - mu*mu;
        stat[0] = mu;
        stat[1] = rsqrtf(var + 1e-6f);
    }
    __syncthreads();
    float mu = stat[0], rstd = stat[1];
    #pragma unroll
    for (int it = 0; it < 4; it++) {
        int d = tid + it*256;
        out[(size_t)row*Dn + d] = (vals[it] - mu) * rstd * gamma[d] + beta[d];
    }
}

// ---------------------------------------------------------------------------
extern "C" void kernel_launch(void* const* d_in, const int* in_sizes, int n_in,
                              void* d_out, int out_size) {
    const float* key   = (const float*)d_in[0];
    const float* value = (const float*)d_in[1];
    const float* query = (const float*)d_in[2];
    const int*   mask  = (const int*)d_in[3];
    const float* Wk = (const float*)d_in[4];
    const float* Wv = (const float*)d_in[5];
    const float* Wq = (const float*)d_in[6];
    const float* lng = (const float*)d_in[7];
    const float* lnb = (const float*)d_in[8];

    float* normed = (float*)d_out;                       // [B, L, D]
    float* attn;
    if ((size_t)out_size > (size_t)Bn*Ln*Dn) {
        attn = normed + (size_t)Bn*Ln*Dn;                // [B*H, L, L]
    } else {
        cudaGetSymbolAddress((void**)&attn, g_sc);
    }

    cudaFuncSetAttribute(proj_kernel,
                         cudaFuncAttributeMaxDynamicSharedMemorySize, PROJ_SMEM);
    cudaFuncSetAttribute(scores_kernel,
                         cudaFuncAttributeMaxDynamicSharedMemorySize, SCORES_SMEM);

    dim3 gp(Dn/128, Mn/128, 3);     // (8, 32, 3) — fused K/V/Q projections
    proj_kernel<<<gp, 256, PROJ_SMEM>>>(key, value, query, Wk, Wv, Wq);

    dim3 gs(Ln/128, Ln/128, BHn);   // (16, 16, 32)
    scores_kernel<<<gs, 256, SCORES_SMEM>>>(mask);

    rowsum_kernel<<<(BHn*Ln)/256, 256>>>();

    dim3 gv(Ln/128, BHn);        // (16, 32)
    pv_kernel<<<gv, 256>>>(attn);

    ln_kernel<<<Mn, 256>>>(query, lng, lnb, normed);
}

// round 13
// speedup vs baseline: 4.3462x; 1.1579x over previous
#include <cuda_runtime.h>
#include <cuda_fp16.h>
#include <cstdint>
#include <math.h>

#define Bn 2
#define Ln 2048
#define Dn 1024
#define Hn 16
#define DKn 64
#define BHn (Bn*Hn)      // 32
#define Mn (Bn*Ln)       // 4096

// Scratch (device globals — no allocation allowed)
__device__ __half g_q[(size_t)BHn*Ln*DKn];   // [bh][l][dk] fp16
__device__ __half g_k[(size_t)BHn*Ln*DKn];   // [bh][l][dk] fp16
__device__ __half g_vt[(size_t)BHn*DKn*Ln];  // [bh][dk][l] fp16 (transposed)
__device__ float g_o[(size_t)BHn*Ln*DKn];
__device__ float g_part[(size_t)BHn*Ln*32];
__device__ float g_ri[(size_t)BHn*Ln];
__device__ __half g_ub[(size_t)BHn*Ln*Ln];   // unnormalized u, fp16
// Fallback scores buffer in case the harness output holds only `normed`
__device__ float g_sc[(size_t)BHn*Ln*Ln];

// ---- tf32 mma (projections) ----
__device__ __forceinline__ unsigned f2tf(float x) {
    unsigned r; asm("cvt.rna.tf32.f32 %0, %1;" : "=r"(r) : "f"(x));
    return r;
}
__device__ __forceinline__ void mma_tf32(float* c, const unsigned* a, const unsigned* b) {
    asm volatile(
        "mma.sync.aligned.m16n8k8.row.col.f32.tf32.tf32.f32 "
        "{%0,%1,%2,%3}, {%4,%5,%6,%7}, {%8,%9}, {%0,%1,%2,%3};"
        : "+f"(c[0]), "+f"(c[1]), "+f"(c[2]), "+f"(c[3])
        : "r"(a[0]), "r"(a[1]), "r"(a[2]), "r"(a[3]),
          "r"(b[0]), "r"(b[1]));
}

// ---- fp16 mma (scores / pv): D(16x8,f32) += A(16x16,f16) * B(16x8,f16) ----
__device__ __forceinline__ void mma_f16(float* c, const unsigned* a, const unsigned* b) {
    asm volatile(
        "mma.sync.aligned.m16n8k16.row.col.f32.f16.f16.f32 "
        "{%0,%1,%2,%3}, {%4,%5,%6,%7}, {%8,%9}, {%0,%1,%2,%3};"
        : "+f"(c[0]), "+f"(c[1]), "+f"(c[2]), "+f"(c[3])
        : "r"(a[0]), "r"(a[1]), "r"(a[2]), "r"(a[3]),
          "r"(b[0]), "r"(b[1]));
}

// ---- cp.async helpers ----
__device__ __forceinline__ void cp16(void* smem_dst, const void* gmem_src) {
    unsigned dst = (unsigned)__cvta_generic_to_shared(smem_dst);
    asm volatile("cp.async.cg.shared.global [%0], [%1], 16;"
                 :: "r"(dst), "l"(gmem_src));
}
__device__ __forceinline__ void cp_commit() {
    asm volatile("cp.async.commit_group;");
}

// ---------------------------------------------------------------------------
// Fused projection GEMMs via tf32 mma, cp.async double-buffered.
// Epilogue writes fp16: K,Q -> [bh][l][dk]; V -> transposed [bh][dk][l].
// ---------------------------------------------------------------------------
#define PROJ_SMEM ((2*128*36 + 2*32*136) * 4)
__global__ __launch_bounds__(256, 2) void proj_kernel(const float* __restrict__ Xk,
                                                      const float* __restrict__ Xv,
                                                      const float* __restrict__ Xq,
                                                      const float* __restrict__ Wk,
                                                      const float* __restrict__ Wv,
                                                      const float* __restrict__ Wq) {
    const int which = blockIdx.z;
    const float* X = (which == 0) ? Xk : ((which == 1) ? Xv : Xq);
    const float* W = (which == 0) ? Wk : ((which == 1) ? Wv : Wq);

    const int bm = blockIdx.y * 128;
    const int bn = blockIdx.x * 128;
    const int tid = threadIdx.x;
    const int w = tid >> 5, lane = tid & 31;
    const int g = lane >> 2, t = lane & 3;
    const int mw = (w >> 1) * 32;
    const int nw = (w & 1) * 64;

    extern __shared__ float smem[];
    float* Xr = smem;                 // [2][128][36]
    float* Wr = smem + 2*128*36;      // [2][32][136]

    #define PROJ_STAGE(buf, k0)                                                   \
        do {                                                                      \
            float* Xd = &Xr[(size_t)(buf)*128*36];                                \
            float* Wd = &Wr[(size_t)(buf)*32*136];                                \
            _Pragma("unroll")                                                     \
            for (int it = 0; it < 4; it++) {                                      \
                int e = tid + it*256;                                             \
                int r = e >> 3, c4 = (e & 7) * 4;                                 \
                cp16(&Xd[r*36 + c4], &X[(size_t)(bm + r)*Dn + (k0) + c4]);        \
            }                                                                     \
            _Pragma("unroll")                                                     \
            for (int it = 0; it < 4; it++) {                                      \
                int e = tid + it*256;                                             \
                int kr = e >> 5, n4 = (e & 31) * 4;                               \
                cp16(&Wd[kr*136 + n4], &W[(size_t)((k0) + kr)*Dn + bn + n4]);     \
            }                                                                     \
            cp_commit();                                                          \
        } while (0)

    PROJ_STAGE(0, 0);

    float acc[2][8][4];
    #pragma unroll
    for (int mt = 0; mt < 2; mt++)
        #pragma unroll
        for (int nt = 0; nt < 8; nt++)
            #pragma unroll
            for (int c = 0; c < 4; c++) acc[mt][nt][c] = 0.f;

    const int NCH = Dn / 32;   // 32
    for (int i = 0; i < NCH; i++) {
        if (i < NCH - 1) {
            PROJ_STAGE((i + 1) & 1, (i + 1) * 32);
            asm volatile("cp.async.wait_group 1;");
        } else {
            asm volatile("cp.async.wait_group 0;");
        }
        __syncthreads();

        const float* Xc = &Xr[(size_t)(i & 1)*128*36];
        const float* Wc = &Wr[(size_t)(i & 1)*32*136];
        #pragma unroll
        for (int ks = 0; ks < 4; ks++) {
            int k = ks * 8;
            unsigned a[2][4];
            #pragma unroll
            for (int mt = 0; mt < 2; mt++) {
                int r = mw + mt*16 + g;
                a[mt][0] = f2tf(Xc[r*36 + k + t]);
                a[mt][1] = f2tf(Xc[(r+8)*36 + k + t]);
                a[mt][2] = f2tf(Xc[r*36 + k + t + 4]);
                a[mt][3] = f2tf(Xc[(r+8)*36 + k + t + 4]);
            }
            #pragma unroll
            for (int nt = 0; nt < 8; nt++) {
                int n = nw + nt*8 + g;
                unsigned b2[2];
                b2[0] = f2tf(Wc[(k+t)*136 + n]);
                b2[1] = f2tf(Wc[(k+t+4)*136 + n]);
                mma_tf32(acc[0][nt], a[0], b2);
                mma_tf32(acc[1][nt], a[1], b2);
            }
        }
        __syncthreads();
    }

    __half* outh = (which == 0) ? g_k : g_q;   // K or Q (row layout)
    #pragma unroll
    for (int mt = 0; mt < 2; mt++) {
        #pragma unroll
        for (int h2 = 0; h2 < 2; h2++) {
            int m = bm + mw + mt*16 + h2*8 + g;
            int bb = m >> 11, l = m & (Ln-1);
            #pragma unroll
            for (int nt = 0; nt < 8; nt++) {
                int n = bn + nw + nt*8 + 2*t;
                int h = n >> 6, dk = n & 63;
                float v0 = acc[mt][nt][h2*2+0];
                float v1 = acc[mt][nt][h2*2+1];
                if (which == 1) {   // V: transposed [bh][dk][l]
                    size_t base = ((size_t)(bb*Hn + h))*DKn;
                    g_vt[(base + dk)*Ln + l]     = __float2half(v0);
                    g_vt[(base + dk + 1)*Ln + l] = __float2half(v1);
                } else {            // K/Q: [bh][l][dk]
                    *(__half2*)&outh[(((size_t)(bb*Hn + h))*Ln + l)*DKn + dk] =
                        __floats2half2_rn(v0, v1);
                }
            }
        }
    }
    #undef PROJ_STAGE
}

// ---------------------------------------------------------------------------
// Scores via fp16 mma (m16n8k16): u = exp((q.k)/8) or 0 -> g_ub (fp16).
// Q/K staged fp16, one-shot cp.async; mask prefetched to a u64 bitmap.
// ---------------------------------------------------------------------------
#define SCORES_SMEM (2*128*72*2)
__global__ __launch_bounds__(256, 2) void scores_kernel(const int* __restrict__ mask) {
    const int bh = blockIdx.z;
    const int q0 = blockIdx.y * 128;
    const int j0 = blockIdx.x * 128;
    const int b = bh >> 4;
    const int tid = threadIdx.x;
    const int w = tid >> 5, lane = tid & 31;
    const int g = lane >> 2, t = lane & 3;
    const int qw = (w >> 1) * 32;
    const int jw = (w & 1) * 64;

    extern __shared__ float smemf[];
    __half* Qh = (__half*)smemf;           // [128][72]
    __half* Kh = Qh + 128*72;              // [128][72]

    // stage Q,K fp16: 128 rows x 64 halves = 8 cp16/row -> 4/thread each
    #pragma unroll
    for (int it = 0; it < 4; it++) {
        int e = tid + it*256;          // [0,1024)
        int r = e >> 3, c8 = (e & 7) * 8;
        cp16(&Qh[r*72 + c8], g_q + ((size_t)bh*Ln + q0 + r)*DKn + c8);
    }
    #pragma unroll
    for (int it = 0; it < 4; it++) {
        int e = tid + it*256;
        int r = e >> 3, c8 = (e & 7) * 8;
        cp16(&Kh[r*72 + c8], g_k + ((size_t)bh*Ln + j0 + r)*DKn + c8);
    }
    cp_commit();

    // mask prefetch + bit-compress (overlaps staging)
    unsigned long long mbits = 0ull;
    #pragma unroll
    for (int mt = 0; mt < 2; mt++) {
        #pragma unroll
        for (int h2 = 0; h2 < 2; h2++) {
            int q = q0 + qw + mt*16 + h2*8 + g;
            int2 mv[8];
            #pragma unroll
            for (int nt = 0; nt < 8; nt++) {
                int j = j0 + jw + nt*8 + 2*t;
                mv[nt] = *(const int2*)(mask + ((size_t)b*Ln + q)*Ln + j);
            }
            #pragma unroll
            for (int nt = 0; nt < 8; nt++) {
                int bit = ((mt*2 + h2)*8 + nt)*2;
                if (mv[nt].x) mbits |= 1ull << bit;
                if (mv[nt].y) mbits |= 2ull << bit;
            }
        }
    }

    asm volatile("cp.async.wait_group 0;");
    __syncthreads();

    float acc[2][8][4];
    #pragma unroll
    for (int mt = 0; mt < 2; mt++)
        #pragma unroll
        for (int nt = 0; nt < 8; nt++)
            #pragma unroll
            for (int c = 0; c < 4; c++) acc[mt][nt][c] = 0.f;

    #pragma unroll
    for (int ks = 0; ks < 4; ks++) {
        int k2 = ks * 16;
        unsigned a[2][4];
        #pragma unroll
        for (int mt = 0; mt < 2; mt++) {
            int r = qw + mt*16 + g;
            a[mt][0] = *(const unsigned*)&Qh[r*72 + k2 + 2*t];
            a[mt][1] = *(const unsigned*)&Qh[(r+8)*72 + k2 + 2*t];
            a[mt][2] = *(const unsigned*)&Qh[r*72 + k2 + 2*t + 8];
            a[mt][3] = *(const unsigned*)&Qh[(r+8)*72 + k2 + 2*t + 8];
        }
        #pragma unroll
        for (int nt = 0; nt < 8; nt++) {
            int rj = jw + nt*8 + g;
            unsigned b2[2];
            b2[0] = *(const unsigned*)&Kh[rj*72 + k2 + 2*t];
            b2[1] = *(const unsigned*)&Kh[rj*72 + k2 + 2*t + 8];
            mma_f16(acc[0][nt], a[0], b2);
            mma_f16(acc[1][nt], a[1], b2);
        }
    }

    // epilogue: exp (masked), fp16-pack u, per-row partial sums
    #pragma unroll
    for (int mt = 0; mt < 2; mt++) {
        #pragma unroll
        for (int h2 = 0; h2 < 2; h2++) {
            int q = q0 + qw + mt*16 + h2*8 + g;
            float s = 0.f;
            #pragma unroll
            for (int nt = 0; nt < 8; nt++) {
                int j = j0 + jw + nt*8 + 2*t;
                int bit = ((mt*2 + h2)*8 + nt)*2;
                float c0 = acc[mt][nt][h2*2+0];
                float c1 = acc[mt][nt][h2*2+1];
                float u0 = ((mbits >> bit) & 1ull) ? 0.f : __expf(c0*0.125f);
                float u1 = ((mbits >> bit) & 2ull) ? 0.f : __expf(c1*0.125f);
                s += u0 + u1;
                *(__half2*)(g_ub + ((size_t)bh*Ln + q)*Ln + j) =
                    __floats2half2_rn(u0, u1);
            }
            s += __shfl_xor_sync(0xffffffffu, s, 1);
            s += __shfl_xor_sync(0xffffffffu, s, 2);
            if (t == 0)
                g_part[((size_t)bh*Ln + q)*32 + blockIdx.x*2 + (w & 1)] = s;
        }
    }
}

// ---------------------------------------------------------------------------
// Row-sum reduction: ri[bh,q] = 1 / sum of 32 partials
// ---------------------------------------------------------------------------
__global__ __launch_bounds__(256) void rowsum_kernel() {
    int row = blockIdx.x * 256 + threadIdx.x;
    float s = 0.f;
    #pragma unroll
    for (int jb = 0; jb < 32; jb++) s += g_part[(size_t)row*32 + jb];
    g_ri[row] = 1.0f / s;
}

// ---------------------------------------------------------------------------
// PV via fp16 mma, j-chunk 64, u and V^T both cp.async double-buffered.
// Writes fp32 p = u*ri to attn (final output); o = (sum u*V)*ri.
// ---------------------------------------------------------------------------
#define PV_SMEM (2*128*72*2 + 2*64*72*2 + 512)
__global__ __launch_bounds__(256, 2) void pv_kernel(float* __restrict__ attn) {
    const int bh = blockIdx.y;
    const int q0 = blockIdx.x * 128;
    const int tid = threadIdx.x;
    const int w = tid >> 5, lane = tid & 31;
    const int g = lane >> 2, t = lane & 3;
    const int qw = w * 16;

    extern __shared__ float smemf[];
    __half* Ps = (__half*)smemf;             // [2][128][72]
    __half* Vt = Ps + 2*128*72;              // [2][64][72]
    float* riS = (float*)(Vt + 2*64*72);     // [128]

    if (tid < 128) riS[tid] = g_ri[(size_t)bh*Ln + q0 + tid];
    __syncthreads();

    const size_t scb = ((size_t)bh*Ln + q0)*Ln;
    const size_t vtb = (size_t)bh*DKn*Ln;

    float acc[8][4];
    #pragma unroll
    for (int nt = 0; nt < 8; nt++)
        #pragma unroll
        for (int c = 0; c < 4; c++) acc[nt][c] = 0.f;

    // stage chunk (64 j) into buffer buf: u 128x64 halves (4 cp16/thr),
    // Vt 64x64 halves (2 cp16/thr)
    #define PV_STAGE(buf, jc)                                                     \
        do {                                                                      \
            __half* Pd = Ps + (size_t)(buf)*128*72;                               \
            __half* Vd = Vt + (size_t)(buf)*64*72;                                \
            _Pragma("unroll")                                                     \
            for (int it = 0; it < 4; it++) {                                      \
                int e = tid + it*256;                                             \
                int q = e >> 3, c8 = (e & 7) * 8;                                 \
                cp16(&Pd[q*72 + c8], g_ub + scb + (size_t)q*Ln + (jc) + c8);      \
            }                                                                     \
            _Pragma("unroll")                                                     \
            for (int it = 0; it < 2; it++) {                                      \
                int e = tid + it*256;                                             \
                int d = e >> 3, c8 = (e & 7) * 8;                                 \
                cp16(&Vd[d*72 + c8], g_vt + vtb + (size_t)d*Ln + (jc) + c8);      \
            }                                                                     \
            cp_commit();                                                          \
        } while (0)

    PV_STAGE(0, 0);

    const int NCH = Ln / 64;   // 32
    for (int i = 0; i < NCH; i++) {
        const int jc = i * 64;
        const __half* Pc = Ps + (size_t)(i & 1)*128*72;
        const __half* Vc = Vt + (size_t)(i & 1)*64*72;

        if (i < NCH - 1) {
            PV_STAGE((i + 1) & 1, jc + 64);
            asm volatile("cp.async.wait_group 1;");
        } else {
            asm volatile("cp.async.wait_group 0;");
        }
        __syncthreads();

        // p-write: expand fp16 u, scale by ri, store fp32 to attn
        #pragma unroll
        for (int it = 0; it < 4; it++) {
            int e = tid + it*256;          // [0,1024): 8 halves per slot
            int q = e >> 3, j8 = (e & 7) * 8;
            uint4 pw = *(const uint4*)(Pc + q*72 + j8);
            float ri = riS[q];
            float2 f0 = __half22float2(*(__half2*)&pw.x);
            float2 f1 = __half22float2(*(__half2*)&pw.y);
            float2 f2 = __half22float2(*(__half2*)&pw.z);
            float2 f3 = __half22float2(*(__half2*)&pw.w);
            size_t gi = scb + (size_t)q*Ln + jc + j8;
            *(float4*)(attn + gi) =
                make_float4(f0.x*ri, f0.y*ri, f1.x*ri, f1.y*ri);
            *(float4*)(attn + gi + 4) =
                make_float4(f2.x*ri, f2.y*ri, f3.x*ri, f3.y*ri);
        }

        // MMA over chunk: 4 x k16 covers 64 j
        #pragma unroll
        for (int ks = 0; ks < 4; ks++) {
            int k2 = ks * 16;
            unsigned a[4];
            a[0] = *(const unsigned*)&Pc[(qw + g)*72 + k2 + 2*t];
            a[1] = *(const unsigned*)&Pc[(qw + 8 + g)*72 + k2 + 2*t];
            a[2] = *(const unsigned*)&Pc[(qw + g)*72 + k2 + 2*t + 8];
            a[3] = *(const unsigned*)&Pc[(qw + 8 + g)*72 + k2 + 2*t + 8];
            #pragma unroll
            for (int nt = 0; nt < 8; nt++) {
                int d = nt*8 + g;
                unsigned b2[2];
                b2[0] = *(const unsigned*)&Vc[d*72 + k2 + 2*t];
                b2[1] = *(const unsigned*)&Vc[d*72 + k2 + 2*t + 8];
                mma_f16(acc[nt], a, b2);
            }
        }
        __syncthreads();
    }

    #pragma unroll
    for (int h2 = 0; h2 < 2; h2++) {
        int qr = qw + h2*8 + g;
        float ri = riS[qr];
        int q = q0 + qr;
        #pragma unroll
        for (int nt = 0; nt < 8; nt++) {
            int d = nt*8 + 2*t;
            *(float2*)&g_o[((size_t)bh*Ln + q)*DKn + d] =
                make_float2(acc[nt][h2*2+0]*ri, acc[nt][h2*2+1]*ri);
        }
    }
    #undef PV_STAGE
}

// ---------------------------------------------------------------------------
// Residual + LayerNorm (unchanged)
// ---------------------------------------------------------------------------
__global__ __launch_bounds__(256) void ln_kernel(const float* __restrict__ query,
                                                 const float* __restrict__ gamma,
                                                 const float* __restrict__ beta,
                                                 float* __restrict__ out) {
    const int row = blockIdx.x;
    const int b = row >> 11, l = row & (Ln-1);
    const int tid = threadIdx.x;
    float vals[4];
    float s = 0.f, ss = 0.f;
    #pragma unroll
    for (int it = 0; it < 4; it++) {
        int d = tid + it*256;
        int h = d >> 6, dk = d & 63;
        float o = g_o[(((size_t)(b*Hn + h))*Ln + l)*DKn + dk];
        float r = o + query[(size_t)row*Dn + d];
        vals[it] = r;
        s += r; ss += r*r;
    }
    __shared__ float sm[8], sq[8], stat[2];
    #pragma unroll
    for (int off = 16; off; off >>= 1) {
        s  += __shfl_xor_sync(0xffffffffu, s, off);
        ss += __shfl_xor_sync(0xffffffffu, ss, off);
    }
    int warp = tid >> 5, lane = tid & 31;
    if (lane == 0) { sm[warp] = s; sq[warp] = ss; }
    __syncthreads();
    if (tid == 0) {
        float S = 0.f, SS = 0.f;
        #pragma unroll
        for (int w = 0; w < 8; w++) { S += sm[w]; SS += sq[w]; }
        float mu = S * (1.0f/Dn);
        float var = SS * (1.0f/Dn) - mu*mu;
        stat[0] = mu;
        stat[1] = rsqrtf(var + 1e-6f);
    }
    __syncthreads();
    float mu = stat[0], rstd = stat[1];
    #pragma unroll
    for (int it = 0; it < 4; it++) {
        int d = tid + it*256;
        out[(size_t)row*Dn + d] = (vals[it] - mu) * rstd * gamma[d] + beta[d];
    }
}

// ---------------------------------------------------------------------------
extern "C" void kernel_launch(void* const* d_in, const int* in_sizes, int n_in,
                              void* d_out, int out_size) {
    const float* key   = (const float*)d_in[0];
    const float* value = (const float*)d_in[1];
    const float* query = (const float*)d_in[2];
    const int*   mask  = (const int*)d_in[3];
    const float* Wk = (const float*)d_in[4];
    const float* Wv = (const float*)d_in[5];
    const float* Wq = (const float*)d_in[6];
    const float* lng = (const float*)d_in[7];
    const float* lnb = (const float*)d_in[8];

    float* normed = (float*)d_out;                       // [B, L, D]
    float* attn;
    if ((size_t)out_size > (size_t)Bn*Ln*Dn) {
        attn = normed + (size_t)Bn*Ln*Dn;                // [B*H, L, L]
    } else {
        cudaGetSymbolAddress((void**)&attn, g_sc);
    }

    cudaFuncSetAttribute(proj_kernel,
                         cudaFuncAttributeMaxDynamicSharedMemorySize, PROJ_SMEM);
    cudaFuncSetAttribute(scores_kernel,
                         cudaFuncAttributeMaxDynamicSharedMemorySize, SCORES_SMEM);
    cudaFuncSetAttribute(pv_kernel,
                         cudaFuncAttributeMaxDynamicSharedMemorySize, PV_SMEM);

    dim3 gp(Dn/128, Mn/128, 3);
    proj_kernel<<<gp, 256, PROJ_SMEM>>>(key, value, query, Wk, Wv, Wq);

    dim3 gs(Ln/128, Ln/128, BHn);
    scores_kernel<<<gs, 256, SCORES_SMEM>>>(mask);

    rowsum_kernel<<<(BHn*Ln)/256, 256>>>();

    dim3 gv(Ln/128, BHn);
    pv_kernel<<<gv, 256, PV_SMEM>>>(attn);

    ln_kernel<<<Mn, 256>>>(query, lng, lnb, normed);
}

// round 14
// speedup vs baseline: 4.3718x; 1.0059x over previous
#include <cuda_runtime.h>
#include <cuda_fp16.h>
#include <cstdint>
#include <math.h>

#define Bn 2
#define Ln 2048
#define Dn 1024
#define Hn 16
#define DKn 64
#define BHn (Bn*Hn)      // 32
#define Mn (Bn*Ln)       // 4096

// Scratch (device globals — no allocation allowed)
__device__ __half g_q[(size_t)BHn*Ln*DKn];   // [bh][l][dk] fp16
__device__ __half g_k[(size_t)BHn*Ln*DKn];   // [bh][l][dk] fp16
__device__ __half g_vt[(size_t)BHn*DKn*Ln];  // [bh][dk][l] fp16 (transposed)
__device__ float g_o[(size_t)BHn*Ln*DKn];
__device__ float g_ri[(size_t)BHn*Ln];
__device__ __half g_ub[(size_t)BHn*Ln*Ln];   // unnormalized u, fp16
__device__ unsigned long long g_mb[(size_t)Bn*Ln*(Ln/64)];  // mask bitmap
// Fallback scores buffer in case the harness output holds only `normed`
__device__ float g_sc[(size_t)BHn*Ln*Ln];

// ---- tf32 mma (projections) ----
__device__ __forceinline__ unsigned f2tf(float x) {
    unsigned r; asm("cvt.rna.tf32.f32 %0, %1;" : "=r"(r) : "f"(x));
    return r;
}
__device__ __forceinline__ void mma_tf32(float* c, const unsigned* a, const unsigned* b) {
    asm volatile(
        "mma.sync.aligned.m16n8k8.row.col.f32.tf32.tf32.f32 "
        "{%0,%1,%2,%3}, {%4,%5,%6,%7}, {%8,%9}, {%0,%1,%2,%3};"
        : "+f"(c[0]), "+f"(c[1]), "+f"(c[2]), "+f"(c[3])
        : "r"(a[0]), "r"(a[1]), "r"(a[2]), "r"(a[3]),
          "r"(b[0]), "r"(b[1]));
}

// ---- fp16 mma: D(16x8,f32) += A(16x16,f16) * B(16x8,f16) ----
__device__ __forceinline__ void mma_f16(float* c, const unsigned* a, const unsigned* b) {
    asm volatile(
        "mma.sync.aligned.m16n8k16.row.col.f32.f16.f16.f32 "
        "{%0,%1,%2,%3}, {%4,%5,%6,%7}, {%8,%9}, {%0,%1,%2,%3};"
        : "+f"(c[0]), "+f"(c[1]), "+f"(c[2]), "+f"(c[3])
        : "r"(a[0]), "r"(a[1]), "r"(a[2]), "r"(a[3]),
          "r"(b[0]), "r"(b[1]));
}

// ---- cp.async helpers ----
__device__ __forceinline__ void cp16(void* smem_dst, const void* gmem_src) {
    unsigned dst = (unsigned)__cvta_generic_to_shared(smem_dst);
    asm volatile("cp.async.cg.shared.global [%0], [%1], 16;"
                 :: "r"(dst), "l"(gmem_src));
}
__device__ __forceinline__ void cp_commit() {
    asm volatile("cp.async.commit_group;");
}
__device__ __forceinline__ unsigned h2u(__half2 h) {
    return *(unsigned*)&h;
}

// ---------------------------------------------------------------------------
// Mask bitmap compression: 64 int32 bools -> one u64 (ballot-based).
// ---------------------------------------------------------------------------
__global__ __launch_bounds__(256) void maskc_kernel(const int* __restrict__ mask) {
    int gw = blockIdx.x * 8 + (threadIdx.x >> 5);   // 4096 warps
    int lane = threadIdx.x & 31;
    #pragma unroll
    for (int k = 0; k < 32; k++) {
        size_t word = (size_t)gw * 32 + k;          // [0, 131072)
        size_t base = word * 64;
        unsigned lo = __ballot_sync(0xffffffffu, mask[base + lane] != 0);
        unsigned hi = __ballot_sync(0xffffffffu, mask[base + 32 + lane] != 0);
        if (lane == 0)
            g_mb[word] = (unsigned long long)lo | ((unsigned long long)hi << 32);
    }
}

// ---------------------------------------------------------------------------
// Fused projection GEMMs via tf32 mma (round-13 validated, unchanged).
// ---------------------------------------------------------------------------
#define PROJ_SMEM ((2*128*36 + 2*32*136) * 4)
__global__ __launch_bounds__(256, 2) void proj_kernel(const float* __restrict__ Xk,
                                                      const float* __restrict__ Xv,
                                                      const float* __restrict__ Xq,
                                                      const float* __restrict__ Wk,
                                                      const float* __restrict__ Wv,
                                                      const float* __restrict__ Wq) {
    const int which = blockIdx.z;
    const float* X = (which == 0) ? Xk : ((which == 1) ? Xv : Xq);
    const float* W = (which == 0) ? Wk : ((which == 1) ? Wv : Wq);

    const int bm = blockIdx.y * 128;
    const int bn = blockIdx.x * 128;
    const int tid = threadIdx.x;
    const int w = tid >> 5, lane = tid & 31;
    const int g = lane >> 2, t = lane & 3;
    const int mw = (w >> 1) * 32;
    const int nw = (w & 1) * 64;

    extern __shared__ float smem[];
    float* Xr = smem;                 // [2][128][36]
    float* Wr = smem + 2*128*36;      // [2][32][136]

    #define PROJ_STAGE(buf, k0)                                                   \
        do {                                                                      \
            float* Xd = &Xr[(size_t)(buf)*128*36];                                \
            float* Wd = &Wr[(size_t)(buf)*32*136];                                \
            _Pragma("unroll")                                                     \
            for (int it = 0; it < 4; it++) {                                      \
                int e = tid + it*256;                                             \
                int r = e >> 3, c4 = (e & 7) * 4;                                 \
                cp16(&Xd[r*36 + c4], &X[(size_t)(bm + r)*Dn + (k0) + c4]);        \
            }                                                                     \
            _Pragma("unroll")                                                     \
            for (int it = 0; it < 4; it++) {                                      \
                int e = tid + it*256;                                             \
                int kr = e >> 5, n4 = (e & 31) * 4;                               \
                cp16(&Wd[kr*136 + n4], &W[(size_t)((k0) + kr)*Dn + bn + n4]);     \
            }                                                                     \
            cp_commit();                                                          \
        } while (0)

    PROJ_STAGE(0, 0);

    float acc[2][8][4];
    #pragma unroll
    for (int mt = 0; mt < 2; mt++)
        #pragma unroll
        for (int nt = 0; nt < 8; nt++)
            #pragma unroll
            for (int c = 0; c < 4; c++) acc[mt][nt][c] = 0.f;

    const int NCH = Dn / 32;   // 32
    for (int i = 0; i < NCH; i++) {
        if (i < NCH - 1) {
            PROJ_STAGE((i + 1) & 1, (i + 1) * 32);
            asm volatile("cp.async.wait_group 1;");
        } else {
            asm volatile("cp.async.wait_group 0;");
        }
        __syncthreads();

        const float* Xc = &Xr[(size_t)(i & 1)*128*36];
        const float* Wc = &Wr[(size_t)(i & 1)*32*136];
        #pragma unroll
        for (int ks = 0; ks < 4; ks++) {
            int k = ks * 8;
            unsigned a[2][4];
            #pragma unroll
            for (int mt = 0; mt < 2; mt++) {
                int r = mw + mt*16 + g;
                a[mt][0] = f2tf(Xc[r*36 + k + t]);
                a[mt][1] = f2tf(Xc[(r+8)*36 + k + t]);
                a[mt][2] = f2tf(Xc[r*36 + k + t + 4]);
                a[mt][3] = f2tf(Xc[(r+8)*36 + k + t + 4]);
            }
            #pragma unroll
            for (int nt = 0; nt < 8; nt++) {
                int n = nw + nt*8 + g;
                unsigned b2[2];
                b2[0] = f2tf(Wc[(k+t)*136 + n]);
                b2[1] = f2tf(Wc[(k+t+4)*136 + n]);
                mma_tf32(acc[0][nt], a[0], b2);
                mma_tf32(acc[1][nt], a[1], b2);
            }
        }
        __syncthreads();
    }

    __half* outh = (which == 0) ? g_k : g_q;
    #pragma unroll
    for (int mt = 0; mt < 2; mt++) {
        #pragma unroll
        for (int h2 = 0; h2 < 2; h2++) {
            int m = bm + mw + mt*16 + h2*8 + g;
            int bb = m >> 11, l = m & (Ln-1);
            #pragma unroll
            for (int nt = 0; nt < 8; nt++) {
                int n = bn + nw + nt*8 + 2*t;
                int h = n >> 6, dk = n & 63;
                float v0 = acc[mt][nt][h2*2+0];
                float v1 = acc[mt][nt][h2*2+1];
                if (which == 1) {
                    size_t base = ((size_t)(bb*Hn + h))*DKn;
                    g_vt[(base + dk)*Ln + l]     = __float2half(v0);
                    g_vt[(base + dk + 1)*Ln + l] = __float2half(v1);
                } else {
                    *(__half2*)&outh[(((size_t)(bb*Hn + h))*Ln + l)*DKn + dk] =
                        __floats2half2_rn(v0, v1);
                }
            }
        }
    }
    #undef PROJ_STAGE
}

// ---------------------------------------------------------------------------
// Fused scores+PV (flash-attn style). grid (Ln/128, BHn); 8 warps = 4m x 2n.
// Per CTA: q-tile 128, loop all j in chunks of 64 (each n-warp owns 32 j).
// Computes u=exp(qk/8) (masked) -> g_ub fp16; accumulates o += u*V in regs
// via S-frag -> A-frag conversion; full rowsum local -> g_ri; o*ri -> g_o.
// ---------------------------------------------------------------------------
#define QH_OFF 0                    // half[128][72]  = 18432 B
#define KH_OFF 18432                // half[2][64][72] = 18432 B
#define VH_OFF 36864                // half[2][64][72] = 18432 B
#define MB_OFF 55296                // u64 [128][34]  = 34816 B
#define RS_OFF 90112                // float[128][2]  = 1024 B
#define FUSED_SMEM 91136
__global__ __launch_bounds__(256, 2) void fused_kernel() {
    const int bh = blockIdx.y;
    const int q0 = blockIdx.x * 128;
    const int b = bh >> 4;
    const int tid = threadIdx.x;
    const int w = tid >> 5, lane = tid & 31;
    const int g = lane >> 2, t = lane & 3;
    const int mw = (w >> 1) * 32;    // q offset within tile
    const int jw = (w & 1) * 32;     // j offset within 64-chunk

    extern __shared__ char sm[];
    __half* Qh = (__half*)(sm + QH_OFF);                       // [128][72]
    __half* Kh = (__half*)(sm + KH_OFF);                       // [2][64][72]
    __half* Vh = (__half*)(sm + VH_OFF);                       // [2][64][72]
    unsigned long long* mb = (unsigned long long*)(sm + MB_OFF); // [128][34]
    float* rsums = (float*)(sm + RS_OFF);                      // [128][2]

    // ---- prologue staging: Q tile, mask bitmap, K/V chunk 0 ----
    #pragma unroll
    for (int it = 0; it < 4; it++) {
        int e = tid + it*256;                   // [0,1024)
        int r = e >> 3, c8 = (e & 7) * 8;
        cp16(&Qh[r*72 + c8], g_q + ((size_t)bh*Ln + q0 + r)*DKn + c8);
    }
    #pragma unroll
    for (int it = 0; it < 8; it++) {
        int e = tid + it*256;                   // [0,2048)
        int r = e >> 4, w2 = (e & 15) * 2;
        cp16(&mb[r*34 + w2], g_mb + ((size_t)b*Ln + q0 + r)*32 + w2);
    }
    #define STAGE_KV(buf, jc_)                                                    \
        do {                                                                      \
            __half* Kd = Kh + (size_t)(buf)*64*72;                                \
            __half* Vd = Vh + (size_t)(buf)*64*72;                                \
            _Pragma("unroll")                                                     \
            for (int it = 0; it < 2; it++) {                                      \
                int e = tid + it*256;                                             \
                int r = e >> 3, c8 = (e & 7) * 8;                                 \
                cp16(&Kd[r*72 + c8], g_k + ((size_t)bh*Ln + (jc_) + r)*DKn + c8); \
            }                                                                     \
            _Pragma("unroll")                                                     \
            for (int it = 0; it < 2; it++) {                                      \
                int e = tid + it*256;                                             \
                int r = e >> 3, c8 = (e & 7) * 8;                                 \
                cp16(&Vd[r*72 + c8], g_vt + ((size_t)bh*DKn + r)*Ln + (jc_) + c8);\
            }                                                                     \
        } while (0)

    STAGE_KV(0, 0);
    cp_commit();

    float oacc[2][8][4];
    #pragma unroll
    for (int mt = 0; mt < 2; mt++)
        #pragma unroll
        for (int nt = 0; nt < 8; nt++)
            #pragma unroll
            for (int c = 0; c < 4; c++) oacc[mt][nt][c] = 0.f;
    float rs[2][2] = {{0.f,0.f},{0.f,0.f}};

    const int NCH = Ln / 64;   // 32
    for (int i = 0; i < NCH; i++) {
        const int jc = i * 64;
        if (i < NCH - 1) {
            STAGE_KV((i + 1) & 1, jc + 64);
            cp_commit();
            asm volatile("cp.async.wait_group 1;");
        } else {
            asm volatile("cp.async.wait_group 0;");
        }
        __syncthreads();

        const __half* Kc = Kh + (size_t)(i & 1)*64*72;
        const __half* Vc = Vh + (size_t)(i & 1)*64*72;

        // mask words for this chunk (word index == chunk index)
        unsigned long long mwd[2][2];
        #pragma unroll
        for (int mt = 0; mt < 2; mt++)
            #pragma unroll
            for (int h2 = 0; h2 < 2; h2++)
                mwd[mt][h2] = mb[(mw + mt*16 + h2*8 + g)*34 + i];

        #pragma unroll
        for (int sub = 0; sub < 2; sub++) {
            const int jb = jw + sub*16;     // local j base of this 16-wide strip
            // ---- QK^T: S[32q x 16j] per warp ----
            float sacc[2][2][4];
            #pragma unroll
            for (int mt = 0; mt < 2; mt++)
                #pragma unroll
                for (int n2 = 0; n2 < 2; n2++)
                    #pragma unroll
                    for (int c = 0; c < 4; c++) sacc[mt][n2][c] = 0.f;
            #pragma unroll
            for (int ks = 0; ks < 4; ks++) {
                int k2 = ks * 16;
                unsigned a[2][4];
                #pragma unroll
                for (int mt = 0; mt < 2; mt++) {
                    int r = mw + mt*16 + g;
                    a[mt][0] = *(const unsigned*)&Qh[r*72 + k2 + 2*t];
                    a[mt][1] = *(const unsigned*)&Qh[(r+8)*72 + k2 + 2*t];
                    a[mt][2] = *(const unsigned*)&Qh[r*72 + k2 + 2*t + 8];
                    a[mt][3] = *(const unsigned*)&Qh[(r+8)*72 + k2 + 2*t + 8];
                }
                #pragma unroll
                for (int n2 = 0; n2 < 2; n2++) {
                    int rj = jb + n2*8 + g;
                    unsigned bb[2];
                    bb[0] = *(const unsigned*)&Kc[rj*72 + k2 + 2*t];
                    bb[1] = *(const unsigned*)&Kc[rj*72 + k2 + 2*t + 8];
                    mma_f16(sacc[0][n2], a[0], bb);
                    mma_f16(sacc[1][n2], a[1], bb);
                }
            }
            // ---- epilogue: mask, exp, u store, rowsum, S->A conversion ----
            unsigned pa[2][4];
            #pragma unroll
            for (int mt = 0; mt < 2; mt++) {
                float uu[2][4];
                #pragma unroll
                for (int n2 = 0; n2 < 2; n2++) {
                    int boff = jb + n2*8 + 2*t;
                    unsigned long long m0 = mwd[mt][0] >> boff;
                    unsigned long long m1 = mwd[mt][1] >> boff;
                    uu[n2][0] = (m0 & 1ull) ? 0.f : __expf(sacc[mt][n2][0]*0.125f);
                    uu[n2][1] = (m0 & 2ull) ? 0.f : __expf(sacc[mt][n2][1]*0.125f);
                    uu[n2][2] = (m1 & 1ull) ? 0.f : __expf(sacc[mt][n2][2]*0.125f);
                    uu[n2][3] = (m1 & 2ull) ? 0.f : __expf(sacc[mt][n2][3]*0.125f);
                    int qrow = q0 + mw + mt*16 + g;
                    size_t base = ((size_t)bh*Ln + qrow)*Ln + jc + boff;
                    *(__half2*)(g_ub + base) = __floats2half2_rn(uu[n2][0], uu[n2][1]);
                    *(__half2*)(g_ub + base + (size_t)8*Ln) =
                        __floats2half2_rn(uu[n2][2], uu[n2][3]);
                }
                rs[mt][0] += (uu[0][0]+uu[0][1]) + (uu[1][0]+uu[1][1]);
                rs[mt][1] += (uu[0][2]+uu[0][3]) + (uu[1][2]+uu[1][3]);
                pa[mt][0] = h2u(__floats2half2_rn(uu[0][0], uu[0][1]));
                pa[mt][1] = h2u(__floats2half2_rn(uu[0][2], uu[0][3]));
                pa[mt][2] = h2u(__floats2half2_rn(uu[1][0], uu[1][1]));
                pa[mt][3] = h2u(__floats2half2_rn(uu[1][2], uu[1][3]));
            }
            // ---- PV: o += u(16j) * V ----
            #pragma unroll
            for (int ntd = 0; ntd < 8; ntd++) {
                int n = ntd*8 + g;
                unsigned bv[2];
                bv[0] = *(const unsigned*)&Vc[n*72 + jb + 2*t];
                bv[1] = *(const unsigned*)&Vc[n*72 + jb + 2*t + 8];
                mma_f16(oacc[0][ntd], pa[0], bv);
                mma_f16(oacc[1][ntd], pa[1], bv);
            }
        }
        __syncthreads();
    }

    // ---- rowsum reduce over t-lanes; combine the two n-warps via smem ----
    #pragma unroll
    for (int mt = 0; mt < 2; mt++)
        #pragma unroll
        for (int h2 = 0; h2 < 2; h2++) {
            float v = rs[mt][h2];
            v += __shfl_xor_sync(0xffffffffu, v, 1);
            v += __shfl_xor_sync(0xffffffffu, v, 2);
            if (t == 0)
                rsums[(mw + mt*16 + h2*8 + g)*2 + (w & 1)] = v;
        }
    __syncthreads();
    if (tid < 128) {
        float s = rsums[tid*2 + 0] + rsums[tid*2 + 1];
        float ri = 1.0f / s;
        g_ri[(size_t)bh*Ln + q0 + tid] = ri;
        rsums[tid*2 + 0] = ri;   // keep for local O scaling
    }
    __syncthreads();

    // ---- cross-warp O reduction (odd warps stash, even warps finalize) ----
    float* Osm = (float*)(sm + KH_OFF);    // [128][66] floats (reuses K/V space)
    if (w & 1) {
        #pragma unroll
        for (int mt = 0; mt < 2; mt++) {
            int ql = mw + mt*16 + g;
            #pragma unroll
            for (int ntd = 0; ntd < 8; ntd++) {
                int dk = ntd*8 + 2*t;
                *(float2*)&Osm[ql*66 + dk] =
                    make_float2(oacc[mt][ntd][0], oacc[mt][ntd][1]);
                *(float2*)&Osm[(ql+8)*66 + dk] =
                    make_float2(oacc[mt][ntd][2], oacc[mt][ntd][3]);
            }
        }
    }
    __syncthreads();
    if (!(w & 1)) {
        #pragma unroll
        for (int mt = 0; mt < 2; mt++) {
            int ql = mw + mt*16 + g;
            float ri0 = rsums[ql*2];
            float ri8 = rsums[(ql+8)*2];
            #pragma unroll
            for (int ntd = 0; ntd < 8; ntd++) {
                int dk = ntd*8 + 2*t;
                float2 s0 = *(float2*)&Osm[ql*66 + dk];
                float2 s8 = *(float2*)&Osm[(ql+8)*66 + dk];
                size_t ob = ((size_t)bh*Ln + q0 + ql)*DKn + dk;
                *(float2*)&g_o[ob] =
                    make_float2((oacc[mt][ntd][0]+s0.x)*ri0,
                                (oacc[mt][ntd][1]+s0.y)*ri0);
                *(float2*)&g_o[ob + (size_t)8*DKn] =
                    make_float2((oacc[mt][ntd][2]+s8.x)*ri8,
                                (oacc[mt][ntd][3]+s8.y)*ri8);
            }
        }
    }
    #undef STAGE_KV
}

// ---------------------------------------------------------------------------
// Normalize stream: attn[row][j] = u[row][j] * ri[row]  (fp16 -> fp32)
// One block per row; 256 threads x 8 elements = 2048.
// ---------------------------------------------------------------------------
__global__ __launch_bounds__(256) void norm_kernel(float* __restrict__ attn) {
    const size_t row = blockIdx.x;          // bh*Ln + q
    const float ri = g_ri[row];
    const int j8 = threadIdx.x * 8;
    uint4 pw = *(const uint4*)(g_ub + row*Ln + j8);
    float2 f0 = __half22float2(*(__half2*)&pw.x);
    float2 f1 = __half22float2(*(__half2*)&pw.y);
    float2 f2 = __half22float2(*(__half2*)&pw.z);
    float2 f3 = __half22float2(*(__half2*)&pw.w);
    float* dst = attn + row*Ln + j8;
    *(float4*)dst       = make_float4(f0.x*ri, f0.y*ri, f1.x*ri, f1.y*ri);
    *(float4*)(dst + 4) = make_float4(f2.x*ri, f2.y*ri, f3.x*ri, f3.y*ri);
}

// ---------------------------------------------------------------------------
// Residual + LayerNorm (unchanged)
// ---------------------------------------------------------------------------
__global__ __launch_bounds__(256) void ln_kernel(const float* __restrict__ query,
                                                 const float* __restrict__ gamma,
                                                 const float* __restrict__ beta,
                                                 float* __restrict__ out) {
    const int row = blockIdx.x;
    const int b = row >> 11, l = row & (Ln-1);
    const int tid = threadIdx.x;
    float vals[4];
    float s = 0.f, ss = 0.f;
    #pragma unroll
    for (int it = 0; it < 4; it++) {
        int d = tid + it*256;
        int h = d >> 6, dk = d & 63;
        float o = g_o[(((size_t)(b*Hn + h))*Ln + l)*DKn + dk];
        float r = o + query[(size_t)row*Dn + d];
        vals[it] = r;
        s += r; ss += r*r;
    }
    __shared__ float sm[8], sq[8], stat[2];
    #pragma unroll
    for (int off = 16; off; off >>= 1) {
        s  += __shfl_xor_sync(0xffffffffu, s, off);
        ss += __shfl_xor_sync(0xffffffffu, ss, off);
    }
    int warp = tid >> 5, lane = tid & 31;
    if (lane == 0) { sm[warp] = s; sq[warp] = ss; }
    __syncthreads();
    if (tid == 0) {
        float S = 0.f, SS = 0.f;
        #pragma unroll
        for (int w = 0; w < 8; w++) { S += sm[w]; SS += sq[w]; }
        float mu = S * (1.0f/Dn);
        float var = SS * (1.0f/Dn) - mu*mu;
        stat[0] = mu;
        stat[1] = rsqrtf(var + 1e-6f);
    }
    __syncthreads();
    float mu = stat[0], rstd = stat[1];
    #pragma unroll
    for (int it = 0; it < 4; it++) {
        int d = tid + it*256;
        out[(size_t)row*Dn + d] = (vals[it] - mu) * rstd * gamma[d] + beta[d];
    }
}

// ---------------------------------------------------------------------------
extern "C" void kernel_launch(void* const* d_in, const int* in_sizes, int n_in,
                              void* d_out, int out_size) {
    const float* key   = (const float*)d_in[0];
    const float* value = (const float*)d_in[1];
    const float* query = (const float*)d_in[2];
    const int*   mask  = (const int*)d_in[3];
    const float* Wk = (const float*)d_in[4];
    const float* Wv = (const float*)d_in[5];
    const float* Wq = (const float*)d_in[6];
    const float* lng = (const float*)d_in[7];
    const float* lnb = (const float*)d_in[8];

    float* normed = (float*)d_out;                       // [B, L, D]
    float* attn;
    if ((size_t)out_size > (size_t)Bn*Ln*Dn) {
        attn = normed + (size_t)Bn*Ln*Dn;                // [B*H, L, L]
    } else {
        cudaGetSymbolAddress((void**)&attn, g_sc);
    }

    cudaFuncSetAttribute(proj_kernel,
                         cudaFuncAttributeMaxDynamicSharedMemorySize, PROJ_SMEM);
    cudaFuncSetAttribute(fused_kernel,
                         cudaFuncAttributeMaxDynamicSharedMemorySize, FUSED_SMEM);

    maskc_kernel<<<512, 256>>>(mask);

    dim3 gp(Dn/128, Mn/128, 3);
    proj_kernel<<<gp, 256, PROJ_SMEM>>>(key, value, query, Wk, Wv, Wq);

    dim3 gf(Ln/128, BHn);       // (16, 32)
    fused_kernel<<<gf, 256, FUSED_SMEM>>>();

    norm_kernel<<<BHn*Ln, 256>>>(attn);

    ln_kernel<<<Mn, 256>>>(query, lng, lnb, normed);
}

// round 15
// speedup vs baseline: 4.5910x; 1.0501x over previous
#include <cuda_runtime.h>
#include <cuda_fp16.h>
#include <cstdint>
#include <math.h>

#define Bn 2
#define Ln 2048
#define Dn 1024
#define Hn 16
#define DKn 64
#define BHn (Bn*Hn)      // 32
#define Mn (Bn*Ln)       // 4096

// Scratch (device globals — no allocation allowed)
__device__ __half g_q[(size_t)BHn*Ln*DKn];   // [bh][l][dk] fp16
__device__ __half g_k[(size_t)BHn*Ln*DKn];   // [bh][l][dk] fp16
__device__ __half g_vt[(size_t)BHn*DKn*Ln];  // [bh][dk][l] fp16 (transposed)
__device__ float g_o[(size_t)BHn*Ln*DKn];
__device__ unsigned long long g_mb[(size_t)Bn*Ln*(Ln/64)];  // mask bitmap
// Fallback scores buffer in case the harness output holds only `normed`
__device__ float g_sc[(size_t)BHn*Ln*Ln];

// ---- tf32 mma (projections) ----
__device__ __forceinline__ unsigned f2tf(float x) {
    unsigned r; asm("cvt.rna.tf32.f32 %0, %1;" : "=r"(r) : "f"(x));
    return r;
}
__device__ __forceinline__ void mma_tf32(float* c, const unsigned* a, const unsigned* b) {
    asm volatile(
        "mma.sync.aligned.m16n8k8.row.col.f32.tf32.tf32.f32 "
        "{%0,%1,%2,%3}, {%4,%5,%6,%7}, {%8,%9}, {%0,%1,%2,%3};"
        : "+f"(c[0]), "+f"(c[1]), "+f"(c[2]), "+f"(c[3])
        : "r"(a[0]), "r"(a[1]), "r"(a[2]), "r"(a[3]),
          "r"(b[0]), "r"(b[1]));
}

// ---- fp16 mma: D(16x8,f32) += A(16x16,f16) * B(16x8,f16) ----
__device__ __forceinline__ void mma_f16(float* c, const unsigned* a, const unsigned* b) {
    asm volatile(
        "mma.sync.aligned.m16n8k16.row.col.f32.f16.f16.f32 "
        "{%0,%1,%2,%3}, {%4,%5,%6,%7}, {%8,%9}, {%0,%1,%2,%3};"
        : "+f"(c[0]), "+f"(c[1]), "+f"(c[2]), "+f"(c[3])
        : "r"(a[0]), "r"(a[1]), "r"(a[2]), "r"(a[3]),
          "r"(b[0]), "r"(b[1]));
}

// ---- cp.async helpers ----
__device__ __forceinline__ void cp16(void* smem_dst, const void* gmem_src) {
    unsigned dst = (unsigned)__cvta_generic_to_shared(smem_dst);
    asm volatile("cp.async.cg.shared.global [%0], [%1], 16;"
                 :: "r"(dst), "l"(gmem_src));
}
__device__ __forceinline__ void cp_commit() {
    asm volatile("cp.async.commit_group;");
}
__device__ __forceinline__ unsigned h2u(__half2 h) {
    return *(unsigned*)&h;
}

// ---------------------------------------------------------------------------
// Mask bitmap compression: 64 int32 bools -> one u64 (ballot-based).
// ---------------------------------------------------------------------------
__global__ __launch_bounds__(256) void maskc_kernel(const int* __restrict__ mask) {
    int gw = blockIdx.x * 8 + (threadIdx.x >> 5);   // 4096 warps
    int lane = threadIdx.x & 31;
    #pragma unroll
    for (int k = 0; k < 32; k++) {
        size_t word = (size_t)gw * 32 + k;          // [0, 131072)
        size_t base = word * 64;
        unsigned lo = __ballot_sync(0xffffffffu, mask[base + lane] != 0);
        unsigned hi = __ballot_sync(0xffffffffu, mask[base + 32 + lane] != 0);
        if (lane == 0)
            g_mb[word] = (unsigned long long)lo | ((unsigned long long)hi << 32);
    }
}

// ---------------------------------------------------------------------------
// Fused projection GEMMs via tf32 mma (round-13 validated, unchanged).
// ---------------------------------------------------------------------------
#define PROJ_SMEM ((2*128*36 + 2*32*136) * 4)
__global__ __launch_bounds__(256, 2) void proj_kernel(const float* __restrict__ Xk,
                                                      const float* __restrict__ Xv,
                                                      const float* __restrict__ Xq,
                                                      const float* __restrict__ Wk,
                                                      const float* __restrict__ Wv,
                                                      const float* __restrict__ Wq) {
    const int which = blockIdx.z;
    const float* X = (which == 0) ? Xk : ((which == 1) ? Xv : Xq);
    const float* W = (which == 0) ? Wk : ((which == 1) ? Wv : Wq);

    const int bm = blockIdx.y * 128;
    const int bn = blockIdx.x * 128;
    const int tid = threadIdx.x;
    const int w = tid >> 5, lane = tid & 31;
    const int g = lane >> 2, t = lane & 3;
    const int mw = (w >> 1) * 32;
    const int nw = (w & 1) * 64;

    extern __shared__ float smem[];
    float* Xr = smem;                 // [2][128][36]
    float* Wr = smem + 2*128*36;      // [2][32][136]

    #define PROJ_STAGE(buf, k0)                                                   \
        do {                                                                      \
            float* Xd = &Xr[(size_t)(buf)*128*36];                                \
            float* Wd = &Wr[(size_t)(buf)*32*136];                                \
            _Pragma("unroll")                                                     \
            for (int it = 0; it < 4; it++) {                                      \
                int e = tid + it*256;                                             \
                int r = e >> 3, c4 = (e & 7) * 4;                                 \
                cp16(&Xd[r*36 + c4], &X[(size_t)(bm + r)*Dn + (k0) + c4]);        \
            }                                                                     \
            _Pragma("unroll")                                                     \
            for (int it = 0; it < 4; it++) {                                      \
                int e = tid + it*256;                                             \
                int kr = e >> 5, n4 = (e & 31) * 4;                               \
                cp16(&Wd[kr*136 + n4], &W[(size_t)((k0) + kr)*Dn + bn + n4]);     \
            }                                                                     \
            cp_commit();                                                          \
        } while (0)

    PROJ_STAGE(0, 0);

    float acc[2][8][4];
    #pragma unroll
    for (int mt = 0; mt < 2; mt++)
        #pragma unroll
        for (int nt = 0; nt < 8; nt++)
            #pragma unroll
            for (int c = 0; c < 4; c++) acc[mt][nt][c] = 0.f;

    const int NCH = Dn / 32;   // 32
    for (int i = 0; i < NCH; i++) {
        if (i < NCH - 1) {
            PROJ_STAGE((i + 1) & 1, (i + 1) * 32);
            asm volatile("cp.async.wait_group 1;");
        } else {
            asm volatile("cp.async.wait_group 0;");
        }
        __syncthreads();

        const float* Xc = &Xr[(size_t)(i & 1)*128*36];
        const float* Wc = &Wr[(size_t)(i & 1)*32*136];
        #pragma unroll
        for (int ks = 0; ks < 4; ks++) {
            int k = ks * 8;
            unsigned a[2][4];
            #pragma unroll
            for (int mt = 0; mt < 2; mt++) {
                int r = mw + mt*16 + g;
                a[mt][0] = f2tf(Xc[r*36 + k + t]);
                a[mt][1] = f2tf(Xc[(r+8)*36 + k + t]);
                a[mt][2] = f2tf(Xc[r*36 + k + t + 4]);
                a[mt][3] = f2tf(Xc[(r+8)*36 + k + t + 4]);
            }
            #pragma unroll
            for (int nt = 0; nt < 8; nt++) {
                int n = nw + nt*8 + g;
                unsigned b2[2];
                b2[0] = f2tf(Wc[(k+t)*136 + n]);
                b2[1] = f2tf(Wc[(k+t+4)*136 + n]);
                mma_tf32(acc[0][nt], a[0], b2);
                mma_tf32(acc[1][nt], a[1], b2);
            }
        }
        __syncthreads();
    }

    __half* outh = (which == 0) ? g_k : g_q;
    #pragma unroll
    for (int mt = 0; mt < 2; mt++) {
        #pragma unroll
        for (int h2 = 0; h2 < 2; h2++) {
            int m = bm + mw + mt*16 + h2*8 + g;
            int bb = m >> 11, l = m & (Ln-1);
            #pragma unroll
            for (int nt = 0; nt < 8; nt++) {
                int n = bn + nw + nt*8 + 2*t;
                int h = n >> 6, dk = n & 63;
                float v0 = acc[mt][nt][h2*2+0];
                float v1 = acc[mt][nt][h2*2+1];
                if (which == 1) {
                    size_t base = ((size_t)(bb*Hn + h))*DKn;
                    g_vt[(base + dk)*Ln + l]     = __float2half(v0);
                    g_vt[(base + dk + 1)*Ln + l] = __float2half(v1);
                } else {
                    *(__half2*)&outh[(((size_t)(bb*Hn + h))*Ln + l)*DKn + dk] =
                        __floats2half2_rn(v0, v1);
                }
            }
        }
    }
    #undef PROJ_STAGE
}

// ---------------------------------------------------------------------------
// Fused 2-pass attention. grid (Ln/128, BHn); 8 warps = 4m x 2n.
// Pass A: rowsums (QK^T + mask + exp, no stores).
// Pass B: recompute u, p = u*ri -> attn fp32 (final), o += p*V -> g_o.
// ---------------------------------------------------------------------------
#define QH_OFF 0                    // half[128][72]   = 18432 B
#define KH_OFF 18432                // half[2][64][72] = 18432 B
#define VH_OFF 36864                // half[2][64][72] = 18432 B
#define MB_OFF 55296                // u64 [128][34]   = 34816 B
#define RS_OFF 90112                // float[128][2]   = 1024 B
#define FUSED_SMEM 91648
__global__ __launch_bounds__(256, 2) void fused_kernel(float* __restrict__ attn) {
    const int bh = blockIdx.y;
    const int q0 = blockIdx.x * 128;
    const int b = bh >> 4;
    const int tid = threadIdx.x;
    const int w = tid >> 5, lane = tid & 31;
    const int g = lane >> 2, t = lane & 3;
    const int mw = (w >> 1) * 32;    // q offset within tile
    const int jw = (w & 1) * 32;     // j offset within 64-chunk

    extern __shared__ char sm[];
    __half* Qh = (__half*)(sm + QH_OFF);                         // [128][72]
    __half* Kh = (__half*)(sm + KH_OFF);                         // [2][64][72]
    __half* Vh = (__half*)(sm + VH_OFF);                         // [2][64][72]
    unsigned long long* mb = (unsigned long long*)(sm + MB_OFF); // [128][34]
    float* rsums = (float*)(sm + RS_OFF);                        // [128][2]

    // ---- prologue staging: Q tile + mask bitmap ----
    #pragma unroll
    for (int it = 0; it < 4; it++) {
        int e = tid + it*256;                   // [0,1024)
        int r = e >> 3, c8 = (e & 7) * 8;
        cp16(&Qh[r*72 + c8], g_q + ((size_t)bh*Ln + q0 + r)*DKn + c8);
    }
    #pragma unroll
    for (int it = 0; it < 8; it++) {
        int e = tid + it*256;                   // [0,2048)
        int r = e >> 4, w2 = (e & 15) * 2;
        cp16(&mb[r*34 + w2], g_mb + ((size_t)b*Ln + q0 + r)*32 + w2);
    }
    #define STAGE_K(buf, jc_)                                                     \
        do {                                                                      \
            __half* Kd = Kh + (size_t)(buf)*64*72;                                \
            _Pragma("unroll")                                                     \
            for (int it = 0; it < 2; it++) {                                      \
                int e = tid + it*256;                                             \
                int r = e >> 3, c8 = (e & 7) * 8;                                 \
                cp16(&Kd[r*72 + c8], g_k + ((size_t)bh*Ln + (jc_) + r)*DKn + c8); \
            }                                                                     \
        } while (0)
    #define STAGE_V(buf, jc_)                                                     \
        do {                                                                      \
            __half* Vd = Vh + (size_t)(buf)*64*72;                                \
            _Pragma("unroll")                                                     \
            for (int it = 0; it < 2; it++) {                                      \
                int e = tid + it*256;                                             \
                int r = e >> 3, c8 = (e & 7) * 8;                                 \
                cp16(&Vd[r*72 + c8], g_vt + ((size_t)bh*DKn + r)*Ln + (jc_) + c8);\
            }                                                                     \
        } while (0)

    const int NCH = Ln / 64;   // 32

    // ================= PASS A: rowsums =================
    STAGE_K(0, 0);
    cp_commit();
    float rs[2][2] = {{0.f,0.f},{0.f,0.f}};

    for (int i = 0; i < NCH; i++) {
        const int jc = i * 64;
        if (i < NCH - 1) {
            STAGE_K((i + 1) & 1, jc + 64);
            cp_commit();
            asm volatile("cp.async.wait_group 1;");
        } else {
            asm volatile("cp.async.wait_group 0;");
        }
        __syncthreads();
        const __half* Kc = Kh + (size_t)(i & 1)*64*72;

        unsigned long long mwd[2][2];
        #pragma unroll
        for (int mt = 0; mt < 2; mt++)
            #pragma unroll
            for (int h2 = 0; h2 < 2; h2++)
                mwd[mt][h2] = mb[(mw + mt*16 + h2*8 + g)*34 + i];

        #pragma unroll
        for (int sub = 0; sub < 2; sub++) {
            const int jb = jw + sub*16;
            float sacc[2][2][4];
            #pragma unroll
            for (int mt = 0; mt < 2; mt++)
                #pragma unroll
                for (int n2 = 0; n2 < 2; n2++)
                    #pragma unroll
                    for (int c = 0; c < 4; c++) sacc[mt][n2][c] = 0.f;
            #pragma unroll
            for (int ks = 0; ks < 4; ks++) {
                int k2 = ks * 16;
                unsigned a[2][4];
                #pragma unroll
                for (int mt = 0; mt < 2; mt++) {
                    int r = mw + mt*16 + g;
                    a[mt][0] = *(const unsigned*)&Qh[r*72 + k2 + 2*t];
                    a[mt][1] = *(const unsigned*)&Qh[(r+8)*72 + k2 + 2*t];
                    a[mt][2] = *(const unsigned*)&Qh[r*72 + k2 + 2*t + 8];
                    a[mt][3] = *(const unsigned*)&Qh[(r+8)*72 + k2 + 2*t + 8];
                }
                #pragma unroll
                for (int n2 = 0; n2 < 2; n2++) {
                    int rj = jb + n2*8 + g;
                    unsigned bb[2];
                    bb[0] = *(const unsigned*)&Kc[rj*72 + k2 + 2*t];
                    bb[1] = *(const unsigned*)&Kc[rj*72 + k2 + 2*t + 8];
                    mma_f16(sacc[0][n2], a[0], bb);
                    mma_f16(sacc[1][n2], a[1], bb);
                }
            }
            #pragma unroll
            for (int mt = 0; mt < 2; mt++) {
                #pragma unroll
                for (int n2 = 0; n2 < 2; n2++) {
                    int boff = jb + n2*8 + 2*t;
                    unsigned long long m0 = mwd[mt][0] >> boff;
                    unsigned long long m1 = mwd[mt][1] >> boff;
                    rs[mt][0] += ((m0 & 1ull) ? 0.f : __expf(sacc[mt][n2][0]*0.125f))
                               + ((m0 & 2ull) ? 0.f : __expf(sacc[mt][n2][1]*0.125f));
                    rs[mt][1] += ((m1 & 1ull) ? 0.f : __expf(sacc[mt][n2][2]*0.125f))
                               + ((m1 & 2ull) ? 0.f : __expf(sacc[mt][n2][3]*0.125f));
                }
            }
        }
        __syncthreads();
    }

    // rowsum reduce (t-lanes, then both n-warps via smem) -> ri in rsums[q][0]
    #pragma unroll
    for (int mt = 0; mt < 2; mt++)
        #pragma unroll
        for (int h2 = 0; h2 < 2; h2++) {
            float v = rs[mt][h2];
            v += __shfl_xor_sync(0xffffffffu, v, 1);
            v += __shfl_xor_sync(0xffffffffu, v, 2);
            if (t == 0)
                rsums[(mw + mt*16 + h2*8 + g)*2 + (w & 1)] = v;
        }
    __syncthreads();
    if (tid < 128)
        rsums[tid*2] = 1.0f / (rsums[tid*2] + rsums[tid*2 + 1]);
    __syncthreads();

    // per-thread ri values for the 4 q-rows this thread owns
    float rith[2][2];
    #pragma unroll
    for (int mt = 0; mt < 2; mt++) {
        rith[mt][0] = rsums[(mw + mt*16 + g)*2];
        rith[mt][1] = rsums[(mw + mt*16 + 8 + g)*2];
    }

    // ================= PASS B: attn write + PV =================
    STAGE_K(0, 0);
    STAGE_V(0, 0);
    cp_commit();

    float oacc[2][8][4];
    #pragma unroll
    for (int mt = 0; mt < 2; mt++)
        #pragma unroll
        for (int nt = 0; nt < 8; nt++)
            #pragma unroll
            for (int c = 0; c < 4; c++) oacc[mt][nt][c] = 0.f;

    for (int i = 0; i < NCH; i++) {
        const int jc = i * 64;
        if (i < NCH - 1) {
            STAGE_K((i + 1) & 1, jc + 64);
            STAGE_V((i + 1) & 1, jc + 64);
            cp_commit();
            asm volatile("cp.async.wait_group 1;");
        } else {
            asm volatile("cp.async.wait_group 0;");
        }
        __syncthreads();

        const __half* Kc = Kh + (size_t)(i & 1)*64*72;
        const __half* Vc = Vh + (size_t)(i & 1)*64*72;

        unsigned long long mwd[2][2];
        #pragma unroll
        for (int mt = 0; mt < 2; mt++)
            #pragma unroll
            for (int h2 = 0; h2 < 2; h2++)
                mwd[mt][h2] = mb[(mw + mt*16 + h2*8 + g)*34 + i];

        #pragma unroll
        for (int sub = 0; sub < 2; sub++) {
            const int jb = jw + sub*16;
            float sacc[2][2][4];
            #pragma unroll
            for (int mt = 0; mt < 2; mt++)
                #pragma unroll
                for (int n2 = 0; n2 < 2; n2++)
                    #pragma unroll
                    for (int c = 0; c < 4; c++) sacc[mt][n2][c] = 0.f;
            #pragma unroll
            for (int ks = 0; ks < 4; ks++) {
                int k2 = ks * 16;
                unsigned a[2][4];
                #pragma unroll
                for (int mt = 0; mt < 2; mt++) {
                    int r = mw + mt*16 + g;
                    a[mt][0] = *(const unsigned*)&Qh[r*72 + k2 + 2*t];
                    a[mt][1] = *(const unsigned*)&Qh[(r+8)*72 + k2 + 2*t];
                    a[mt][2] = *(const unsigned*)&Qh[r*72 + k2 + 2*t + 8];
                    a[mt][3] = *(const unsigned*)&Qh[(r+8)*72 + k2 + 2*t + 8];
                }
                #pragma unroll
                for (int n2 = 0; n2 < 2; n2++) {
                    int rj = jb + n2*8 + g;
                    unsigned bb[2];
                    bb[0] = *(const unsigned*)&Kc[rj*72 + k2 + 2*t];
                    bb[1] = *(const unsigned*)&Kc[rj*72 + k2 + 2*t + 8];
                    mma_f16(sacc[0][n2], a[0], bb);
                    mma_f16(sacc[1][n2], a[1], bb);
                }
            }
            // epilogue: exp, normalize, write attn fp32, build p frags
            unsigned pa[2][4];
            #pragma unroll
            for (int mt = 0; mt < 2; mt++) {
                float pp[2][4];
                #pragma unroll
                for (int n2 = 0; n2 < 2; n2++) {
                    int boff = jb + n2*8 + 2*t;
                    unsigned long long m0 = mwd[mt][0] >> boff;
                    unsigned long long m1 = mwd[mt][1] >> boff;
                    pp[n2][0] = (m0 & 1ull) ? 0.f
                              : __expf(sacc[mt][n2][0]*0.125f) * rith[mt][0];
                    pp[n2][1] = (m0 & 2ull) ? 0.f
                              : __expf(sacc[mt][n2][1]*0.125f) * rith[mt][0];
                    pp[n2][2] = (m1 & 1ull) ? 0.f
                              : __expf(sacc[mt][n2][2]*0.125f) * rith[mt][1];
                    pp[n2][3] = (m1 & 2ull) ? 0.f
                              : __expf(sacc[mt][n2][3]*0.125f) * rith[mt][1];
                    int qrow = q0 + mw + mt*16 + g;
                    size_t base = ((size_t)bh*Ln + qrow)*Ln + jc + boff;
                    *(float2*)(attn + base) = make_float2(pp[n2][0], pp[n2][1]);
                    *(float2*)(attn + base + (size_t)8*Ln) =
                        make_float2(pp[n2][2], pp[n2][3]);
                }
                pa[mt][0] = h2u(__floats2half2_rn(pp[0][0], pp[0][1]));
                pa[mt][1] = h2u(__floats2half2_rn(pp[0][2], pp[0][3]));
                pa[mt][2] = h2u(__floats2half2_rn(pp[1][0], pp[1][1]));
                pa[mt][3] = h2u(__floats2half2_rn(pp[1][2], pp[1][3]));
            }
            // PV: o += p(16j) * V
            #pragma unroll
            for (int ntd = 0; ntd < 8; ntd++) {
                int n = ntd*8 + g;
                unsigned bv[2];
                bv[0] = *(const unsigned*)&Vc[n*72 + jb + 2*t];
                bv[1] = *(const unsigned*)&Vc[n*72 + jb + 2*t + 8];
                mma_f16(oacc[0][ntd], pa[0], bv);
                mma_f16(oacc[1][ntd], pa[1], bv);
            }
        }
        __syncthreads();
    }

    // ---- cross-warp O reduction (odd warps stash, even warps finalize) ----
    float* Osm = (float*)(sm + KH_OFF);    // [128][66] floats (reuses K/V space)
    if (w & 1) {
        #pragma unroll
        for (int mt = 0; mt < 2; mt++) {
            int ql = mw + mt*16 + g;
            #pragma unroll
            for (int ntd = 0; ntd < 8; ntd++) {
                int dk = ntd*8 + 2*t;
                *(float2*)&Osm[ql*66 + dk] =
                    make_float2(oacc[mt][ntd][0], oacc[mt][ntd][1]);
                *(float2*)&Osm[(ql+8)*66 + dk] =
                    make_float2(oacc[mt][ntd][2], oacc[mt][ntd][3]);
            }
        }
    }
    __syncthreads();
    if (!(w & 1)) {
        #pragma unroll
        for (int mt = 0; mt < 2; mt++) {
            int ql = mw + mt*16 + g;
            #pragma unroll
            for (int ntd = 0; ntd < 8; ntd++) {
                int dk = ntd*8 + 2*t;
                float2 s0 = *(float2*)&Osm[ql*66 + dk];
                float2 s8 = *(float2*)&Osm[(ql+8)*66 + dk];
                size_t ob = ((size_t)bh*Ln + q0 + ql)*DKn + dk;
                *(float2*)&g_o[ob] =
                    make_float2(oacc[mt][ntd][0]+s0.x, oacc[mt][ntd][1]+s0.y);
                *(float2*)&g_o[ob + (size_t)8*DKn] =
                    make_float2(oacc[mt][ntd][2]+s8.x, oacc[mt][ntd][3]+s8.y);
            }
        }
    }
    #undef STAGE_K
    #undef STAGE_V
}

// ---------------------------------------------------------------------------
// Residual + LayerNorm (unchanged)
// ---------------------------------------------------------------------------
__global__ __launch_bounds__(256) void ln_kernel(const float* __restrict__ query,
                                                 const float* __restrict__ gamma,
                                                 const float* __restrict__ beta,
                                                 float* __restrict__ out) {
    const int row = blockIdx.x;
    const int b = row >> 11, l = row & (Ln-1);
    const int tid = threadIdx.x;
    float vals[4];
    float s = 0.f, ss = 0.f;
    #pragma unroll
    for (int it = 0; it < 4; it++) {
        int d = tid + it*256;
        int h = d >> 6, dk = d & 63;
        float o = g_o[(((size_t)(b*Hn + h))*Ln + l)*DKn + dk];
        float r = o + query[(size_t)row*Dn + d];
        vals[it] = r;
        s += r; ss += r*r;
    }
    __shared__ float sm[8], sq[8], stat[2];
    #pragma unroll
    for (int off = 16; off; off >>= 1) {
        s  += __shfl_xor_sync(0xffffffffu, s, off);
        ss += __shfl_xor_sync(0xffffffffu, ss, off);
    }
    int warp = tid >> 5, lane = tid & 31;
    if (lane == 0) { sm[warp] = s; sq[warp] = ss; }
    __syncthreads();
    if (tid == 0) {
        float S = 0.f, SS = 0.f;
        #pragma unroll
        for (int w = 0; w < 8; w++) { S += sm[w]; SS += sq[w]; }
        float mu = S * (1.0f/Dn);
        float var = SS * (1.0f/Dn) - mu*mu;
        stat[0] = mu;
        stat[1] = rsqrtf(var + 1e-6f);
    }
    __syncthreads();
    float mu = stat[0], rstd = stat[1];
    #pragma unroll
    for (int it = 0; it < 4; it++) {
        int d = tid + it*256;
        out[(size_t)row*Dn + d] = (vals[it] - mu) * rstd * gamma[d] + beta[d];
    }
}

// ---------------------------------------------------------------------------
extern "C" void kernel_launch(void* const* d_in, const int* in_sizes, int n_in,
                              void* d_out, int out_size) {
    const float* key   = (const float*)d_in[0];
    const float* value = (const float*)d_in[1];
    const float* query = (const float*)d_in[2];
    const int*   mask  = (const int*)d_in[3];
    const float* Wk = (const float*)d_in[4];
    const float* Wv = (const float*)d_in[5];
    const float* Wq = (const float*)d_in[6];
    const float* lng = (const float*)d_in[7];
    const float* lnb = (const float*)d_in[8];

    float* normed = (float*)d_out;                       // [B, L, D]
    float* attn;
    if ((size_t)out_size > (size_t)Bn*Ln*Dn) {
        attn = normed + (size_t)Bn*Ln*Dn;                // [B*H, L, L]
    } else {
        cudaGetSymbolAddress((void**)&attn, g_sc);
    }

    cudaFuncSetAttribute(proj_kernel,
                         cudaFuncAttributeMaxDynamicSharedMemorySize, PROJ_SMEM);
    cudaFuncSetAttribute(fused_kernel,
                         cudaFuncAttributeMaxDynamicSharedMemorySize, FUSED_SMEM);

    maskc_kernel<<<512, 256>>>(mask);

    dim3 gp(Dn/128, Mn/128, 3);
    proj_kernel<<<gp, 256, PROJ_SMEM>>>(key, value, query, Wk, Wv, Wq);

    dim3 gf(Ln/128, BHn);       // (16, 32)
    fused_kernel<<<gf, 256, FUSED_SMEM>>>(attn);

    ln_kernel<<<Mn, 256>>>(query, lng, lnb, normed);
}